// round 1
// baseline (speedup 1.0000x reference)
#include <cuda_runtime.h>
#include <cstdint>
#include <cstddef>

#define D_MODEL 1024
#define D_INNER 2048
#define BATCH   4
#define SEQ     2048
#define M_TOTAL (BATCH * SEQ)   // 8192

// ---------------- scratch (device globals; no allocation) ----------------
__device__ float g_xz   [(size_t)M_TOTAL * (2 * D_INNER)];  // 8192 x 4096
__device__ float g_xconv[(size_t)M_TOTAL * D_INNER];        // 8192 x 2048
__device__ float g_vals [(size_t)M_TOTAL * D_INNER];        // 8192 x 2048
__device__ float g_y    [(size_t)M_TOTAL * D_INNER];        // 8192 x 2048

// ---------------- helpers ----------------
__device__ __forceinline__ float silu_f(float x) {
    return x / (1.0f + expf(-x));
}
__device__ __forceinline__ float softplus_f(float x) {
    return (x > 20.0f) ? x : log1pf(expf(x));
}

// ---------------- SGEMM: C[M,N] = A[M,K] * B[N,K]^T  (both K-major) ----------------
// MODE 0: C = acc + bias                 (in_proj -> xz)
// MODE 1: C = softplus(acc+bias) * aux   (dt * x_conv -> vals)
// MODE 2: C = acc + bias                 (out_proj -> d_out)
#define BM 128
#define BN 128
#define BK 16
#define SPAD 4  // smem row pad: stride 132 floats = 528B (16B aligned)

template <int MODE>
__global__ __launch_bounds__(256, 2) void sgemm_nt(
    const float* __restrict__ A, const float* __restrict__ B,
    const float* __restrict__ bias, float* __restrict__ C,
    const float* __restrict__ aux, int M, int N, int K)
{
    __shared__ float As[2][BK][BM + SPAD];
    __shared__ float Bs[2][BK][BN + SPAD];

    const int tid = threadIdx.x;
    const int bm = blockIdx.y * BM;
    const int bn = blockIdx.x * BN;

    const int tx = tid & 15;        // 0..15 -> column group
    const int ty = tid >> 4;        // 0..15 -> row group
    const int row0 = ty * 8;
    const int col0 = tx * 8;

    // global tile load mapping: 128 rows x 16 cols = 512 float4; 256 thr x 2
    const int lr = tid >> 2;        // 0..63
    const int lc = (tid & 3) << 2;  // 0,4,8,12

    const float* Ab = A + (size_t)bm * K;
    const float* Bb = B + (size_t)bn * K;

    float acc[8][8];
    #pragma unroll
    for (int i = 0; i < 8; i++)
        #pragma unroll
        for (int j = 0; j < 8; j++) acc[i][j] = 0.0f;

    const int nk = K / BK;

    auto load_tile = [&](int k0, int buf) {
        #pragma unroll
        for (int h = 0; h < 2; h++) {
            int r = lr + h * 64;
            float4 av = *reinterpret_cast<const float4*>(Ab + (size_t)r * K + k0 + lc);
            float4 bv = *reinterpret_cast<const float4*>(Bb + (size_t)r * K + k0 + lc);
            As[buf][lc + 0][r] = av.x; As[buf][lc + 1][r] = av.y;
            As[buf][lc + 2][r] = av.z; As[buf][lc + 3][r] = av.w;
            Bs[buf][lc + 0][r] = bv.x; Bs[buf][lc + 1][r] = bv.y;
            Bs[buf][lc + 2][r] = bv.z; Bs[buf][lc + 3][r] = bv.w;
        }
    };

    load_tile(0, 0);
    __syncthreads();

    for (int kt = 0; kt < nk; kt++) {
        int buf = kt & 1;
        if (kt + 1 < nk) load_tile((kt + 1) * BK, buf ^ 1);

        #pragma unroll
        for (int k = 0; k < BK; k++) {
            float a[8], b[8];
            *reinterpret_cast<float4*>(&a[0]) = *reinterpret_cast<const float4*>(&As[buf][k][row0]);
            *reinterpret_cast<float4*>(&a[4]) = *reinterpret_cast<const float4*>(&As[buf][k][row0 + 4]);
            *reinterpret_cast<float4*>(&b[0]) = *reinterpret_cast<const float4*>(&Bs[buf][k][col0]);
            *reinterpret_cast<float4*>(&b[4]) = *reinterpret_cast<const float4*>(&Bs[buf][k][col0 + 4]);
            #pragma unroll
            for (int i = 0; i < 8; i++)
                #pragma unroll
                for (int j = 0; j < 8; j++)
                    acc[i][j] = fmaf(a[i], b[j], acc[i][j]);
        }
        __syncthreads();
    }

    // epilogue
    #pragma unroll
    for (int i = 0; i < 8; i++) {
        int gm = bm + row0 + i;
        size_t rowoff = (size_t)gm * N + bn + col0;
        #pragma unroll
        for (int j = 0; j < 8; j += 4) {
            float4 o;
            float* po = &o.x;
            #pragma unroll
            for (int u = 0; u < 4; u++) {
                int gn = bn + col0 + j + u;
                float v = acc[i][j + u] + bias[gn];
                if (MODE == 1) {
                    v = softplus_f(v) * aux[rowoff + j + u];
                }
                po[u] = v;
            }
            *reinterpret_cast<float4*>(&C[rowoff + j]) = o;
        }
    }
}

// ---------------- depthwise causal conv (width 4) + SiLU ----------------
__global__ void conv_silu_kernel(const float* __restrict__ xz,
                                 const float* __restrict__ Wc,
                                 const float* __restrict__ bc,
                                 float* __restrict__ xconv)
{
    int idx = blockIdx.x * blockDim.x + threadIdx.x;
    if (idx >= M_TOTAL * D_INNER) return;
    int c = idx & (D_INNER - 1);
    int m = idx >> 11;             // D_INNER == 2048
    int t = m & (SEQ - 1);

    float4 w = *reinterpret_cast<const float4*>(Wc + c * 4);
    float acc = bc[c];

    const size_t st = 2 * D_INNER;             // row stride in xz
    size_t base = (size_t)m * st + c;          // x_branch = first half of xz row

    if (t >= 3) {
        acc += w.x * xz[base - 3 * st] + w.y * xz[base - 2 * st]
             + w.z * xz[base - st]     + w.w * xz[base];
    } else {
        acc += w.w * xz[base];
        if (t >= 1) acc += w.z * xz[base - st];
        if (t >= 2) acc += w.y * xz[base - 2 * st];
    }
    xconv[idx] = silu_f(acc);
}

// ---------------- diagonal recurrence + SiLU(z) gating ----------------
__global__ void scan_gate_kernel(const float* __restrict__ vals,
                                 const float* __restrict__ xz,
                                 const float* __restrict__ decay,
                                 float* __restrict__ y)
{
    int idx = blockIdx.x * blockDim.x + threadIdx.x;  // 0..8191
    if (idx >= BATCH * D_INNER) return;
    int b = idx >> 11;
    int c = idx & (D_INNER - 1);

    float d = decay[c];
    float h = 0.0f;
    size_t voff = (size_t)b * SEQ * D_INNER + c;
    size_t zoff = (size_t)b * SEQ * (2 * D_INNER) + D_INNER + c;

    for (int t = 0; t < SEQ; t += 8) {
        float v[8], z[8];
        #pragma unroll
        for (int u = 0; u < 8; u++) {
            v[u] = vals[voff + (size_t)(t + u) * D_INNER];
            z[u] = xz[zoff + (size_t)(t + u) * (2 * D_INNER)];
        }
        #pragma unroll
        for (int u = 0; u < 8; u++) {
            h = fmaf(d, h, v[u]);
            y[voff + (size_t)(t + u) * D_INNER] = h * silu_f(z[u]);
        }
    }
}

// ---------------- launcher ----------------
extern "C" void kernel_launch(void* const* d_in, const int* in_sizes, int n_in,
                              void* d_out, int out_size)
{
    const float* x      = (const float*)d_in[0];
    const float* W_in   = (const float*)d_in[1];
    const float* b_in   = (const float*)d_in[2];
    const float* W_conv = (const float*)d_in[3];
    const float* b_conv = (const float*)d_in[4];
    const float* W_dt   = (const float*)d_in[5];
    const float* b_dt   = (const float*)d_in[6];
    const float* W_out  = (const float*)d_in[7];
    const float* b_out  = (const float*)d_in[8];
    const float* decay  = (const float*)d_in[9];
    float* out = (float*)d_out;

    float *xz, *xconv, *vals, *y;
    cudaGetSymbolAddress((void**)&xz, g_xz);
    cudaGetSymbolAddress((void**)&xconv, g_xconv);
    cudaGetSymbolAddress((void**)&vals, g_vals);
    cudaGetSymbolAddress((void**)&y, g_y);

    // GEMM1: xz = x @ W_in^T + b_in   [8192, 4096]
    sgemm_nt<0><<<dim3((2 * D_INNER) / BN, M_TOTAL / BM), 256>>>(
        x, W_in, b_in, xz, nullptr, M_TOTAL, 2 * D_INNER, D_MODEL);

    // conv + silu: x_conv [8192, 2048]
    conv_silu_kernel<<<(M_TOTAL * D_INNER) / 256, 256>>>(xz, W_conv, b_conv, xconv);

    // GEMM2: vals = softplus(x_conv @ W_dt^T + b_dt) * x_conv   [8192, 2048]
    sgemm_nt<1><<<dim3(D_INNER / BN, M_TOTAL / BM), 256>>>(
        xconv, W_dt, b_dt, vals, xconv, M_TOTAL, D_INNER, D_INNER);

    // scan over time + gate with silu(z): y [8192, 2048]
    scan_gate_kernel<<<(BATCH * D_INNER) / 256, 256>>>(vals, xz, decay, y);

    // GEMM3: out = y @ W_out^T + b_out   [8192, 1024]
    sgemm_nt<2><<<dim3(D_MODEL / BN, M_TOTAL / BM), 256>>>(
        y, W_out, b_out, out, nullptr, M_TOTAL, D_MODEL, D_INNER);
}

// round 5
// speedup vs baseline: 2.1063x; 2.1063x over previous
#include <cuda_runtime.h>
#include <cuda_bf16.h>
#include <cstdint>
#include <cstddef>

#define D_MODEL 1024
#define D_INNER 2048
#define BATCH   4
#define SEQ     2048
#define M_TOTAL (BATCH * SEQ)   // 8192
#define NCH     16              // scan chunks per sequence
#define LCH     (SEQ / NCH)     // 128

// ---------------- scratch (device globals; no allocation) ----------------
__device__ float g_xz   [(size_t)M_TOTAL * (2 * D_INNER)];  // 8192 x 4096
__device__ float g_xconv[(size_t)M_TOTAL * D_INNER];
__device__ float g_vals [(size_t)M_TOTAL * D_INNER];

__device__ __nv_bfloat16 g_xh [(size_t)M_TOTAL * D_MODEL];
__device__ __nv_bfloat16 g_xl [(size_t)M_TOTAL * D_MODEL];
__device__ __nv_bfloat16 g_xch[(size_t)M_TOTAL * D_INNER];
__device__ __nv_bfloat16 g_xcl[(size_t)M_TOTAL * D_INNER];
__device__ __nv_bfloat16 g_yh [(size_t)M_TOTAL * D_INNER];
__device__ __nv_bfloat16 g_yl [(size_t)M_TOTAL * D_INNER];
__device__ __nv_bfloat16 g_wih[(size_t)(2*D_INNER) * D_MODEL];
__device__ __nv_bfloat16 g_wil[(size_t)(2*D_INNER) * D_MODEL];
__device__ __nv_bfloat16 g_wdh[(size_t)D_INNER * D_INNER];
__device__ __nv_bfloat16 g_wdl[(size_t)D_INNER * D_INNER];
__device__ __nv_bfloat16 g_woh[(size_t)D_MODEL * D_INNER];
__device__ __nv_bfloat16 g_wol[(size_t)D_MODEL * D_INNER];
__device__ float g_carry[BATCH * NCH * D_INNER];
__device__ float g_hin  [BATCH * NCH * D_INNER];

// ---------------- helpers ----------------
__device__ __forceinline__ uint32_t smem_u32(const void* p) {
    uint32_t a;
    asm("{ .reg .u64 t; cvta.to.shared.u64 t, %1; cvt.u32.u64 %0, t; }" : "=r"(a) : "l"(p));
    return a;
}
__device__ __forceinline__ void cp16(uint32_t saddr, const void* g) {
    asm volatile("cp.async.cg.shared.global [%0], [%1], 16;" :: "r"(saddr), "l"(g) : "memory");
}
__device__ __forceinline__ float silu_f(float x) { return x / (1.0f + expf(-x)); }
__device__ __forceinline__ float softplus_f(float x) { return (x > 20.0f) ? x : log1pf(expf(x)); }
__device__ __forceinline__ void split_bf16(float v, __nv_bfloat16& h, __nv_bfloat16& l) {
    h = __float2bfloat16(v);
    l = __float2bfloat16(v - __bfloat162float(h));
}

// ---------------- mma.sync bf16 GEMM ----------------
// C[M,N] = (Ah+Al)[M,K] @ (Bh+Bl)[N,K]^T via K' = 3K: [Ah|Al|Ah] x [Bh|Bh|Bl]
// MODE 0/2: C = acc + bias      MODE 1: C = softplus(acc+bias) * aux
#define BM 128
#define BN 128
#define BK 32          // bf16 K per stage
#define AST 40         // smem row stride (halves): 80B, conflict-free ldmatrix

template <int MODE>
__global__ __launch_bounds__(256)
void gemm_mma(const __nv_bfloat16* __restrict__ Ah, const __nv_bfloat16* __restrict__ Al,
              const __nv_bfloat16* __restrict__ Bh, const __nv_bfloat16* __restrict__ Bl,
              const float* __restrict__ bias, float* __restrict__ C,
              const float* __restrict__ aux, int M, int N, int K)
{
    __shared__ __nv_bfloat16 As[2][BM][AST];
    __shared__ __nv_bfloat16 Bs[2][BN][AST];

    const int tid  = threadIdx.x;
    const int wid  = tid >> 5;
    const int lane = tid & 31;
    const int bm = blockIdx.y * BM;
    const int bn = blockIdx.x * BN;
    const int wm = (wid >> 2) * 64;   // warp m offset (0 or 64)
    const int wn = (wid & 3) * 32;    // warp n offset (0,32,64,96)

    const __nv_bfloat16* Abh = Ah + (size_t)bm * K;
    const __nv_bfloat16* Abl = Al + (size_t)bm * K;
    const __nv_bfloat16* Bbh = Bh + (size_t)bn * K;
    const __nv_bfloat16* Bbl = Bl + (size_t)bn * K;

    const int segLen = K / BK;        // chunks per segment
    const int nst = 3 * segLen;       // total k-chunks (K' = 3K)

    float acc[4][4][4];
    #pragma unroll
    for (int i = 0; i < 4; i++)
        #pragma unroll
        for (int j = 0; j < 4; j++)
            #pragma unroll
            for (int r = 0; r < 4; r++) acc[i][j][r] = 0.0f;

    // loader: 128 rows x 32 halves (64B) per tile -> 512 x 16B; 256 thr x 2
    const int lrow = tid >> 2;        // 0..63 (x2 halves of rows)
    const int lq   = (tid & 3) * 8;   // half-offset 0,8,16,24

    auto load_stage = [&](int s, int buf) {
        const __nv_bfloat16 *Asrc, *Bsrc;
        int kb;
        if (s < segLen)            { Asrc = Abh; Bsrc = Bbh; kb = s * BK; }
        else if (s < 2 * segLen)   { Asrc = Abl; Bsrc = Bbh; kb = (s - segLen) * BK; }
        else                       { Asrc = Abh; Bsrc = Bbl; kb = (s - 2 * segLen) * BK; }
        #pragma unroll
        for (int h = 0; h < 2; h++) {
            int r = lrow + h * 64;
            cp16(smem_u32(&As[buf][r][lq]), Asrc + (size_t)r * K + kb + lq);
            cp16(smem_u32(&Bs[buf][r][lq]), Bsrc + (size_t)r * K + kb + lq);
        }
        asm volatile("cp.async.commit_group;" ::: "memory");
    };

    load_stage(0, 0);
    asm volatile("cp.async.wait_group 0;" ::: "memory");
    __syncthreads();

    for (int s = 0; s < nst; s++) {
        const int buf = s & 1;
        if (s + 1 < nst) load_stage(s + 1, buf ^ 1);

        // compute chunk from As/Bs[buf]
        #pragma unroll
        for (int kk = 0; kk < 2; kk++) {
            uint32_t a[4][4], b[4][2];
            #pragma unroll
            for (int mf = 0; mf < 4; mf++) {
                uint32_t addr = smem_u32(&As[buf][wm + mf * 16 + (lane & 15)][kk * 16 + (lane >> 4) * 8]);
                asm volatile("ldmatrix.sync.aligned.m8n8.x4.shared.b16 {%0,%1,%2,%3}, [%4];"
                             : "=r"(a[mf][0]), "=r"(a[mf][1]), "=r"(a[mf][2]), "=r"(a[mf][3]) : "r"(addr));
            }
            #pragma unroll
            for (int nf = 0; nf < 4; nf++) {
                uint32_t addr = smem_u32(&Bs[buf][wn + nf * 8 + (lane & 7)][kk * 16 + ((lane >> 3) & 1) * 8]);
                asm volatile("ldmatrix.sync.aligned.m8n8.x2.shared.b16 {%0,%1}, [%2];"
                             : "=r"(b[nf][0]), "=r"(b[nf][1]) : "r"(addr));
            }
            #pragma unroll
            for (int mf = 0; mf < 4; mf++)
                #pragma unroll
                for (int nf = 0; nf < 4; nf++) {
                    asm volatile(
                        "mma.sync.aligned.m16n8k16.row.col.f32.bf16.bf16.f32 "
                        "{%0,%1,%2,%3}, {%4,%5,%6,%7}, {%8,%9}, {%0,%1,%2,%3};"
                        : "+f"(acc[mf][nf][0]), "+f"(acc[mf][nf][1]),
                          "+f"(acc[mf][nf][2]), "+f"(acc[mf][nf][3])
                        : "r"(a[mf][0]), "r"(a[mf][1]), "r"(a[mf][2]), "r"(a[mf][3]),
                          "r"(b[nf][0]), "r"(b[nf][1]));
                }
        }

        if (s + 1 < nst) { asm volatile("cp.async.wait_group 0;" ::: "memory"); }
        __syncthreads();
    }

    // epilogue: acc regs -> global (32B-sector-aligned float2 stores)
    const int tr = lane >> 2;          // 0..7
    const int tc = (lane & 3) * 2;     // 0,2,4,6
    #pragma unroll
    for (int mf = 0; mf < 4; mf++) {
        #pragma unroll
        for (int h = 0; h < 2; h++) {  // c0/c1 vs c2/c3 rows
            int gm = bm + wm + mf * 16 + tr + h * 8;
            size_t rb = (size_t)gm * N;
            #pragma unroll
            for (int nf = 0; nf < 4; nf++) {
                int gn = bn + wn + nf * 8 + tc;
                float v0 = acc[mf][nf][h * 2 + 0] + bias[gn];
                float v1 = acc[mf][nf][h * 2 + 1] + bias[gn + 1];
                if (MODE == 1) {
                    float2 ax = *reinterpret_cast<const float2*>(aux + rb + gn);
                    v0 = softplus_f(v0) * ax.x;
                    v1 = softplus_f(v1) * ax.y;
                }
                float2 o; o.x = v0; o.y = v1;
                *reinterpret_cast<float2*>(C + rb + gn) = o;
            }
        }
    }
}

// ---------------- conversion: fp32 -> bf16 hi/lo (vectorized x4) ----------------
__global__ void cvt_kernel(const float* __restrict__ s, __nv_bfloat16* __restrict__ h,
                           __nv_bfloat16* __restrict__ l, int n4)
{
    int i = blockIdx.x * 256 + threadIdx.x;
    if (i >= n4) return;
    float4 v = reinterpret_cast<const float4*>(s)[i];
    __nv_bfloat16 hh[4], ll[4];
    split_bf16(v.x, hh[0], ll[0]);
    split_bf16(v.y, hh[1], ll[1]);
    split_bf16(v.z, hh[2], ll[2]);
    split_bf16(v.w, hh[3], ll[3]);
    reinterpret_cast<__nv_bfloat162*>(h)[2*i]   = __nv_bfloat162(hh[0], hh[1]);
    reinterpret_cast<__nv_bfloat162*>(h)[2*i+1] = __nv_bfloat162(hh[2], hh[3]);
    reinterpret_cast<__nv_bfloat162*>(l)[2*i]   = __nv_bfloat162(ll[0], ll[1]);
    reinterpret_cast<__nv_bfloat162*>(l)[2*i+1] = __nv_bfloat162(ll[2], ll[3]);
}

// ---------------- depthwise causal conv (width 4) + SiLU + split ----------------
__global__ void conv_silu_kernel(const float* __restrict__ xz,
                                 const float* __restrict__ Wc,
                                 const float* __restrict__ bc,
                                 float* __restrict__ xconv,
                                 __nv_bfloat16* __restrict__ xch,
                                 __nv_bfloat16* __restrict__ xcl)
{
    int idx = blockIdx.x * blockDim.x + threadIdx.x;
    if (idx >= M_TOTAL * D_INNER) return;
    int c = idx & (D_INNER - 1);
    int m = idx >> 11;
    int t = m & (SEQ - 1);

    float4 w = *reinterpret_cast<const float4*>(Wc + c * 4);
    float acc = bc[c];
    const size_t st = 2 * D_INNER;
    size_t base = (size_t)m * st + c;

    if (t >= 3) {
        acc += w.x * xz[base - 3 * st] + w.y * xz[base - 2 * st]
             + w.z * xz[base - st]     + w.w * xz[base];
    } else {
        acc += w.w * xz[base];
        if (t >= 1) acc += w.z * xz[base - st];
        if (t >= 2) acc += w.y * xz[base - 2 * st];
    }
    float v = silu_f(acc);
    xconv[idx] = v;
    __nv_bfloat16 hh, ll;
    split_bf16(v, hh, ll);
    xch[idx] = hh; xcl[idx] = ll;
}

// ---------------- chunked scan ----------------
__global__ void scanA_kernel(const float* __restrict__ vals, const float* __restrict__ decay,
                             float* __restrict__ carry)
{
    int idx = blockIdx.x * 256 + threadIdx.x;      // 131072
    if (idx >= BATCH * NCH * D_INNER) return;
    int c = idx & (D_INNER - 1);
    int ch = (idx >> 11) & (NCH - 1);
    int b = idx >> 15;
    float d = decay[c];
    float h = 0.0f;
    size_t base = ((size_t)(b * SEQ + ch * LCH)) * D_INNER + c;
    #pragma unroll 8
    for (int i = 0; i < LCH; i++)
        h = fmaf(d, h, vals[base + (size_t)i * D_INNER]);
    carry[(b * NCH + ch) * D_INNER + c] = h;
}

__global__ void scanB_kernel(const float* __restrict__ carry, const float* __restrict__ decay,
                             float* __restrict__ hin)
{
    int idx = blockIdx.x * 256 + threadIdx.x;      // 8192
    if (idx >= BATCH * D_INNER) return;
    int c = idx & (D_INNER - 1);
    int b = idx >> 11;
    float d = decay[c];
    float dL = d;
    #pragma unroll
    for (int j = 0; j < 7; j++) dL = dL * dL;      // d^128
    float H = 0.0f;
    for (int ch = 0; ch < NCH; ch++) {
        int o = (b * NCH + ch) * D_INNER + c;
        hin[o] = H;
        H = fmaf(dL, H, carry[o]);
    }
}

__global__ void scanC_kernel(const float* __restrict__ vals, const float* __restrict__ xz,
                             const float* __restrict__ decay, const float* __restrict__ hin,
                             __nv_bfloat16* __restrict__ yh, __nv_bfloat16* __restrict__ yl)
{
    int idx = blockIdx.x * 256 + threadIdx.x;
    if (idx >= BATCH * NCH * D_INNER) return;
    int c = idx & (D_INNER - 1);
    int ch = (idx >> 11) & (NCH - 1);
    int b = idx >> 15;
    float d = decay[c];
    float h = hin[(b * NCH + ch) * D_INNER + c];
    size_t m0 = (size_t)(b * SEQ + ch * LCH);
    size_t vbase = m0 * D_INNER + c;
    size_t zbase = m0 * (2 * D_INNER) + D_INNER + c;
    #pragma unroll 8
    for (int i = 0; i < LCH; i++) {
        h = fmaf(d, h, vals[vbase + (size_t)i * D_INNER]);
        float z = xz[zbase + (size_t)i * (2 * D_INNER)];
        float g = h * silu_f(z);
        __nv_bfloat16 hh, ll;
        split_bf16(g, hh, ll);
        yh[vbase + (size_t)i * D_INNER] = hh;
        yl[vbase + (size_t)i * D_INNER] = ll;
    }
}

// ---------------- launcher ----------------
extern "C" void kernel_launch(void* const* d_in, const int* in_sizes, int n_in,
                              void* d_out, int out_size)
{
    const float* x      = (const float*)d_in[0];
    const float* W_in   = (const float*)d_in[1];
    const float* b_in   = (const float*)d_in[2];
    const float* W_conv = (const float*)d_in[3];
    const float* b_conv = (const float*)d_in[4];
    const float* W_dt   = (const float*)d_in[5];
    const float* b_dt   = (const float*)d_in[6];
    const float* W_out  = (const float*)d_in[7];
    const float* b_out  = (const float*)d_in[8];
    const float* decay  = (const float*)d_in[9];
    float* out = (float*)d_out;

    float *xz, *xconv, *vals, *carry, *hin;
    __nv_bfloat16 *xh, *xl, *xch, *xcl, *yh, *yl, *wih, *wil, *wdh, *wdl, *woh, *wol;
    cudaGetSymbolAddress((void**)&xz, g_xz);
    cudaGetSymbolAddress((void**)&xconv, g_xconv);
    cudaGetSymbolAddress((void**)&vals, g_vals);
    cudaGetSymbolAddress((void**)&carry, g_carry);
    cudaGetSymbolAddress((void**)&hin, g_hin);
    cudaGetSymbolAddress((void**)&xh, g_xh);
    cudaGetSymbolAddress((void**)&xl, g_xl);
    cudaGetSymbolAddress((void**)&xch, g_xch);
    cudaGetSymbolAddress((void**)&xcl, g_xcl);
    cudaGetSymbolAddress((void**)&yh, g_yh);
    cudaGetSymbolAddress((void**)&yl, g_yl);
    cudaGetSymbolAddress((void**)&wih, g_wih);
    cudaGetSymbolAddress((void**)&wil, g_wil);
    cudaGetSymbolAddress((void**)&wdh, g_wdh);
    cudaGetSymbolAddress((void**)&wdl, g_wdl);
    cudaGetSymbolAddress((void**)&woh, g_woh);
    cudaGetSymbolAddress((void**)&wol, g_wol);

    // split conversions (all sizes divisible by 4)
    cvt_kernel<<<(M_TOTAL * D_MODEL / 4 + 255) / 256, 256>>>(x, xh, xl, M_TOTAL * D_MODEL / 4);
    cvt_kernel<<<(2 * D_INNER * D_MODEL / 4 + 255) / 256, 256>>>(W_in, wih, wil, 2 * D_INNER * D_MODEL / 4);
    cvt_kernel<<<(D_INNER * D_INNER / 4 + 255) / 256, 256>>>(W_dt, wdh, wdl, D_INNER * D_INNER / 4);
    cvt_kernel<<<(D_MODEL * D_INNER / 4 + 255) / 256, 256>>>(W_out, woh, wol, D_MODEL * D_INNER / 4);

    // GEMM1: xz = x @ W_in^T + b_in   [8192, 4096], K=1024
    gemm_mma<0><<<dim3((2 * D_INNER) / BN, M_TOTAL / BM), 256>>>(
        xh, xl, wih, wil, b_in, xz, nullptr, M_TOTAL, 2 * D_INNER, D_MODEL);

    // conv + silu (+ bf16 split)
    conv_silu_kernel<<<(M_TOTAL * D_INNER) / 256, 256>>>(xz, W_conv, b_conv, xconv, xch, xcl);

    // GEMM2: vals = softplus(xconv @ W_dt^T + b_dt) * xconv   [8192, 2048], K=2048
    gemm_mma<1><<<dim3(D_INNER / BN, M_TOTAL / BM), 256>>>(
        xch, xcl, wdh, wdl, b_dt, vals, xconv, M_TOTAL, D_INNER, D_INNER);

    // chunked scan + gate -> y (bf16 hi/lo)
    scanA_kernel<<<(BATCH * NCH * D_INNER) / 256, 256>>>(vals, decay, carry);
    scanB_kernel<<<(BATCH * D_INNER) / 256, 256>>>(carry, decay, hin);
    scanC_kernel<<<(BATCH * NCH * D_INNER) / 256, 256>>>(vals, xz, decay, hin, yh, yl);

    // GEMM3: out = y @ W_out^T + b_out   [8192, 1024], K=2048
    gemm_mma<2><<<dim3(D_MODEL / BN, M_TOTAL / BM), 256>>>(
        yh, yl, woh, wol, b_out, out, nullptr, M_TOTAL, D_MODEL, D_INNER);
}

// round 6
// speedup vs baseline: 2.3804x; 1.1301x over previous
#include <cuda_runtime.h>
#include <cuda_bf16.h>
#include <cstdint>
#include <cstddef>

#define D_MODEL 1024
#define D_INNER 2048
#define BATCH   4
#define SEQ     2048
#define M_TOTAL (BATCH * SEQ)   // 8192
#define NCH     16              // scan chunks per sequence
#define LCH     (SEQ / NCH)     // 128

// ---------------- scratch (device globals; no allocation) ----------------
__device__ float g_xz   [(size_t)M_TOTAL * (2 * D_INNER)];  // 8192 x 4096
__device__ float g_xconv[(size_t)M_TOTAL * D_INNER];
__device__ float g_vals [(size_t)M_TOTAL * D_INNER];

__device__ __nv_bfloat16 g_xh [(size_t)M_TOTAL * D_MODEL];
__device__ __nv_bfloat16 g_xl [(size_t)M_TOTAL * D_MODEL];
__device__ __nv_bfloat16 g_xch[(size_t)M_TOTAL * D_INNER];
__device__ __nv_bfloat16 g_xcl[(size_t)M_TOTAL * D_INNER];
__device__ __nv_bfloat16 g_yh [(size_t)M_TOTAL * D_INNER];
__device__ __nv_bfloat16 g_yl [(size_t)M_TOTAL * D_INNER];
__device__ __nv_bfloat16 g_wih[(size_t)(2*D_INNER) * D_MODEL];
__device__ __nv_bfloat16 g_wil[(size_t)(2*D_INNER) * D_MODEL];
__device__ __nv_bfloat16 g_wdh[(size_t)D_INNER * D_INNER];
__device__ __nv_bfloat16 g_wdl[(size_t)D_INNER * D_INNER];
__device__ __nv_bfloat16 g_woh[(size_t)D_MODEL * D_INNER];
__device__ __nv_bfloat16 g_wol[(size_t)D_MODEL * D_INNER];
__device__ float g_carry[BATCH * NCH * D_INNER];
__device__ float g_hin  [BATCH * NCH * D_INNER];

// ---------------- helpers ----------------
__device__ __forceinline__ uint32_t smem_u32(const void* p) {
    uint32_t a;
    asm("{ .reg .u64 t; cvta.to.shared.u64 t, %1; cvt.u32.u64 %0, t; }" : "=r"(a) : "l"(p));
    return a;
}
__device__ __forceinline__ void cp16(uint32_t saddr, const void* g) {
    asm volatile("cp.async.cg.shared.global [%0], [%1], 16;" :: "r"(saddr), "l"(g) : "memory");
}
__device__ __forceinline__ float silu_f(float x) { return x / (1.0f + expf(-x)); }
__device__ __forceinline__ float softplus_f(float x) { return (x > 20.0f) ? x : log1pf(expf(x)); }
__device__ __forceinline__ void split_bf16(float v, __nv_bfloat16& h, __nv_bfloat16& l) {
    h = __float2bfloat16(v);
    l = __float2bfloat16(v - __bfloat162float(h));
}

// ---------------- mma.sync bf16 GEMM, fused hi/lo tiles ----------------
// C = Ah@Bh^T + Al@Bh^T + Ah@Bl^T  (3 MMA combos per fragment load)
// MODE 0/2: C = acc + bias      MODE 1: C = softplus(acc+bias) * aux
#define BM 128
#define BN 128
#define BK 32          // bf16 K per stage
#define AST 40         // smem row stride (halves): 80B, conflict-free ldmatrix
#define TILE_H (BM * AST)          // halves per tile (5120)
#define STAGE_H (4 * TILE_H)       // Ah|Al|Bh|Bl (20480 halves = 40KB)
#define OFF_AH 0
#define OFF_AL TILE_H
#define OFF_BH (2 * TILE_H)
#define OFF_BL (3 * TILE_H)
#define GSMEM_BYTES (2 * STAGE_H * 2)   // 81920

template <int MODE>
__global__ __launch_bounds__(256)
void gemm_mma(const __nv_bfloat16* __restrict__ Ah, const __nv_bfloat16* __restrict__ Al,
              const __nv_bfloat16* __restrict__ Bh, const __nv_bfloat16* __restrict__ Bl,
              const float* __restrict__ bias, float* __restrict__ C,
              const float* __restrict__ aux, int M, int N, int K)
{
    extern __shared__ __nv_bfloat16 smem[];

    const int tid  = threadIdx.x;
    const int wid  = tid >> 5;
    const int lane = tid & 31;
    const int bm = blockIdx.y * BM;
    const int bn = blockIdx.x * BN;
    const int wm = (wid >> 2) * 64;   // warp m offset (0 or 64)
    const int wn = (wid & 3) * 32;    // warp n offset (0,32,64,96)

    const __nv_bfloat16* Abh = Ah + (size_t)bm * K;
    const __nv_bfloat16* Abl = Al + (size_t)bm * K;
    const __nv_bfloat16* Bbh = Bh + (size_t)bn * K;
    const __nv_bfloat16* Bbl = Bl + (size_t)bn * K;

    const int nst = K / BK;

    float acc[4][4][4];
    #pragma unroll
    for (int i = 0; i < 4; i++)
        #pragma unroll
        for (int j = 0; j < 4; j++)
            #pragma unroll
            for (int r = 0; r < 4; r++) acc[i][j][r] = 0.0f;

    // loader: per tile 128 rows x 32 halves = 512 x 16B; 4 tiles -> 8 cp16/thread
    const int lrow = tid >> 2;        // 0..63
    const int lq   = (tid & 3) * 8;   // half-offset 0,8,16,24

    auto load_stage = [&](int s, int buf) {
        const int kb = s * BK;
        __nv_bfloat16* st = smem + buf * STAGE_H;
        #pragma unroll
        for (int h = 0; h < 2; h++) {
            int r = lrow + h * 64;
            size_t go = (size_t)r * K + kb + lq;
            int so = r * AST + lq;
            cp16(smem_u32(st + OFF_AH + so), Abh + go);
            cp16(smem_u32(st + OFF_AL + so), Abl + go);
            cp16(smem_u32(st + OFF_BH + so), Bbh + go);
            cp16(smem_u32(st + OFF_BL + so), Bbl + go);
        }
        asm volatile("cp.async.commit_group;" ::: "memory");
    };

    load_stage(0, 0);
    asm volatile("cp.async.wait_group 0;" ::: "memory");
    __syncthreads();

    for (int s = 0; s < nst; s++) {
        const int buf = s & 1;
        if (s + 1 < nst) load_stage(s + 1, buf ^ 1);

        const __nv_bfloat16* st = smem + buf * STAGE_H;
        #pragma unroll
        for (int kk = 0; kk < 2; kk++) {
            uint32_t ah[4][4], al[4][4], bh[4][2], bl[4][2];
            #pragma unroll
            for (int mf = 0; mf < 4; mf++) {
                int so = (wm + mf * 16 + (lane & 15)) * AST + kk * 16 + (lane >> 4) * 8;
                uint32_t adh = smem_u32(st + OFF_AH + so);
                uint32_t adl = smem_u32(st + OFF_AL + so);
                asm volatile("ldmatrix.sync.aligned.m8n8.x4.shared.b16 {%0,%1,%2,%3}, [%4];"
                             : "=r"(ah[mf][0]), "=r"(ah[mf][1]), "=r"(ah[mf][2]), "=r"(ah[mf][3]) : "r"(adh));
                asm volatile("ldmatrix.sync.aligned.m8n8.x4.shared.b16 {%0,%1,%2,%3}, [%4];"
                             : "=r"(al[mf][0]), "=r"(al[mf][1]), "=r"(al[mf][2]), "=r"(al[mf][3]) : "r"(adl));
            }
            #pragma unroll
            for (int nf = 0; nf < 4; nf++) {
                int so = (wn + nf * 8 + (lane & 7)) * AST + kk * 16 + ((lane >> 3) & 1) * 8;
                uint32_t bdh = smem_u32(st + OFF_BH + so);
                uint32_t bdl = smem_u32(st + OFF_BL + so);
                asm volatile("ldmatrix.sync.aligned.m8n8.x2.shared.b16 {%0,%1}, [%2];"
                             : "=r"(bh[nf][0]), "=r"(bh[nf][1]) : "r"(bdh));
                asm volatile("ldmatrix.sync.aligned.m8n8.x2.shared.b16 {%0,%1}, [%2];"
                             : "=r"(bl[nf][0]), "=r"(bl[nf][1]) : "r"(bdl));
            }
            #pragma unroll
            for (int mf = 0; mf < 4; mf++)
                #pragma unroll
                for (int nf = 0; nf < 4; nf++) {
                    asm volatile(
                        "mma.sync.aligned.m16n8k16.row.col.f32.bf16.bf16.f32 "
                        "{%0,%1,%2,%3}, {%4,%5,%6,%7}, {%8,%9}, {%0,%1,%2,%3};"
                        : "+f"(acc[mf][nf][0]), "+f"(acc[mf][nf][1]),
                          "+f"(acc[mf][nf][2]), "+f"(acc[mf][nf][3])
                        : "r"(ah[mf][0]), "r"(ah[mf][1]), "r"(ah[mf][2]), "r"(ah[mf][3]),
                          "r"(bh[nf][0]), "r"(bh[nf][1]));
                    asm volatile(
                        "mma.sync.aligned.m16n8k16.row.col.f32.bf16.bf16.f32 "
                        "{%0,%1,%2,%3}, {%4,%5,%6,%7}, {%8,%9}, {%0,%1,%2,%3};"
                        : "+f"(acc[mf][nf][0]), "+f"(acc[mf][nf][1]),
                          "+f"(acc[mf][nf][2]), "+f"(acc[mf][nf][3])
                        : "r"(al[mf][0]), "r"(al[mf][1]), "r"(al[mf][2]), "r"(al[mf][3]),
                          "r"(bh[nf][0]), "r"(bh[nf][1]));
                    asm volatile(
                        "mma.sync.aligned.m16n8k16.row.col.f32.bf16.bf16.f32 "
                        "{%0,%1,%2,%3}, {%4,%5,%6,%7}, {%8,%9}, {%0,%1,%2,%3};"
                        : "+f"(acc[mf][nf][0]), "+f"(acc[mf][nf][1]),
                          "+f"(acc[mf][nf][2]), "+f"(acc[mf][nf][3])
                        : "r"(ah[mf][0]), "r"(ah[mf][1]), "r"(ah[mf][2]), "r"(ah[mf][3]),
                          "r"(bl[nf][0]), "r"(bl[nf][1]));
                }
        }

        if (s + 1 < nst) { asm volatile("cp.async.wait_group 0;" ::: "memory"); }
        __syncthreads();
    }

    // epilogue: acc regs -> global (float2 stores)
    const int tr = lane >> 2;          // 0..7
    const int tc = (lane & 3) * 2;     // 0,2,4,6
    #pragma unroll
    for (int mf = 0; mf < 4; mf++) {
        #pragma unroll
        for (int h = 0; h < 2; h++) {
            int gm = bm + wm + mf * 16 + tr + h * 8;
            size_t rb = (size_t)gm * N;
            #pragma unroll
            for (int nf = 0; nf < 4; nf++) {
                int gn = bn + wn + nf * 8 + tc;
                float v0 = acc[mf][nf][h * 2 + 0] + bias[gn];
                float v1 = acc[mf][nf][h * 2 + 1] + bias[gn + 1];
                if (MODE == 1) {
                    float2 ax = *reinterpret_cast<const float2*>(aux + rb + gn);
                    v0 = softplus_f(v0) * ax.x;
                    v1 = softplus_f(v1) * ax.y;
                }
                float2 o; o.x = v0; o.y = v1;
                *reinterpret_cast<float2*>(C + rb + gn) = o;
            }
        }
    }
}

// ---------------- conversion: fp32 -> bf16 hi/lo (vectorized x4) ----------------
__global__ void cvt_kernel(const float* __restrict__ s, __nv_bfloat16* __restrict__ h,
                           __nv_bfloat16* __restrict__ l, int n4)
{
    int i = blockIdx.x * 256 + threadIdx.x;
    if (i >= n4) return;
    float4 v = reinterpret_cast<const float4*>(s)[i];
    __nv_bfloat16 hh[4], ll[4];
    split_bf16(v.x, hh[0], ll[0]);
    split_bf16(v.y, hh[1], ll[1]);
    split_bf16(v.z, hh[2], ll[2]);
    split_bf16(v.w, hh[3], ll[3]);
    reinterpret_cast<__nv_bfloat162*>(h)[2*i]   = __nv_bfloat162(hh[0], hh[1]);
    reinterpret_cast<__nv_bfloat162*>(h)[2*i+1] = __nv_bfloat162(hh[2], hh[3]);
    reinterpret_cast<__nv_bfloat162*>(l)[2*i]   = __nv_bfloat162(ll[0], ll[1]);
    reinterpret_cast<__nv_bfloat162*>(l)[2*i+1] = __nv_bfloat162(ll[2], ll[3]);
}

// ---------------- depthwise causal conv (width 4) + SiLU + split ----------------
__global__ void conv_silu_kernel(const float* __restrict__ xz,
                                 const float* __restrict__ Wc,
                                 const float* __restrict__ bc,
                                 float* __restrict__ xconv,
                                 __nv_bfloat16* __restrict__ xch,
                                 __nv_bfloat16* __restrict__ xcl)
{
    int idx = blockIdx.x * blockDim.x + threadIdx.x;
    if (idx >= M_TOTAL * D_INNER) return;
    int c = idx & (D_INNER - 1);
    int m = idx >> 11;
    int t = m & (SEQ - 1);

    float4 w = *reinterpret_cast<const float4*>(Wc + c * 4);
    float acc = bc[c];
    const size_t st = 2 * D_INNER;
    size_t base = (size_t)m * st + c;

    if (t >= 3) {
        acc += w.x * xz[base - 3 * st] + w.y * xz[base - 2 * st]
             + w.z * xz[base - st]     + w.w * xz[base];
    } else {
        acc += w.w * xz[base];
        if (t >= 1) acc += w.z * xz[base - st];
        if (t >= 2) acc += w.y * xz[base - 2 * st];
    }
    float v = silu_f(acc);
    xconv[idx] = v;
    __nv_bfloat16 hh, ll;
    split_bf16(v, hh, ll);
    xch[idx] = hh; xcl[idx] = ll;
}

// ---------------- chunked scan ----------------
__global__ void scanA_kernel(const float* __restrict__ vals, const float* __restrict__ decay,
                             float* __restrict__ carry)
{
    int idx = blockIdx.x * 256 + threadIdx.x;      // 131072
    if (idx >= BATCH * NCH * D_INNER) return;
    int c = idx & (D_INNER - 1);
    int ch = (idx >> 11) & (NCH - 1);
    int b = idx >> 15;
    float d = decay[c];
    float h = 0.0f;
    size_t base = ((size_t)(b * SEQ + ch * LCH)) * D_INNER + c;
    #pragma unroll 8
    for (int i = 0; i < LCH; i++)
        h = fmaf(d, h, vals[base + (size_t)i * D_INNER]);
    carry[(b * NCH + ch) * D_INNER + c] = h;
}

__global__ void scanB_kernel(const float* __restrict__ carry, const float* __restrict__ decay,
                             float* __restrict__ hin)
{
    int idx = blockIdx.x * 256 + threadIdx.x;      // 8192
    if (idx >= BATCH * D_INNER) return;
    int c = idx & (D_INNER - 1);
    int b = idx >> 11;
    float d = decay[c];
    float dL = d;
    #pragma unroll
    for (int j = 0; j < 7; j++) dL = dL * dL;      // d^128
    float H = 0.0f;
    for (int ch = 0; ch < NCH; ch++) {
        int o = (b * NCH + ch) * D_INNER + c;
        hin[o] = H;
        H = fmaf(dL, H, carry[o]);
    }
}

__global__ void scanC_kernel(const float* __restrict__ vals, const float* __restrict__ xz,
                             const float* __restrict__ decay, const float* __restrict__ hin,
                             __nv_bfloat16* __restrict__ yh, __nv_bfloat16* __restrict__ yl)
{
    int idx = blockIdx.x * 256 + threadIdx.x;
    if (idx >= BATCH * NCH * D_INNER) return;
    int c = idx & (D_INNER - 1);
    int ch = (idx >> 11) & (NCH - 1);
    int b = idx >> 15;
    float d = decay[c];
    float h = hin[(b * NCH + ch) * D_INNER + c];
    size_t m0 = (size_t)(b * SEQ + ch * LCH);
    size_t vbase = m0 * D_INNER + c;
    size_t zbase = m0 * (2 * D_INNER) + D_INNER + c;
    #pragma unroll 8
    for (int i = 0; i < LCH; i++) {
        h = fmaf(d, h, vals[vbase + (size_t)i * D_INNER]);
        float z = xz[zbase + (size_t)i * (2 * D_INNER)];
        float g = h * silu_f(z);
        __nv_bfloat16 hh, ll;
        split_bf16(g, hh, ll);
        yh[vbase + (size_t)i * D_INNER] = hh;
        yl[vbase + (size_t)i * D_INNER] = ll;
    }
}

// ---------------- launcher ----------------
extern "C" void kernel_launch(void* const* d_in, const int* in_sizes, int n_in,
                              void* d_out, int out_size)
{
    const float* x      = (const float*)d_in[0];
    const float* W_in   = (const float*)d_in[1];
    const float* b_in   = (const float*)d_in[2];
    const float* W_conv = (const float*)d_in[3];
    const float* b_conv = (const float*)d_in[4];
    const float* W_dt   = (const float*)d_in[5];
    const float* b_dt   = (const float*)d_in[6];
    const float* W_out  = (const float*)d_in[7];
    const float* b_out  = (const float*)d_in[8];
    const float* decay  = (const float*)d_in[9];
    float* out = (float*)d_out;

    float *xz, *xconv, *vals, *carry, *hin;
    __nv_bfloat16 *xh, *xl, *xch, *xcl, *yh, *yl, *wih, *wil, *wdh, *wdl, *woh, *wol;
    cudaGetSymbolAddress((void**)&xz, g_xz);
    cudaGetSymbolAddress((void**)&xconv, g_xconv);
    cudaGetSymbolAddress((void**)&vals, g_vals);
    cudaGetSymbolAddress((void**)&carry, g_carry);
    cudaGetSymbolAddress((void**)&hin, g_hin);
    cudaGetSymbolAddress((void**)&xh, g_xh);
    cudaGetSymbolAddress((void**)&xl, g_xl);
    cudaGetSymbolAddress((void**)&xch, g_xch);
    cudaGetSymbolAddress((void**)&xcl, g_xcl);
    cudaGetSymbolAddress((void**)&yh, g_yh);
    cudaGetSymbolAddress((void**)&yl, g_yl);
    cudaGetSymbolAddress((void**)&wih, g_wih);
    cudaGetSymbolAddress((void**)&wil, g_wil);
    cudaGetSymbolAddress((void**)&wdh, g_wdh);
    cudaGetSymbolAddress((void**)&wdl, g_wdl);
    cudaGetSymbolAddress((void**)&woh, g_woh);
    cudaGetSymbolAddress((void**)&wol, g_wol);

    cudaFuncSetAttribute(gemm_mma<0>, cudaFuncAttributeMaxDynamicSharedMemorySize, GSMEM_BYTES);
    cudaFuncSetAttribute(gemm_mma<1>, cudaFuncAttributeMaxDynamicSharedMemorySize, GSMEM_BYTES);
    cudaFuncSetAttribute(gemm_mma<2>, cudaFuncAttributeMaxDynamicSharedMemorySize, GSMEM_BYTES);

    // split conversions (all sizes divisible by 4)
    cvt_kernel<<<(M_TOTAL * D_MODEL / 4 + 255) / 256, 256>>>(x, xh, xl, M_TOTAL * D_MODEL / 4);
    cvt_kernel<<<(2 * D_INNER * D_MODEL / 4 + 255) / 256, 256>>>(W_in, wih, wil, 2 * D_INNER * D_MODEL / 4);
    cvt_kernel<<<(D_INNER * D_INNER / 4 + 255) / 256, 256>>>(W_dt, wdh, wdl, D_INNER * D_INNER / 4);
    cvt_kernel<<<(D_MODEL * D_INNER / 4 + 255) / 256, 256>>>(W_out, woh, wol, D_MODEL * D_INNER / 4);

    // GEMM1: xz = x @ W_in^T + b_in   [8192, 4096], K=1024
    gemm_mma<0><<<dim3((2 * D_INNER) / BN, M_TOTAL / BM), 256, GSMEM_BYTES>>>(
        xh, xl, wih, wil, b_in, xz, nullptr, M_TOTAL, 2 * D_INNER, D_MODEL);

    // conv + silu (+ bf16 split)
    conv_silu_kernel<<<(M_TOTAL * D_INNER) / 256, 256>>>(xz, W_conv, b_conv, xconv, xch, xcl);

    // GEMM2: vals = softplus(xconv @ W_dt^T + b_dt) * xconv   [8192, 2048], K=2048
    gemm_mma<1><<<dim3(D_INNER / BN, M_TOTAL / BM), 256, GSMEM_BYTES>>>(
        xch, xcl, wdh, wdl, b_dt, vals, xconv, M_TOTAL, D_INNER, D_INNER);

    // chunked scan + gate -> y (bf16 hi/lo)
    scanA_kernel<<<(BATCH * NCH * D_INNER) / 256, 256>>>(vals, decay, carry);
    scanB_kernel<<<(BATCH * D_INNER) / 256, 256>>>(carry, decay, hin);
    scanC_kernel<<<(BATCH * NCH * D_INNER) / 256, 256>>>(vals, xz, decay, hin, yh, yl);

    // GEMM3: out = y @ W_out^T + b_out   [8192, 1024], K=2048
    gemm_mma<2><<<dim3(D_MODEL / BN, M_TOTAL / BM), 256, GSMEM_BYTES>>>(
        yh, yl, woh, wol, b_out, out, nullptr, M_TOTAL, D_MODEL, D_INNER);
}

// round 8
// speedup vs baseline: 3.1554x; 1.3255x over previous
#include <cuda_runtime.h>
#include <cuda_fp16.h>
#include <cstdint>
#include <cstddef>

#define D_MODEL 1024
#define D_INNER 2048
#define BATCH   4
#define SEQ     2048
#define M_TOTAL (BATCH * SEQ)   // 8192
#define NCH     16              // scan chunks per sequence
#define LCH     (SEQ / NCH)     // 128

// ---------------- scratch (device globals; no allocation) ----------------
__device__ float g_xz   [(size_t)M_TOTAL * (2 * D_INNER)];  // 8192 x 4096
__device__ float g_xconv[(size_t)M_TOTAL * D_INNER];
__device__ float g_vals [(size_t)M_TOTAL * D_INNER];

__device__ __half g_xf  [(size_t)M_TOTAL * D_MODEL];
__device__ __half g_xcf [(size_t)M_TOTAL * D_INNER];
__device__ __half g_yf  [(size_t)M_TOTAL * D_INNER];
__device__ __half g_wih [(size_t)(2*D_INNER) * D_MODEL];
__device__ __half g_wil [(size_t)(2*D_INNER) * D_MODEL];
__device__ __half g_wdh [(size_t)D_INNER * D_INNER];
__device__ __half g_wdl [(size_t)D_INNER * D_INNER];
__device__ __half g_woh [(size_t)D_MODEL * D_INNER];
__device__ __half g_wol [(size_t)D_MODEL * D_INNER];
__device__ float g_carry[BATCH * NCH * D_INNER];
__device__ float g_hin  [BATCH * NCH * D_INNER];

// ---------------- helpers ----------------
__device__ __forceinline__ uint32_t smem_u32(const void* p) {
    uint32_t a;
    asm("{ .reg .u64 t; cvta.to.shared.u64 t, %1; cvt.u32.u64 %0, t; }" : "=r"(a) : "l"(p));
    return a;
}
__device__ __forceinline__ void cp16(uint32_t saddr, const void* g) {
    asm volatile("cp.async.cg.shared.global [%0], [%1], 16;" :: "r"(saddr), "l"(g) : "memory");
}
__device__ __forceinline__ float silu_f(float x) { return x / (1.0f + expf(-x)); }
__device__ __forceinline__ float softplus_f(float x) { return (x > 20.0f) ? x : log1pf(expf(x)); }
__device__ __forceinline__ void split_fp16(float v, __half& h, __half& l) {
    h = __float2half(v);
    l = __float2half(v - __half2float(h));
}

// ---------------- mma.sync fp16 GEMM, weight hi/lo fused ----------------
// C[M,N] = A[M,K] @ (Bh+Bl)[N,K]^T   (2 MMA combos per fragment load)
// Weights split exactly into fp16 hi+lo (error ~2^-24); activations single
// fp16 (error ~2^-12) -> end-to-end rel err a few e-4, under the 1e-3 gate.
// MODE 0/2: C = acc + bias      MODE 1: C = softplus(acc+bias) * aux
#define BM 128
#define BN 128
#define BK 64          // fp16 K per stage
#define AST 72         // smem row stride (halves): 144B, conflict-free ldmatrix
#define TILE_H (BM * AST)          // 9216 halves = 18KB
#define STAGE_H (3 * TILE_H)       // A | Bh | Bl  (54KB)
#define OFF_A  0
#define OFF_BH TILE_H
#define OFF_BL (2 * TILE_H)
#define GSMEM_BYTES (2 * STAGE_H * 2)   // 110592

template <int MODE>
__global__ __launch_bounds__(256)
void gemm_mma(const __half* __restrict__ A,
              const __half* __restrict__ Bh, const __half* __restrict__ Bl,
              const float* __restrict__ bias, float* __restrict__ C,
              const float* __restrict__ aux, int M, int N, int K)
{
    extern __shared__ __half smem[];

    const int tid  = threadIdx.x;
    const int wid  = tid >> 5;
    const int lane = tid & 31;
    const int bm = blockIdx.y * BM;
    const int bn = blockIdx.x * BN;
    const int wm = (wid >> 2) * 64;   // warp m offset (0 or 64)
    const int wn = (wid & 3) * 32;    // warp n offset (0,32,64,96)

    const __half* Aa  = A  + (size_t)bm * K;
    const __half* Bbh = Bh + (size_t)bn * K;
    const __half* Bbl = Bl + (size_t)bn * K;

    const int nst = K / BK;

    float acc[4][4][4];
    #pragma unroll
    for (int i = 0; i < 4; i++)
        #pragma unroll
        for (int j = 0; j < 4; j++)
            #pragma unroll
            for (int r = 0; r < 4; r++) acc[i][j][r] = 0.0f;

    // loader: per tile 128 rows x 64 halves = 1024 x 16B segs; 3 tiles
    auto load_stage = [&](int s, int buf) {
        const int kb = s * BK;
        __half* st = smem + buf * STAGE_H;
        #pragma unroll
        for (int it = 0; it < 4; it++) {
            int seg = tid + it * 256;       // 0..1023
            int r = seg >> 3;
            int q = (seg & 7) * 8;
            size_t go = (size_t)r * K + kb + q;
            int so = r * AST + q;
            cp16(smem_u32(st + OFF_A  + so), Aa  + go);
            cp16(smem_u32(st + OFF_BH + so), Bbh + go);
            cp16(smem_u32(st + OFF_BL + so), Bbl + go);
        }
        asm volatile("cp.async.commit_group;" ::: "memory");
    };

    load_stage(0, 0);
    asm volatile("cp.async.wait_group 0;" ::: "memory");
    __syncthreads();

    for (int s = 0; s < nst; s++) {
        const int buf = s & 1;
        if (s + 1 < nst) load_stage(s + 1, buf ^ 1);

        const __half* st = smem + buf * STAGE_H;
        #pragma unroll
        for (int kk = 0; kk < 4; kk++) {
            uint32_t a[4][4], bh[4][2], bl[4][2];
            #pragma unroll
            for (int mf = 0; mf < 4; mf++) {
                int so = (wm + mf * 16 + (lane & 15)) * AST + kk * 16 + (lane >> 4) * 8;
                uint32_t ad = smem_u32(st + OFF_A + so);
                asm volatile("ldmatrix.sync.aligned.m8n8.x4.shared.b16 {%0,%1,%2,%3}, [%4];"
                             : "=r"(a[mf][0]), "=r"(a[mf][1]), "=r"(a[mf][2]), "=r"(a[mf][3]) : "r"(ad));
            }
            // B: one ldmatrix.x4 covers 2 nf tiles (n16 x k16):
            // lanes 0-7 -> (nf0,k0-7), 8-15 -> (nf0,k8-15),
            // lanes 16-23 -> (nf1,k0-7), 24-31 -> (nf1,k8-15)
            #pragma unroll
            for (int nfp = 0; nfp < 2; nfp++) {
                int nfq   = nfp * 2 + ((lane >> 4) & 1);
                int khalf = (lane >> 3) & 1;
                int so = (wn + nfq * 8 + (lane & 7)) * AST + kk * 16 + khalf * 8;
                uint32_t bdh = smem_u32(st + OFF_BH + so);
                uint32_t bdl = smem_u32(st + OFF_BL + so);
                asm volatile("ldmatrix.sync.aligned.m8n8.x4.shared.b16 {%0,%1,%2,%3}, [%4];"
                             : "=r"(bh[nfp*2][0]), "=r"(bh[nfp*2][1]),
                               "=r"(bh[nfp*2+1][0]), "=r"(bh[nfp*2+1][1]) : "r"(bdh));
                asm volatile("ldmatrix.sync.aligned.m8n8.x4.shared.b16 {%0,%1,%2,%3}, [%4];"
                             : "=r"(bl[nfp*2][0]), "=r"(bl[nfp*2][1]),
                               "=r"(bl[nfp*2+1][0]), "=r"(bl[nfp*2+1][1]) : "r"(bdl));
            }
            #pragma unroll
            for (int mf = 0; mf < 4; mf++)
                #pragma unroll
                for (int nf = 0; nf < 4; nf++) {
                    asm volatile(
                        "mma.sync.aligned.m16n8k16.row.col.f32.f16.f16.f32 "
                        "{%0,%1,%2,%3}, {%4,%5,%6,%7}, {%8,%9}, {%0,%1,%2,%3};"
                        : "+f"(acc[mf][nf][0]), "+f"(acc[mf][nf][1]),
                          "+f"(acc[mf][nf][2]), "+f"(acc[mf][nf][3])
                        : "r"(a[mf][0]), "r"(a[mf][1]), "r"(a[mf][2]), "r"(a[mf][3]),
                          "r"(bh[nf][0]), "r"(bh[nf][1]));
                    asm volatile(
                        "mma.sync.aligned.m16n8k16.row.col.f32.f16.f16.f32 "
                        "{%0,%1,%2,%3}, {%4,%5,%6,%7}, {%8,%9}, {%0,%1,%2,%3};"
                        : "+f"(acc[mf][nf][0]), "+f"(acc[mf][nf][1]),
                          "+f"(acc[mf][nf][2]), "+f"(acc[mf][nf][3])
                        : "r"(a[mf][0]), "r"(a[mf][1]), "r"(a[mf][2]), "r"(a[mf][3]),
                          "r"(bl[nf][0]), "r"(bl[nf][1]));
                }
        }

        if (s + 1 < nst) { asm volatile("cp.async.wait_group 0;" ::: "memory"); }
        __syncthreads();
    }

    // epilogue: acc regs -> global (float2 stores)
    const int tr = lane >> 2;          // 0..7
    const int tc = (lane & 3) * 2;     // 0,2,4,6
    #pragma unroll
    for (int mf = 0; mf < 4; mf++) {
        #pragma unroll
        for (int h = 0; h < 2; h++) {
            int gm = bm + wm + mf * 16 + tr + h * 8;
            size_t rb = (size_t)gm * N;
            #pragma unroll
            for (int nf = 0; nf < 4; nf++) {
                int gn = bn + wn + nf * 8 + tc;
                float v0 = acc[mf][nf][h * 2 + 0] + bias[gn];
                float v1 = acc[mf][nf][h * 2 + 1] + bias[gn + 1];
                if (MODE == 1) {
                    float2 ax = *reinterpret_cast<const float2*>(aux + rb + gn);
                    v0 = softplus_f(v0) * ax.x;
                    v1 = softplus_f(v1) * ax.y;
                }
                float2 o; o.x = v0; o.y = v1;
                *reinterpret_cast<float2*>(C + rb + gn) = o;
            }
        }
    }
}

// ---------------- conversions ----------------
// weights: fp32 -> fp16 hi/lo (x4 vectorized)
__global__ void cvtw_kernel(const float* __restrict__ s, __half* __restrict__ h,
                            __half* __restrict__ l, int n4)
{
    int i = blockIdx.x * 256 + threadIdx.x;
    if (i >= n4) return;
    float4 v = reinterpret_cast<const float4*>(s)[i];
    __half hh[4], ll[4];
    split_fp16(v.x, hh[0], ll[0]);
    split_fp16(v.y, hh[1], ll[1]);
    split_fp16(v.z, hh[2], ll[2]);
    split_fp16(v.w, hh[3], ll[3]);
    reinterpret_cast<__half2*>(h)[2*i]   = __halves2half2(hh[0], hh[1]);
    reinterpret_cast<__half2*>(h)[2*i+1] = __halves2half2(hh[2], hh[3]);
    reinterpret_cast<__half2*>(l)[2*i]   = __halves2half2(ll[0], ll[1]);
    reinterpret_cast<__half2*>(l)[2*i+1] = __halves2half2(ll[2], ll[3]);
}

// activations: fp32 -> single fp16 (x4 vectorized)
__global__ void cvta_kernel(const float* __restrict__ s, __half* __restrict__ h, int n4)
{
    int i = blockIdx.x * 256 + threadIdx.x;
    if (i >= n4) return;
    float4 v = reinterpret_cast<const float4*>(s)[i];
    reinterpret_cast<__half2*>(h)[2*i]   = __halves2half2(__float2half(v.x), __float2half(v.y));
    reinterpret_cast<__half2*>(h)[2*i+1] = __halves2half2(__float2half(v.z), __float2half(v.w));
}

// ---------------- depthwise causal conv (width 4) + SiLU ----------------
__global__ void conv_silu_kernel(const float* __restrict__ xz,
                                 const float* __restrict__ Wc,
                                 const float* __restrict__ bc,
                                 float* __restrict__ xconv,
                                 __half* __restrict__ xcf)
{
    int idx = blockIdx.x * blockDim.x + threadIdx.x;
    if (idx >= M_TOTAL * D_INNER) return;
    int c = idx & (D_INNER - 1);
    int m = idx >> 11;
    int t = m & (SEQ - 1);

    float4 w = *reinterpret_cast<const float4*>(Wc + c * 4);
    float acc = bc[c];
    const size_t st = 2 * D_INNER;
    size_t base = (size_t)m * st + c;

    if (t >= 3) {
        acc += w.x * xz[base - 3 * st] + w.y * xz[base - 2 * st]
             + w.z * xz[base - st]     + w.w * xz[base];
    } else {
        acc += w.w * xz[base];
        if (t >= 1) acc += w.z * xz[base - st];
        if (t >= 2) acc += w.y * xz[base - 2 * st];
    }
    float v = silu_f(acc);
    xconv[idx] = v;
    xcf[idx] = __float2half(v);
}

// ---------------- chunked scan ----------------
__global__ void scanA_kernel(const float* __restrict__ vals, const float* __restrict__ decay,
                             float* __restrict__ carry)
{
    int idx = blockIdx.x * 256 + threadIdx.x;      // 131072
    if (idx >= BATCH * NCH * D_INNER) return;
    int c = idx & (D_INNER - 1);
    int ch = (idx >> 11) & (NCH - 1);
    int b = idx >> 15;
    float d = decay[c];
    float h = 0.0f;
    size_t base = ((size_t)(b * SEQ + ch * LCH)) * D_INNER + c;
    #pragma unroll 8
    for (int i = 0; i < LCH; i++)
        h = fmaf(d, h, vals[base + (size_t)i * D_INNER]);
    carry[(b * NCH + ch) * D_INNER + c] = h;
}

__global__ void scanB_kernel(const float* __restrict__ carry, const float* __restrict__ decay,
                             float* __restrict__ hin)
{
    int idx = blockIdx.x * 256 + threadIdx.x;      // 8192
    if (idx >= BATCH * D_INNER) return;
    int c = idx & (D_INNER - 1);
    int b = idx >> 11;
    float d = decay[c];
    float dL = d;
    #pragma unroll
    for (int j = 0; j < 7; j++) dL = dL * dL;      // d^128
    float H = 0.0f;
    for (int ch = 0; ch < NCH; ch++) {
        int o = (b * NCH + ch) * D_INNER + c;
        hin[o] = H;
        H = fmaf(dL, H, carry[o]);
    }
}

__global__ void scanC_kernel(const float* __restrict__ vals, const float* __restrict__ xz,
                             const float* __restrict__ decay, const float* __restrict__ hin,
                             __half* __restrict__ yf)
{
    int idx = blockIdx.x * 256 + threadIdx.x;
    if (idx >= BATCH * NCH * D_INNER) return;
    int c = idx & (D_INNER - 1);
    int ch = (idx >> 11) & (NCH - 1);
    int b = idx >> 15;
    float d = decay[c];
    float h = hin[(b * NCH + ch) * D_INNER + c];
    size_t m0 = (size_t)(b * SEQ + ch * LCH);
    size_t vbase = m0 * D_INNER + c;
    size_t zbase = m0 * (2 * D_INNER) + D_INNER + c;
    #pragma unroll 8
    for (int i = 0; i < LCH; i++) {
        h = fmaf(d, h, vals[vbase + (size_t)i * D_INNER]);
        float z = xz[zbase + (size_t)i * (2 * D_INNER)];
        yf[vbase + (size_t)i * D_INNER] = __float2half(h * silu_f(z));
    }
}

// ---------------- launcher ----------------
extern "C" void kernel_launch(void* const* d_in, const int* in_sizes, int n_in,
                              void* d_out, int out_size)
{
    const float* x      = (const float*)d_in[0];
    const float* W_in   = (const float*)d_in[1];
    const float* b_in   = (const float*)d_in[2];
    const float* W_conv = (const float*)d_in[3];
    const float* b_conv = (const float*)d_in[4];
    const float* W_dt   = (const float*)d_in[5];
    const float* b_dt   = (const float*)d_in[6];
    const float* W_out  = (const float*)d_in[7];
    const float* b_out  = (const float*)d_in[8];
    const float* decay  = (const float*)d_in[9];
    float* out = (float*)d_out;

    float *xz, *xconv, *vals, *carry, *hin;
    __half *xf, *xcf, *yf, *wih, *wil, *wdh, *wdl, *woh, *wol;
    cudaGetSymbolAddress((void**)&xz, g_xz);
    cudaGetSymbolAddress((void**)&xconv, g_xconv);
    cudaGetSymbolAddress((void**)&vals, g_vals);
    cudaGetSymbolAddress((void**)&carry, g_carry);
    cudaGetSymbolAddress((void**)&hin, g_hin);
    cudaGetSymbolAddress((void**)&xf, g_xf);
    cudaGetSymbolAddress((void**)&xcf, g_xcf);
    cudaGetSymbolAddress((void**)&yf, g_yf);
    cudaGetSymbolAddress((void**)&wih, g_wih);
    cudaGetSymbolAddress((void**)&wil, g_wil);
    cudaGetSymbolAddress((void**)&wdh, g_wdh);
    cudaGetSymbolAddress((void**)&wdl, g_wdl);
    cudaGetSymbolAddress((void**)&woh, g_woh);
    cudaGetSymbolAddress((void**)&wol, g_wol);

    cudaFuncSetAttribute(gemm_mma<0>, cudaFuncAttributeMaxDynamicSharedMemorySize, GSMEM_BYTES);
    cudaFuncSetAttribute(gemm_mma<1>, cudaFuncAttributeMaxDynamicSharedMemorySize, GSMEM_BYTES);
    cudaFuncSetAttribute(gemm_mma<2>, cudaFuncAttributeMaxDynamicSharedMemorySize, GSMEM_BYTES);

    // conversions
    cvta_kernel<<<(M_TOTAL * D_MODEL / 4 + 255) / 256, 256>>>(x, xf, M_TOTAL * D_MODEL / 4);
    cvtw_kernel<<<(2 * D_INNER * D_MODEL / 4 + 255) / 256, 256>>>(W_in, wih, wil, 2 * D_INNER * D_MODEL / 4);
    cvtw_kernel<<<(D_INNER * D_INNER / 4 + 255) / 256, 256>>>(W_dt, wdh, wdl, D_INNER * D_INNER / 4);
    cvtw_kernel<<<(D_MODEL * D_INNER / 4 + 255) / 256, 256>>>(W_out, woh, wol, D_MODEL * D_INNER / 4);

    // GEMM1: xz = x @ W_in^T + b_in   [8192, 4096], K=1024
    gemm_mma<0><<<dim3((2 * D_INNER) / BN, M_TOTAL / BM), 256, GSMEM_BYTES>>>(
        xf, wih, wil, b_in, xz, nullptr, M_TOTAL, 2 * D_INNER, D_MODEL);

    // conv + silu
    conv_silu_kernel<<<(M_TOTAL * D_INNER) / 256, 256>>>(xz, W_conv, b_conv, xconv, xcf);

    // GEMM2: vals = softplus(xconv @ W_dt^T + b_dt) * xconv   [8192, 2048], K=2048
    gemm_mma<1><<<dim3(D_INNER / BN, M_TOTAL / BM), 256, GSMEM_BYTES>>>(
        xcf, wdh, wdl, b_dt, vals, xconv, M_TOTAL, D_INNER, D_INNER);

    // chunked scan + gate -> y (fp16)
    scanA_kernel<<<(BATCH * NCH * D_INNER) / 256, 256>>>(vals, decay, carry);
    scanB_kernel<<<(BATCH * D_INNER) / 256, 256>>>(carry, decay, hin);
    scanC_kernel<<<(BATCH * NCH * D_INNER) / 256, 256>>>(vals, xz, decay, hin, yf);

    // GEMM3: out = y @ W_out^T + b_out   [8192, 1024], K=2048
    gemm_mma<2><<<dim3(D_MODEL / BN, M_TOTAL / BM), 256, GSMEM_BYTES>>>(
        yf, woh, wol, b_out, out, nullptr, M_TOTAL, D_MODEL, D_INNER);
}

// round 10
// speedup vs baseline: 3.2660x; 1.0351x over previous
#include <cuda_runtime.h>
#include <cuda_fp16.h>
#include <cstdint>
#include <cstddef>

#define D_MODEL 1024
#define D_INNER 2048
#define BATCH   4
#define SEQ     2048
#define M_TOTAL (BATCH * SEQ)   // 8192
#define NCH     16              // scan chunks per sequence
#define LCH     (SEQ / NCH)     // 128

// ---------------- scratch (device globals; no allocation) ----------------
__device__ float g_xz   [(size_t)M_TOTAL * (2 * D_INNER)];  // 8192 x 4096
__device__ float g_xconv[(size_t)M_TOTAL * D_INNER];
__device__ float g_vals [(size_t)M_TOTAL * D_INNER];

__device__ __half g_xf  [(size_t)M_TOTAL * D_MODEL];
__device__ __half g_xcf [(size_t)M_TOTAL * D_INNER];
__device__ __half g_yf  [(size_t)M_TOTAL * D_INNER];
__device__ __half g_wih [(size_t)(2*D_INNER) * D_MODEL];
__device__ __half g_wil [(size_t)(2*D_INNER) * D_MODEL];
__device__ __half g_wdh [(size_t)D_INNER * D_INNER];
__device__ __half g_wdl [(size_t)D_INNER * D_INNER];
__device__ __half g_woh [(size_t)D_MODEL * D_INNER];
__device__ __half g_wol [(size_t)D_MODEL * D_INNER];
__device__ float g_carry[BATCH * NCH * D_INNER];
__device__ float g_hin  [BATCH * NCH * D_INNER];

// ---------------- helpers ----------------
__device__ __forceinline__ uint32_t smem_u32(const void* p) {
    uint32_t a;
    asm("{ .reg .u64 t; cvta.to.shared.u64 t, %1; cvt.u32.u64 %0, t; }" : "=r"(a) : "l"(p));
    return a;
}
__device__ __forceinline__ void cp16(uint32_t saddr, const void* g) {
    asm volatile("cp.async.cg.shared.global [%0], [%1], 16;" :: "r"(saddr), "l"(g) : "memory");
}
__device__ __forceinline__ float silu_f(float x) { return x / (1.0f + expf(-x)); }
__device__ __forceinline__ float softplus_f(float x) { return (x > 20.0f) ? x : log1pf(expf(x)); }
__device__ __forceinline__ void split_fp16(float v, __half& h, __half& l) {
    h = __float2half(v);
    l = __float2half(v - __half2float(h));
}

// ---------------- mma.sync fp16 GEMM, weight hi/lo fused ----------------
// C[M,N] = A[M,K] @ (Bh+Bl)[N,K]^T
// CTA tile 128x256, 8 warps as 2x4 -> 64x64 warp tile.
// MODE 0/2: C = acc + bias      MODE 1: C = softplus(acc+bias) * aux
#define BM 128
#define BN 256
#define BK 64          // fp16 K per stage
#define AST 72         // smem row stride (halves): 144B, conflict-free ldmatrix
#define TILE_A_H (BM * AST)            // 9216 halves (18KB)
#define TILE_B_H (BN * AST)            // 18432 halves (36KB)
#define STAGE_H (TILE_A_H + 2 * TILE_B_H)   // A | Bh | Bl  (90KB)
#define OFF_A  0
#define OFF_BH TILE_A_H
#define OFF_BL (TILE_A_H + TILE_B_H)
#define GSMEM_BYTES (2 * STAGE_H * 2)  // 184320

template <int MODE>
__global__ __launch_bounds__(256)
void gemm_mma(const __half* __restrict__ A,
              const __half* __restrict__ Bh, const __half* __restrict__ Bl,
              const float* __restrict__ bias, float* __restrict__ C,
              const float* __restrict__ aux, int M, int N, int K)
{
    extern __shared__ __half smem[];

    const int tid  = threadIdx.x;
    const int wid  = tid >> 5;
    const int lane = tid & 31;
    const int bm = blockIdx.y * BM;
    const int bn = blockIdx.x * BN;
    const int wm = (wid >> 2) * 64;   // warp m offset (0 or 64)
    const int wn = (wid & 3) * 64;    // warp n offset (0,64,128,192)

    const __half* Aa  = A  + (size_t)bm * K;
    const __half* Bbh = Bh + (size_t)bn * K;
    const __half* Bbl = Bl + (size_t)bn * K;

    const int nst = K / BK;

    float acc[4][8][4];
    #pragma unroll
    for (int i = 0; i < 4; i++)
        #pragma unroll
        for (int j = 0; j < 8; j++)
            #pragma unroll
            for (int r = 0; r < 4; r++) acc[i][j][r] = 0.0f;

    // loader: A 128 rows, Bh/Bl 256 rows; 64 halves (8 x 16B segs) per row
    auto load_stage = [&](int s, int buf) {
        const int kb = s * BK;
        __half* st = smem + buf * STAGE_H;
        #pragma unroll
        for (int it = 0; it < 4; it++) {           // A: 1024 segs
            int seg = tid + it * 256;
            int r = seg >> 3;
            int q = (seg & 7) * 8;
            cp16(smem_u32(st + OFF_A + r * AST + q), Aa + (size_t)r * K + kb + q);
        }
        #pragma unroll
        for (int it = 0; it < 8; it++) {           // Bh: 2048 segs
            int seg = tid + it * 256;
            int r = seg >> 3;
            int q = (seg & 7) * 8;
            cp16(smem_u32(st + OFF_BH + r * AST + q), Bbh + (size_t)r * K + kb + q);
        }
        #pragma unroll
        for (int it = 0; it < 8; it++) {           // Bl: 2048 segs
            int seg = tid + it * 256;
            int r = seg >> 3;
            int q = (seg & 7) * 8;
            cp16(smem_u32(st + OFF_BL + r * AST + q), Bbl + (size_t)r * K + kb + q);
        }
        asm volatile("cp.async.commit_group;" ::: "memory");
    };

    load_stage(0, 0);
    asm volatile("cp.async.wait_group 0;" ::: "memory");
    __syncthreads();

    for (int s = 0; s < nst; s++) {
        const int buf = s & 1;
        if (s + 1 < nst) load_stage(s + 1, buf ^ 1);

        const __half* st = smem + buf * STAGE_H;
        #pragma unroll
        for (int kk = 0; kk < 4; kk++) {
            uint32_t a[4][4];
            #pragma unroll
            for (int mf = 0; mf < 4; mf++) {
                int so = (wm + mf * 16 + (lane & 15)) * AST + kk * 16 + (lane >> 4) * 8;
                uint32_t ad = smem_u32(st + OFF_A + so);
                asm volatile("ldmatrix.sync.aligned.m8n8.x4.shared.b16 {%0,%1,%2,%3}, [%4];"
                             : "=r"(a[mf][0]), "=r"(a[mf][1]), "=r"(a[mf][2]), "=r"(a[mf][3]) : "r"(ad));
            }
            // B in two nf-halves to bound register pressure
            #pragma unroll
            for (int half = 0; half < 2; half++) {
                uint32_t bh[4][2], bl[4][2];
                #pragma unroll
                for (int nfp = 0; nfp < 2; nfp++) {
                    int nfq   = half * 4 + nfp * 2 + ((lane >> 4) & 1);
                    int khalf = (lane >> 3) & 1;
                    int so = (wn + nfq * 8 + (lane & 7)) * AST + kk * 16 + khalf * 8;
                    uint32_t bdh = smem_u32(st + OFF_BH + so);
                    uint32_t bdl = smem_u32(st + OFF_BL + so);
                    asm volatile("ldmatrix.sync.aligned.m8n8.x4.shared.b16 {%0,%1,%2,%3}, [%4];"
                                 : "=r"(bh[nfp*2][0]), "=r"(bh[nfp*2][1]),
                                   "=r"(bh[nfp*2+1][0]), "=r"(bh[nfp*2+1][1]) : "r"(bdh));
                    asm volatile("ldmatrix.sync.aligned.m8n8.x4.shared.b16 {%0,%1,%2,%3}, [%4];"
                                 : "=r"(bl[nfp*2][0]), "=r"(bl[nfp*2][1]),
                                   "=r"(bl[nfp*2+1][0]), "=r"(bl[nfp*2+1][1]) : "r"(bdl));
                }
                #pragma unroll
                for (int mf = 0; mf < 4; mf++)
                    #pragma unroll
                    for (int nf = 0; nf < 4; nf++) {
                        int nfg = half * 4 + nf;
                        asm volatile(
                            "mma.sync.aligned.m16n8k16.row.col.f32.f16.f16.f32 "
                            "{%0,%1,%2,%3}, {%4,%5,%6,%7}, {%8,%9}, {%0,%1,%2,%3};"
                            : "+f"(acc[mf][nfg][0]), "+f"(acc[mf][nfg][1]),
                              "+f"(acc[mf][nfg][2]), "+f"(acc[mf][nfg][3])
                            : "r"(a[mf][0]), "r"(a[mf][1]), "r"(a[mf][2]), "r"(a[mf][3]),
                              "r"(bh[nf][0]), "r"(bh[nf][1]));
                        asm volatile(
                            "mma.sync.aligned.m16n8k16.row.col.f32.f16.f16.f32 "
                            "{%0,%1,%2,%3}, {%4,%5,%6,%7}, {%8,%9}, {%0,%1,%2,%3};"
                            : "+f"(acc[mf][nfg][0]), "+f"(acc[mf][nfg][1]),
                              "+f"(acc[mf][nfg][2]), "+f"(acc[mf][nfg][3])
                            : "r"(a[mf][0]), "r"(a[mf][1]), "r"(a[mf][2]), "r"(a[mf][3]),
                              "r"(bl[nf][0]), "r"(bl[nf][1]));
                    }
            }
        }

        if (s + 1 < nst) { asm volatile("cp.async.wait_group 0;" ::: "memory"); }
        __syncthreads();
    }

    // epilogue: acc regs -> global (float2 stores)
    const int tr = lane >> 2;          // 0..7
    const int tc = (lane & 3) * 2;     // 0,2,4,6
    #pragma unroll
    for (int mf = 0; mf < 4; mf++) {
        #pragma unroll
        for (int h = 0; h < 2; h++) {
            int gm = bm + wm + mf * 16 + tr + h * 8;
            size_t rb = (size_t)gm * N;
            #pragma unroll
            for (int nf = 0; nf < 8; nf++) {
                int gn = bn + wn + nf * 8 + tc;
                float v0 = acc[mf][nf][h * 2 + 0] + bias[gn];
                float v1 = acc[mf][nf][h * 2 + 1] + bias[gn + 1];
                if (MODE == 1) {
                    float2 ax = *reinterpret_cast<const float2*>(aux + rb + gn);
                    v0 = softplus_f(v0) * ax.x;
                    v1 = softplus_f(v1) * ax.y;
                }
                float2 o; o.x = v0; o.y = v1;
                *reinterpret_cast<float2*>(C + rb + gn) = o;
            }
        }
    }
}

// ---------------- conversions ----------------
__global__ void cvtw_kernel(const float* __restrict__ s, __half* __restrict__ h,
                            __half* __restrict__ l, int n4)
{
    int i = blockIdx.x * 256 + threadIdx.x;
    if (i >= n4) return;
    float4 v = reinterpret_cast<const float4*>(s)[i];
    __half hh[4], ll[4];
    split_fp16(v.x, hh[0], ll[0]);
    split_fp16(v.y, hh[1], ll[1]);
    split_fp16(v.z, hh[2], ll[2]);
    split_fp16(v.w, hh[3], ll[3]);
    reinterpret_cast<__half2*>(h)[2*i]   = __halves2half2(hh[0], hh[1]);
    reinterpret_cast<__half2*>(h)[2*i+1] = __halves2half2(hh[2], hh[3]);
    reinterpret_cast<__half2*>(l)[2*i]   = __halves2half2(ll[0], ll[1]);
    reinterpret_cast<__half2*>(l)[2*i+1] = __halves2half2(ll[2], ll[3]);
}

__global__ void cvta_kernel(const float* __restrict__ s, __half* __restrict__ h, int n4)
{
    int i = blockIdx.x * 256 + threadIdx.x;
    if (i >= n4) return;
    float4 v = reinterpret_cast<const float4*>(s)[i];
    reinterpret_cast<__half2*>(h)[2*i]   = __halves2half2(__float2half(v.x), __float2half(v.y));
    reinterpret_cast<__half2*>(h)[2*i+1] = __halves2half2(__float2half(v.z), __float2half(v.w));
}

// ---------------- depthwise causal conv (width 4) + SiLU ----------------
__global__ void conv_silu_kernel(const float* __restrict__ xz,
                                 const float* __restrict__ Wc,
                                 const float* __restrict__ bc,
                                 float* __restrict__ xconv,
                                 __half* __restrict__ xcf)
{
    int idx = blockIdx.x * blockDim.x + threadIdx.x;
    if (idx >= M_TOTAL * D_INNER) return;
    int c = idx & (D_INNER - 1);
    int m = idx >> 11;
    int t = m & (SEQ - 1);

    float4 w = *reinterpret_cast<const float4*>(Wc + c * 4);
    float acc = bc[c];
    const size_t st = 2 * D_INNER;
    size_t base = (size_t)m * st + c;

    if (t >= 3) {
        acc += w.x * xz[base - 3 * st] + w.y * xz[base - 2 * st]
             + w.z * xz[base - st]     + w.w * xz[base];
    } else {
        acc += w.w * xz[base];
        if (t >= 1) acc += w.z * xz[base - st];
        if (t >= 2) acc += w.y * xz[base - 2 * st];
    }
    float v = silu_f(acc);
    xconv[idx] = v;
    xcf[idx] = __float2half(v);
}

// ---------------- chunked scan ----------------
__global__ void scanA_kernel(const float* __restrict__ vals, const float* __restrict__ decay,
                             float* __restrict__ carry)
{
    int idx = blockIdx.x * 256 + threadIdx.x;      // 131072
    if (idx >= BATCH * NCH * D_INNER) return;
    int c = idx & (D_INNER - 1);
    int ch = (idx >> 11) & (NCH - 1);
    int b = idx >> 15;
    float d = decay[c];
    float h = 0.0f;
    size_t base = ((size_t)(b * SEQ + ch * LCH)) * D_INNER + c;
    #pragma unroll 8
    for (int i = 0; i < LCH; i++)
        h = fmaf(d, h, vals[base + (size_t)i * D_INNER]);
    carry[(b * NCH + ch) * D_INNER + c] = h;
}

__global__ void scanB_kernel(const float* __restrict__ carry, const float* __restrict__ decay,
                             float* __restrict__ hin)
{
    int idx = blockIdx.x * 256 + threadIdx.x;      // 8192
    if (idx >= BATCH * D_INNER) return;
    int c = idx & (D_INNER - 1);
    int b = idx >> 11;
    float d = decay[c];
    float dL = d;
    #pragma unroll
    for (int j = 0; j < 7; j++) dL = dL * dL;      // d^128
    float H = 0.0f;
    for (int ch = 0; ch < NCH; ch++) {
        int o = (b * NCH + ch) * D_INNER + c;
        hin[o] = H;
        H = fmaf(dL, H, carry[o]);
    }
}

__global__ void scanC_kernel(const float* __restrict__ vals, const float* __restrict__ xz,
                             const float* __restrict__ decay, const float* __restrict__ hin,
                             __half* __restrict__ yf)
{
    int idx = blockIdx.x * 256 + threadIdx.x;
    if (idx >= BATCH * NCH * D_INNER) return;
    int c = idx & (D_INNER - 1);
    int ch = (idx >> 11) & (NCH - 1);
    int b = idx >> 15;
    float d = decay[c];
    float h = hin[(b * NCH + ch) * D_INNER + c];
    size_t m0 = (size_t)(b * SEQ + ch * LCH);
    size_t vbase = m0 * D_INNER + c;
    size_t zbase = m0 * (2 * D_INNER) + D_INNER + c;
    #pragma unroll 8
    for (int i = 0; i < LCH; i++) {
        h = fmaf(d, h, vals[vbase + (size_t)i * D_INNER]);
        float z = xz[zbase + (size_t)i * (2 * D_INNER)];
        yf[vbase + (size_t)i * D_INNER] = __float2half(h * silu_f(z));
    }
}

// ---------------- launcher ----------------
extern "C" void kernel_launch(void* const* d_in, const int* in_sizes, int n_in,
                              void* d_out, int out_size)
{
    const float* x      = (const float*)d_in[0];
    const float* W_in   = (const float*)d_in[1];
    const float* b_in   = (const float*)d_in[2];
    const float* W_conv = (const float*)d_in[3];
    const float* b_conv = (const float*)d_in[4];
    const float* W_dt   = (const float*)d_in[5];
    const float* b_dt   = (const float*)d_in[6];
    const float* W_out  = (const float*)d_in[7];
    const float* b_out  = (const float*)d_in[8];
    const float* decay  = (const float*)d_in[9];
    float* out = (float*)d_out;

    float *xz, *xconv, *vals, *carry, *hin;
    __half *xf, *xcf, *yf, *wih, *wil, *wdh, *wdl, *woh, *wol;
    cudaGetSymbolAddress((void**)&xz, g_xz);
    cudaGetSymbolAddress((void**)&xconv, g_xconv);
    cudaGetSymbolAddress((void**)&vals, g_vals);
    cudaGetSymbolAddress((void**)&carry, g_carry);
    cudaGetSymbolAddress((void**)&hin, g_hin);
    cudaGetSymbolAddress((void**)&xf, g_xf);
    cudaGetSymbolAddress((void**)&xcf, g_xcf);
    cudaGetSymbolAddress((void**)&yf, g_yf);
    cudaGetSymbolAddress((void**)&wih, g_wih);
    cudaGetSymbolAddress((void**)&wil, g_wil);
    cudaGetSymbolAddress((void**)&wdh, g_wdh);
    cudaGetSymbolAddress((void**)&wdl, g_wdl);
    cudaGetSymbolAddress((void**)&woh, g_woh);
    cudaGetSymbolAddress((void**)&wol, g_wol);

    cudaFuncSetAttribute(gemm_mma<0>, cudaFuncAttributeMaxDynamicSharedMemorySize, GSMEM_BYTES);
    cudaFuncSetAttribute(gemm_mma<1>, cudaFuncAttributeMaxDynamicSharedMemorySize, GSMEM_BYTES);
    cudaFuncSetAttribute(gemm_mma<2>, cudaFuncAttributeMaxDynamicSharedMemorySize, GSMEM_BYTES);

    // conversions
    cvta_kernel<<<(M_TOTAL * D_MODEL / 4 + 255) / 256, 256>>>(x, xf, M_TOTAL * D_MODEL / 4);
    cvtw_kernel<<<(2 * D_INNER * D_MODEL / 4 + 255) / 256, 256>>>(W_in, wih, wil, 2 * D_INNER * D_MODEL / 4);
    cvtw_kernel<<<(D_INNER * D_INNER / 4 + 255) / 256, 256>>>(W_dt, wdh, wdl, D_INNER * D_INNER / 4);
    cvtw_kernel<<<(D_MODEL * D_INNER / 4 + 255) / 256, 256>>>(W_out, woh, wol, D_MODEL * D_INNER / 4);

    // GEMM1: xz = x @ W_in^T + b_in   [8192, 4096], K=1024
    gemm_mma<0><<<dim3((2 * D_INNER) / BN, M_TOTAL / BM), 256, GSMEM_BYTES>>>(
        xf, wih, wil, b_in, xz, nullptr, M_TOTAL, 2 * D_INNER, D_MODEL);

    // conv + silu
    conv_silu_kernel<<<(M_TOTAL * D_INNER) / 256, 256>>>(xz, W_conv, b_conv, xconv, xcf);

    // GEMM2: vals = softplus(xconv @ W_dt^T + b_dt) * xconv   [8192, 2048], K=2048
    gemm_mma<1><<<dim3(D_INNER / BN, M_TOTAL / BM), 256, GSMEM_BYTES>>>(
        xcf, wdh, wdl, b_dt, vals, xconv, M_TOTAL, D_INNER, D_INNER);

    // chunked scan + gate -> y (fp16)
    scanA_kernel<<<(BATCH * NCH * D_INNER) / 256, 256>>>(vals, decay, carry);
    scanB_kernel<<<(BATCH * D_INNER) / 256, 256>>>(carry, decay, hin);
    scanC_kernel<<<(BATCH * NCH * D_INNER) / 256, 256>>>(vals, xz, decay, hin, yf);

    // GEMM3: out = y @ W_out^T + b_out   [8192, 1024], K=2048
    gemm_mma<2><<<dim3(D_MODEL / BN, M_TOTAL / BM), 256, GSMEM_BYTES>>>(
        yf, woh, wol, b_out, out, nullptr, M_TOTAL, D_MODEL, D_INNER);
}

// round 11
// speedup vs baseline: 4.9827x; 1.5256x over previous
#include <cuda_runtime.h>
#include <cuda_fp16.h>
#include <cstdint>
#include <cstddef>

#define D_MODEL 1024
#define D_INNER 2048
#define BATCH   4
#define SEQ     2048
#define M_TOTAL (BATCH * SEQ)   // 8192
#define NCH     16              // scan chunks per sequence
#define LCH     (SEQ / NCH)     // 128

// ---------------- scratch (device globals; no allocation) ----------------
__device__ float g_xz   [(size_t)M_TOTAL * (2 * D_INNER)];  // 8192 x 4096
__device__ float g_xconv[(size_t)M_TOTAL * D_INNER];
__device__ float g_vals [(size_t)M_TOTAL * D_INNER];

__device__ __half g_xf  [(size_t)M_TOTAL * D_MODEL];
__device__ __half g_xcf [(size_t)M_TOTAL * D_INNER];
__device__ __half g_yf  [(size_t)M_TOTAL * D_INNER];
__device__ __half g_wi  [(size_t)(2*D_INNER) * D_MODEL];
__device__ __half g_wd  [(size_t)D_INNER * D_INNER];
__device__ __half g_wo  [(size_t)D_MODEL * D_INNER];
__device__ float g_carry[BATCH * NCH * D_INNER];
__device__ float g_hin  [BATCH * NCH * D_INNER];

// ---------------- helpers ----------------
__device__ __forceinline__ uint32_t smem_u32(const void* p) {
    uint32_t a;
    asm("{ .reg .u64 t; cvta.to.shared.u64 t, %1; cvt.u32.u64 %0, t; }" : "=r"(a) : "l"(p));
    return a;
}
__device__ __forceinline__ void cp16(uint32_t saddr, const void* g) {
    asm volatile("cp.async.cg.shared.global [%0], [%1], 16;" :: "r"(saddr), "l"(g) : "memory");
}
__device__ __forceinline__ float silu_f(float x) { return x / (1.0f + expf(-x)); }
__device__ __forceinline__ float softplus_f(float x) { return (x > 20.0f) ? x : log1pf(expf(x)); }

// ---------------- mma.sync fp16 GEMM (single-precision fp16 operands) ----------------
// C[M,N] = A[M,K] @ B[N,K]^T
// CTA tile 128x256, 8 warps as 2x4 -> 64x64 warp tile.
// MODE 0/2: C = acc + bias      MODE 1: C = softplus(acc+bias) * aux
#define BM 128
#define BN 256
#define BK 64          // fp16 K per stage
#define AST 72         // smem row stride (halves): 144B, conflict-free ldmatrix
#define TILE_A_H (BM * AST)            // 9216 halves (18KB)
#define TILE_B_H (BN * AST)            // 18432 halves (36KB)
#define STAGE_H (TILE_A_H + TILE_B_H)  // A | B  (54KB)
#define OFF_A  0
#define OFF_B  TILE_A_H
#define GSMEM_BYTES (2 * STAGE_H * 2)  // 110592

template <int MODE>
__global__ __launch_bounds__(256)
void gemm_mma(const __half* __restrict__ A, const __half* __restrict__ B,
              const float* __restrict__ bias, float* __restrict__ C,
              const float* __restrict__ aux, int M, int N, int K)
{
    extern __shared__ __half smem[];

    const int tid  = threadIdx.x;
    const int wid  = tid >> 5;
    const int lane = tid & 31;
    const int bm = blockIdx.y * BM;
    const int bn = blockIdx.x * BN;
    const int wm = (wid >> 2) * 64;   // warp m offset (0 or 64)
    const int wn = (wid & 3) * 64;    // warp n offset (0,64,128,192)

    const __half* Aa = A + (size_t)bm * K;
    const __half* Bb = B + (size_t)bn * K;

    const int nst = K / BK;

    float acc[4][8][4];
    #pragma unroll
    for (int i = 0; i < 4; i++)
        #pragma unroll
        for (int j = 0; j < 8; j++)
            #pragma unroll
            for (int r = 0; r < 4; r++) acc[i][j][r] = 0.0f;

    // loader: A 128 rows, B 256 rows; 64 halves (8 x 16B segs) per row
    auto load_stage = [&](int s, int buf) {
        const int kb = s * BK;
        __half* st = smem + buf * STAGE_H;
        #pragma unroll
        for (int it = 0; it < 4; it++) {           // A: 1024 segs
            int seg = tid + it * 256;
            int r = seg >> 3;
            int q = (seg & 7) * 8;
            cp16(smem_u32(st + OFF_A + r * AST + q), Aa + (size_t)r * K + kb + q);
        }
        #pragma unroll
        for (int it = 0; it < 8; it++) {           // B: 2048 segs
            int seg = tid + it * 256;
            int r = seg >> 3;
            int q = (seg & 7) * 8;
            cp16(smem_u32(st + OFF_B + r * AST + q), Bb + (size_t)r * K + kb + q);
        }
        asm volatile("cp.async.commit_group;" ::: "memory");
    };

    load_stage(0, 0);
    asm volatile("cp.async.wait_group 0;" ::: "memory");
    __syncthreads();

    for (int s = 0; s < nst; s++) {
        const int buf = s & 1;
        if (s + 1 < nst) load_stage(s + 1, buf ^ 1);

        const __half* st = smem + buf * STAGE_H;
        #pragma unroll
        for (int kk = 0; kk < 4; kk++) {
            uint32_t a[4][4], b[8][2];
            #pragma unroll
            for (int mf = 0; mf < 4; mf++) {
                int so = (wm + mf * 16 + (lane & 15)) * AST + kk * 16 + (lane >> 4) * 8;
                uint32_t ad = smem_u32(st + OFF_A + so);
                asm volatile("ldmatrix.sync.aligned.m8n8.x4.shared.b16 {%0,%1,%2,%3}, [%4];"
                             : "=r"(a[mf][0]), "=r"(a[mf][1]), "=r"(a[mf][2]), "=r"(a[mf][3]) : "r"(ad));
            }
            // B: one ldmatrix.x4 covers 2 nf tiles -> 4 loads for 8 nf
            #pragma unroll
            for (int nfp = 0; nfp < 4; nfp++) {
                int nfq   = nfp * 2 + ((lane >> 4) & 1);
                int khalf = (lane >> 3) & 1;
                int so = (wn + nfq * 8 + (lane & 7)) * AST + kk * 16 + khalf * 8;
                uint32_t bd = smem_u32(st + OFF_B + so);
                asm volatile("ldmatrix.sync.aligned.m8n8.x4.shared.b16 {%0,%1,%2,%3}, [%4];"
                             : "=r"(b[nfp*2][0]), "=r"(b[nfp*2][1]),
                               "=r"(b[nfp*2+1][0]), "=r"(b[nfp*2+1][1]) : "r"(bd));
            }
            #pragma unroll
            for (int mf = 0; mf < 4; mf++)
                #pragma unroll
                for (int nf = 0; nf < 8; nf++) {
                    asm volatile(
                        "mma.sync.aligned.m16n8k16.row.col.f32.f16.f16.f32 "
                        "{%0,%1,%2,%3}, {%4,%5,%6,%7}, {%8,%9}, {%0,%1,%2,%3};"
                        : "+f"(acc[mf][nf][0]), "+f"(acc[mf][nf][1]),
                          "+f"(acc[mf][nf][2]), "+f"(acc[mf][nf][3])
                        : "r"(a[mf][0]), "r"(a[mf][1]), "r"(a[mf][2]), "r"(a[mf][3]),
                          "r"(b[nf][0]), "r"(b[nf][1]));
                }
        }

        if (s + 1 < nst) { asm volatile("cp.async.wait_group 0;" ::: "memory"); }
        __syncthreads();
    }

    // epilogue: acc regs -> global (float2 stores)
    const int tr = lane >> 2;          // 0..7
    const int tc = (lane & 3) * 2;     // 0,2,4,6
    #pragma unroll
    for (int mf = 0; mf < 4; mf++) {
        #pragma unroll
        for (int h = 0; h < 2; h++) {
            int gm = bm + wm + mf * 16 + tr + h * 8;
            size_t rb = (size_t)gm * N;
            #pragma unroll
            for (int nf = 0; nf < 8; nf++) {
                int gn = bn + wn + nf * 8 + tc;
                float v0 = acc[mf][nf][h * 2 + 0] + bias[gn];
                float v1 = acc[mf][nf][h * 2 + 1] + bias[gn + 1];
                if (MODE == 1) {
                    float2 ax = *reinterpret_cast<const float2*>(aux + rb + gn);
                    v0 = softplus_f(v0) * ax.x;
                    v1 = softplus_f(v1) * ax.y;
                }
                float2 o; o.x = v0; o.y = v1;
                *reinterpret_cast<float2*>(C + rb + gn) = o;
            }
        }
    }
}

// ---------------- conversion: fp32 -> fp16 (x4 vectorized) ----------------
__global__ void cvta_kernel(const float* __restrict__ s, __half* __restrict__ h, int n4)
{
    int i = blockIdx.x * 256 + threadIdx.x;
    if (i >= n4) return;
    float4 v = reinterpret_cast<const float4*>(s)[i];
    reinterpret_cast<__half2*>(h)[2*i]   = __halves2half2(__float2half(v.x), __float2half(v.y));
    reinterpret_cast<__half2*>(h)[2*i+1] = __halves2half2(__float2half(v.z), __float2half(v.w));
}

// ---------------- depthwise causal conv (width 4) + SiLU ----------------
__global__ void conv_silu_kernel(const float* __restrict__ xz,
                                 const float* __restrict__ Wc,
                                 const float* __restrict__ bc,
                                 float* __restrict__ xconv,
                                 __half* __restrict__ xcf)
{
    int idx = blockIdx.x * blockDim.x + threadIdx.x;
    if (idx >= M_TOTAL * D_INNER) return;
    int c = idx & (D_INNER - 1);
    int m = idx >> 11;
    int t = m & (SEQ - 1);

    float4 w = *reinterpret_cast<const float4*>(Wc + c * 4);
    float acc = bc[c];
    const size_t st = 2 * D_INNER;
    size_t base = (size_t)m * st + c;

    if (t >= 3) {
        acc += w.x * xz[base - 3 * st] + w.y * xz[base - 2 * st]
             + w.z * xz[base - st]     + w.w * xz[base];
    } else {
        acc += w.w * xz[base];
        if (t >= 1) acc += w.z * xz[base - st];
        if (t >= 2) acc += w.y * xz[base - 2 * st];
    }
    float v = silu_f(acc);
    xconv[idx] = v;
    xcf[idx] = __float2half(v);
}

// ---------------- chunked scan ----------------
__global__ void scanA_kernel(const float* __restrict__ vals, const float* __restrict__ decay,
                             float* __restrict__ carry)
{
    int idx = blockIdx.x * 256 + threadIdx.x;      // 131072
    if (idx >= BATCH * NCH * D_INNER) return;
    int c = idx & (D_INNER - 1);
    int ch = (idx >> 11) & (NCH - 1);
    int b = idx >> 15;
    float d = decay[c];
    float h = 0.0f;
    size_t base = ((size_t)(b * SEQ + ch * LCH)) * D_INNER + c;
    #pragma unroll 8
    for (int i = 0; i < LCH; i++)
        h = fmaf(d, h, vals[base + (size_t)i * D_INNER]);
    carry[(b * NCH + ch) * D_INNER + c] = h;
}

__global__ void scanB_kernel(const float* __restrict__ carry, const float* __restrict__ decay,
                             float* __restrict__ hin)
{
    int idx = blockIdx.x * 256 + threadIdx.x;      // 8192
    if (idx >= BATCH * D_INNER) return;
    int c = idx & (D_INNER - 1);
    int b = idx >> 11;
    float d = decay[c];
    float dL = d;
    #pragma unroll
    for (int j = 0; j < 7; j++) dL = dL * dL;      // d^128
    float H = 0.0f;
    for (int ch = 0; ch < NCH; ch++) {
        int o = (b * NCH + ch) * D_INNER + c;
        hin[o] = H;
        H = fmaf(dL, H, carry[o]);
    }
}

__global__ void scanC_kernel(const float* __restrict__ vals, const float* __restrict__ xz,
                             const float* __restrict__ decay, const float* __restrict__ hin,
                             __half* __restrict__ yf)
{
    int idx = blockIdx.x * 256 + threadIdx.x;
    if (idx >= BATCH * NCH * D_INNER) return;
    int c = idx & (D_INNER - 1);
    int ch = (idx >> 11) & (NCH - 1);
    int b = idx >> 15;
    float d = decay[c];
    float h = hin[(b * NCH + ch) * D_INNER + c];
    size_t m0 = (size_t)(b * SEQ + ch * LCH);
    size_t vbase = m0 * D_INNER + c;
    size_t zbase = m0 * (2 * D_INNER) + D_INNER + c;
    #pragma unroll 8
    for (int i = 0; i < LCH; i++) {
        h = fmaf(d, h, vals[vbase + (size_t)i * D_INNER]);
        float z = xz[zbase + (size_t)i * (2 * D_INNER)];
        yf[vbase + (size_t)i * D_INNER] = __float2half(h * silu_f(z));
    }
}

// ---------------- launcher ----------------
extern "C" void kernel_launch(void* const* d_in, const int* in_sizes, int n_in,
                              void* d_out, int out_size)
{
    const float* x      = (const float*)d_in[0];
    const float* W_in   = (const float*)d_in[1];
    const float* b_in   = (const float*)d_in[2];
    const float* W_conv = (const float*)d_in[3];
    const float* b_conv = (const float*)d_in[4];
    const float* W_dt   = (const float*)d_in[5];
    const float* b_dt   = (const float*)d_in[6];
    const float* W_out  = (const float*)d_in[7];
    const float* b_out  = (const float*)d_in[8];
    const float* decay  = (const float*)d_in[9];
    float* out = (float*)d_out;

    float *xz, *xconv, *vals, *carry, *hin;
    __half *xf, *xcf, *yf, *wi, *wd, *wo;
    cudaGetSymbolAddress((void**)&xz, g_xz);
    cudaGetSymbolAddress((void**)&xconv, g_xconv);
    cudaGetSymbolAddress((void**)&vals, g_vals);
    cudaGetSymbolAddress((void**)&carry, g_carry);
    cudaGetSymbolAddress((void**)&hin, g_hin);
    cudaGetSymbolAddress((void**)&xf, g_xf);
    cudaGetSymbolAddress((void**)&xcf, g_xcf);
    cudaGetSymbolAddress((void**)&yf, g_yf);
    cudaGetSymbolAddress((void**)&wi, g_wi);
    cudaGetSymbolAddress((void**)&wd, g_wd);
    cudaGetSymbolAddress((void**)&wo, g_wo);

    cudaFuncSetAttribute(gemm_mma<0>, cudaFuncAttributeMaxDynamicSharedMemorySize, GSMEM_BYTES);
    cudaFuncSetAttribute(gemm_mma<1>, cudaFuncAttributeMaxDynamicSharedMemorySize, GSMEM_BYTES);
    cudaFuncSetAttribute(gemm_mma<2>, cudaFuncAttributeMaxDynamicSharedMemorySize, GSMEM_BYTES);

    // conversions (all sizes divisible by 4)
    cvta_kernel<<<(M_TOTAL * D_MODEL / 4 + 255) / 256, 256>>>(x, xf, M_TOTAL * D_MODEL / 4);
    cvta_kernel<<<(2 * D_INNER * D_MODEL / 4 + 255) / 256, 256>>>(W_in, wi, 2 * D_INNER * D_MODEL / 4);
    cvta_kernel<<<(D_INNER * D_INNER / 4 + 255) / 256, 256>>>(W_dt, wd, D_INNER * D_INNER / 4);
    cvta_kernel<<<(D_MODEL * D_INNER / 4 + 255) / 256, 256>>>(W_out, wo, D_MODEL * D_INNER / 4);

    // GEMM1: xz = x @ W_in^T + b_in   [8192, 4096], K=1024
    gemm_mma<0><<<dim3((2 * D_INNER) / BN, M_TOTAL / BM), 256, GSMEM_BYTES>>>(
        xf, wi, b_in, xz, nullptr, M_TOTAL, 2 * D_INNER, D_MODEL);

    // conv + silu
    conv_silu_kernel<<<(M_TOTAL * D_INNER) / 256, 256>>>(xz, W_conv, b_conv, xconv, xcf);

    // GEMM2: vals = softplus(xconv @ W_dt^T + b_dt) * xconv   [8192, 2048], K=2048
    gemm_mma<1><<<dim3(D_INNER / BN, M_TOTAL / BM), 256, GSMEM_BYTES>>>(
        xcf, wd, b_dt, vals, xconv, M_TOTAL, D_INNER, D_INNER);

    // chunked scan + gate -> y (fp16)
    scanA_kernel<<<(BATCH * NCH * D_INNER) / 256, 256>>>(vals, decay, carry);
    scanB_kernel<<<(BATCH * D_INNER) / 256, 256>>>(carry, decay, hin);
    scanC_kernel<<<(BATCH * NCH * D_INNER) / 256, 256>>>(vals, xz, decay, hin, yf);

    // GEMM3: out = y @ W_out^T + b_out   [8192, 1024], K=2048
    gemm_mma<2><<<dim3(D_MODEL / BN, M_TOTAL / BM), 256, GSMEM_BYTES>>>(
        yf, wo, b_out, out, nullptr, M_TOTAL, D_MODEL, D_INNER);
}

// round 12
// speedup vs baseline: 5.0772x; 1.0190x over previous
#include <cuda_runtime.h>
#include <cuda_fp16.h>
#include <cstdint>
#include <cstddef>

#define D_MODEL 1024
#define D_INNER 2048
#define BATCH   4
#define SEQ     2048
#define M_TOTAL (BATCH * SEQ)   // 8192
#define NCH     16              // scan chunks per sequence
#define LCH     (SEQ / NCH)     // 128

// ---------------- scratch (device globals; no allocation) ----------------
__device__ __half g_xz  [(size_t)M_TOTAL * (2 * D_INNER)];  // fp16 now
__device__ __half g_vals[(size_t)M_TOTAL * D_INNER];        // fp16 now

__device__ __half g_xf  [(size_t)M_TOTAL * D_MODEL];
__device__ __half g_xcf [(size_t)M_TOTAL * D_INNER];
__device__ __half g_yf  [(size_t)M_TOTAL * D_INNER];
__device__ __half g_wi  [(size_t)(2*D_INNER) * D_MODEL];
__device__ __half g_wd  [(size_t)D_INNER * D_INNER];
__device__ __half g_wo  [(size_t)D_MODEL * D_INNER];
__device__ float g_carry[BATCH * NCH * D_INNER];
__device__ float g_hin  [BATCH * NCH * D_INNER];

// ---------------- helpers ----------------
__device__ __forceinline__ uint32_t smem_u32(const void* p) {
    uint32_t a;
    asm("{ .reg .u64 t; cvta.to.shared.u64 t, %1; cvt.u32.u64 %0, t; }" : "=r"(a) : "l"(p));
    return a;
}
__device__ __forceinline__ void cp16(uint32_t saddr, const void* g) {
    asm volatile("cp.async.cg.shared.global [%0], [%1], 16;" :: "r"(saddr), "l"(g) : "memory");
}
__device__ __forceinline__ float silu_f(float x) { return x / (1.0f + expf(-x)); }
__device__ __forceinline__ float softplus_f(float x) { return (x > 20.0f) ? x : log1pf(expf(x)); }

// ---------------- mma.sync fp16 GEMM ----------------
// C[M,N] = A[M,K] @ B[N,K]^T
// CTA tile 128x256, 8 warps as 2x4 -> 64x64 warp tile. 3-stage cp.async pipeline.
// MODE 0: Chalf = acc + bias
// MODE 1: Chalf = softplus(acc+bias) * auxhalf
// MODE 2: Cfloat = acc + bias
#define BM 128
#define BN 256
#define BK 64          // fp16 K per stage
#define AST 72         // smem row stride (halves): 144B, conflict-free ldmatrix
#define TILE_A_H (BM * AST)            // 9216 halves (18KB)
#define TILE_B_H (BN * AST)            // 18432 halves (36KB)
#define STAGE_H (TILE_A_H + TILE_B_H)  // A | B  (54KB)
#define OFF_A  0
#define OFF_B  TILE_A_H
#define NSTAGE 3
#define GSMEM_BYTES (NSTAGE * STAGE_H * 2)  // 165888

template <int MODE>
__global__ __launch_bounds__(256)
void gemm_mma(const __half* __restrict__ A, const __half* __restrict__ B,
              const float* __restrict__ bias, void* __restrict__ Cv,
              const __half* __restrict__ aux, int M, int N, int K)
{
    extern __shared__ __half smem[];

    const int tid  = threadIdx.x;
    const int wid  = tid >> 5;
    const int lane = tid & 31;
    const int bm = blockIdx.y * BM;
    const int bn = blockIdx.x * BN;
    const int wm = (wid >> 2) * 64;
    const int wn = (wid & 3) * 64;

    const __half* Aa = A + (size_t)bm * K;
    const __half* Bb = B + (size_t)bn * K;

    const int nst = K / BK;

    float acc[4][8][4];
    #pragma unroll
    for (int i = 0; i < 4; i++)
        #pragma unroll
        for (int j = 0; j < 8; j++)
            #pragma unroll
            for (int r = 0; r < 4; r++) acc[i][j][r] = 0.0f;

    auto load_stage = [&](int s, int buf) {
        const int kb = s * BK;
        __half* st = smem + buf * STAGE_H;
        #pragma unroll
        for (int it = 0; it < 4; it++) {           // A: 1024 segs
            int seg = tid + it * 256;
            int r = seg >> 3;
            int q = (seg & 7) * 8;
            cp16(smem_u32(st + OFF_A + r * AST + q), Aa + (size_t)r * K + kb + q);
        }
        #pragma unroll
        for (int it = 0; it < 8; it++) {           // B: 2048 segs
            int seg = tid + it * 256;
            int r = seg >> 3;
            int q = (seg & 7) * 8;
            cp16(smem_u32(st + OFF_B + r * AST + q), Bb + (size_t)r * K + kb + q);
        }
        asm volatile("cp.async.commit_group;" ::: "memory");
    };

    // prologue: two stages in flight
    load_stage(0, 0);
    load_stage(1, 1);
    asm volatile("cp.async.wait_group 1;" ::: "memory");  // stage 0 ready
    __syncthreads();

    int buf = 0;
    for (int s = 0; s < nst; s++) {
        if (s + 2 < nst) load_stage(s + 2, (s + 2) % NSTAGE);

        const __half* st = smem + buf * STAGE_H;
        #pragma unroll
        for (int kk = 0; kk < 4; kk++) {
            uint32_t a[4][4], b[8][2];
            #pragma unroll
            for (int mf = 0; mf < 4; mf++) {
                int so = (wm + mf * 16 + (lane & 15)) * AST + kk * 16 + (lane >> 4) * 8;
                uint32_t ad = smem_u32(st + OFF_A + so);
                asm volatile("ldmatrix.sync.aligned.m8n8.x4.shared.b16 {%0,%1,%2,%3}, [%4];"
                             : "=r"(a[mf][0]), "=r"(a[mf][1]), "=r"(a[mf][2]), "=r"(a[mf][3]) : "r"(ad));
            }
            #pragma unroll
            for (int nfp = 0; nfp < 4; nfp++) {
                int nfq   = nfp * 2 + ((lane >> 4) & 1);
                int khalf = (lane >> 3) & 1;
                int so = (wn + nfq * 8 + (lane & 7)) * AST + kk * 16 + khalf * 8;
                uint32_t bd = smem_u32(st + OFF_B + so);
                asm volatile("ldmatrix.sync.aligned.m8n8.x4.shared.b16 {%0,%1,%2,%3}, [%4];"
                             : "=r"(b[nfp*2][0]), "=r"(b[nfp*2][1]),
                               "=r"(b[nfp*2+1][0]), "=r"(b[nfp*2+1][1]) : "r"(bd));
            }
            #pragma unroll
            for (int mf = 0; mf < 4; mf++)
                #pragma unroll
                for (int nf = 0; nf < 8; nf++) {
                    asm volatile(
                        "mma.sync.aligned.m16n8k16.row.col.f32.f16.f16.f32 "
                        "{%0,%1,%2,%3}, {%4,%5,%6,%7}, {%8,%9}, {%0,%1,%2,%3};"
                        : "+f"(acc[mf][nf][0]), "+f"(acc[mf][nf][1]),
                          "+f"(acc[mf][nf][2]), "+f"(acc[mf][nf][3])
                        : "r"(a[mf][0]), "r"(a[mf][1]), "r"(a[mf][2]), "r"(a[mf][3]),
                          "r"(b[nf][0]), "r"(b[nf][1]));
                }
        }

        if (s + 2 < nst)      { asm volatile("cp.async.wait_group 1;" ::: "memory"); }
        else if (s + 1 < nst) { asm volatile("cp.async.wait_group 0;" ::: "memory"); }
        __syncthreads();
        buf = (buf + 1) % NSTAGE;
    }

    // epilogue
    const int tr = lane >> 2;
    const int tc = (lane & 3) * 2;
    #pragma unroll
    for (int mf = 0; mf < 4; mf++) {
        #pragma unroll
        for (int h = 0; h < 2; h++) {
            int gm = bm + wm + mf * 16 + tr + h * 8;
            size_t rb = (size_t)gm * N;
            #pragma unroll
            for (int nf = 0; nf < 8; nf++) {
                int gn = bn + wn + nf * 8 + tc;
                float v0 = acc[mf][nf][h * 2 + 0] + bias[gn];
                float v1 = acc[mf][nf][h * 2 + 1] + bias[gn + 1];
                if (MODE == 1) {
                    __half2 ax = *reinterpret_cast<const __half2*>(aux + rb + gn);
                    v0 = softplus_f(v0) * __half2float(__low2half(ax));
                    v1 = softplus_f(v1) * __half2float(__high2half(ax));
                }
                if (MODE == 2) {
                    float2 o; o.x = v0; o.y = v1;
                    *reinterpret_cast<float2*>((float*)Cv + rb + gn) = o;
                } else {
                    *reinterpret_cast<__half2*>((__half*)Cv + rb + gn) =
                        __halves2half2(__float2half(v0), __float2half(v1));
                }
            }
        }
    }
}

// ---------------- conversion: fp32 -> fp16 (x4 vectorized) ----------------
__global__ void cvta_kernel(const float* __restrict__ s, __half* __restrict__ h, int n4)
{
    int i = blockIdx.x * 256 + threadIdx.x;
    if (i >= n4) return;
    float4 v = reinterpret_cast<const float4*>(s)[i];
    reinterpret_cast<__half2*>(h)[2*i]   = __halves2half2(__float2half(v.x), __float2half(v.y));
    reinterpret_cast<__half2*>(h)[2*i+1] = __halves2half2(__float2half(v.z), __float2half(v.w));
}

// ---------------- depthwise causal conv (width 4) + SiLU ----------------
__global__ void conv_silu_kernel(const __half* __restrict__ xz,
                                 const float* __restrict__ Wc,
                                 const float* __restrict__ bc,
                                 __half* __restrict__ xcf)
{
    int idx = blockIdx.x * blockDim.x + threadIdx.x;
    if (idx >= M_TOTAL * D_INNER) return;
    int c = idx & (D_INNER - 1);
    int m = idx >> 11;
    int t = m & (SEQ - 1);

    float4 w = *reinterpret_cast<const float4*>(Wc + c * 4);
    float acc = bc[c];
    const size_t st = 2 * D_INNER;
    size_t base = (size_t)m * st + c;

    if (t >= 3) {
        acc += w.x * __half2float(xz[base - 3 * st]) + w.y * __half2float(xz[base - 2 * st])
             + w.z * __half2float(xz[base - st])     + w.w * __half2float(xz[base]);
    } else {
        acc += w.w * __half2float(xz[base]);
        if (t >= 1) acc += w.z * __half2float(xz[base - st]);
        if (t >= 2) acc += w.y * __half2float(xz[base - 2 * st]);
    }
    xcf[idx] = __float2half(silu_f(acc));
}

// ---------------- chunked scan ----------------
__global__ void scanA_kernel(const __half* __restrict__ vals, const float* __restrict__ decay,
                             float* __restrict__ carry)
{
    int idx = blockIdx.x * 256 + threadIdx.x;      // 131072
    if (idx >= BATCH * NCH * D_INNER) return;
    int c = idx & (D_INNER - 1);
    int ch = (idx >> 11) & (NCH - 1);
    int b = idx >> 15;
    float d = decay[c];
    float h = 0.0f;
    size_t base = ((size_t)(b * SEQ + ch * LCH)) * D_INNER + c;
    #pragma unroll 8
    for (int i = 0; i < LCH; i++)
        h = fmaf(d, h, __half2float(vals[base + (size_t)i * D_INNER]));
    carry[(b * NCH + ch) * D_INNER + c] = h;
}

__global__ void scanB_kernel(const float* __restrict__ carry, const float* __restrict__ decay,
                             float* __restrict__ hin)
{
    int idx = blockIdx.x * 256 + threadIdx.x;      // 8192
    if (idx >= BATCH * D_INNER) return;
    int c = idx & (D_INNER - 1);
    int b = idx >> 11;
    float d = decay[c];
    float dL = d;
    #pragma unroll
    for (int j = 0; j < 7; j++) dL = dL * dL;      // d^128
    float H = 0.0f;
    for (int ch = 0; ch < NCH; ch++) {
        int o = (b * NCH + ch) * D_INNER + c;
        hin[o] = H;
        H = fmaf(dL, H, carry[o]);
    }
}

__global__ void scanC_kernel(const __half* __restrict__ vals, const __half* __restrict__ xz,
                             const float* __restrict__ decay, const float* __restrict__ hin,
                             __half* __restrict__ yf)
{
    int idx = blockIdx.x * 256 + threadIdx.x;
    if (idx >= BATCH * NCH * D_INNER) return;
    int c = idx & (D_INNER - 1);
    int ch = (idx >> 11) & (NCH - 1);
    int b = idx >> 15;
    float d = decay[c];
    float h = hin[(b * NCH + ch) * D_INNER + c];
    size_t m0 = (size_t)(b * SEQ + ch * LCH);
    size_t vbase = m0 * D_INNER + c;
    size_t zbase = m0 * (2 * D_INNER) + D_INNER + c;
    #pragma unroll 8
    for (int i = 0; i < LCH; i++) {
        h = fmaf(d, h, __half2float(vals[vbase + (size_t)i * D_INNER]));
        float z = __half2float(xz[zbase + (size_t)i * (2 * D_INNER)]);
        yf[vbase + (size_t)i * D_INNER] = __float2half(h * silu_f(z));
    }
}

// ---------------- launcher ----------------
extern "C" void kernel_launch(void* const* d_in, const int* in_sizes, int n_in,
                              void* d_out, int out_size)
{
    const float* x      = (const float*)d_in[0];
    const float* W_in   = (const float*)d_in[1];
    const float* b_in   = (const float*)d_in[2];
    const float* W_conv = (const float*)d_in[3];
    const float* b_conv = (const float*)d_in[4];
    const float* W_dt   = (const float*)d_in[5];
    const float* b_dt   = (const float*)d_in[6];
    const float* W_out  = (const float*)d_in[7];
    const float* b_out  = (const float*)d_in[8];
    const float* decay  = (const float*)d_in[9];
    float* out = (float*)d_out;

    float *carry, *hin;
    __half *xz, *vals, *xf, *xcf, *yf, *wi, *wd, *wo;
    cudaGetSymbolAddress((void**)&xz, g_xz);
    cudaGetSymbolAddress((void**)&vals, g_vals);
    cudaGetSymbolAddress((void**)&carry, g_carry);
    cudaGetSymbolAddress((void**)&hin, g_hin);
    cudaGetSymbolAddress((void**)&xf, g_xf);
    cudaGetSymbolAddress((void**)&xcf, g_xcf);
    cudaGetSymbolAddress((void**)&yf, g_yf);
    cudaGetSymbolAddress((void**)&wi, g_wi);
    cudaGetSymbolAddress((void**)&wd, g_wd);
    cudaGetSymbolAddress((void**)&wo, g_wo);

    cudaFuncSetAttribute(gemm_mma<0>, cudaFuncAttributeMaxDynamicSharedMemorySize, GSMEM_BYTES);
    cudaFuncSetAttribute(gemm_mma<1>, cudaFuncAttributeMaxDynamicSharedMemorySize, GSMEM_BYTES);
    cudaFuncSetAttribute(gemm_mma<2>, cudaFuncAttributeMaxDynamicSharedMemorySize, GSMEM_BYTES);

    // conversions (all sizes divisible by 4)
    cvta_kernel<<<(M_TOTAL * D_MODEL / 4 + 255) / 256, 256>>>(x, xf, M_TOTAL * D_MODEL / 4);
    cvta_kernel<<<(2 * D_INNER * D_MODEL / 4 + 255) / 256, 256>>>(W_in, wi, 2 * D_INNER * D_MODEL / 4);
    cvta_kernel<<<(D_INNER * D_INNER / 4 + 255) / 256, 256>>>(W_dt, wd, D_INNER * D_INNER / 4);
    cvta_kernel<<<(D_MODEL * D_INNER / 4 + 255) / 256, 256>>>(W_out, wo, D_MODEL * D_INNER / 4);

    // GEMM1: xz(fp16) = x @ W_in^T + b_in   [8192, 4096], K=1024
    gemm_mma<0><<<dim3((2 * D_INNER) / BN, M_TOTAL / BM), 256, GSMEM_BYTES>>>(
        xf, wi, b_in, xz, nullptr, M_TOTAL, 2 * D_INNER, D_MODEL);

    // conv + silu -> xcf (fp16)
    conv_silu_kernel<<<(M_TOTAL * D_INNER) / 256, 256>>>(xz, W_conv, b_conv, xcf);

    // GEMM2: vals(fp16) = softplus(xcf @ W_dt^T + b_dt) * xcf   [8192, 2048], K=2048
    gemm_mma<1><<<dim3(D_INNER / BN, M_TOTAL / BM), 256, GSMEM_BYTES>>>(
        xcf, wd, b_dt, vals, xcf, M_TOTAL, D_INNER, D_INNER);

    // chunked scan + gate -> y (fp16)
    scanA_kernel<<<(BATCH * NCH * D_INNER) / 256, 256>>>(vals, decay, carry);
    scanB_kernel<<<(BATCH * D_INNER) / 256, 256>>>(carry, decay, hin);
    scanC_kernel<<<(BATCH * NCH * D_INNER) / 256, 256>>>(vals, xz, decay, hin, yf);

    // GEMM3: out(fp32) = y @ W_out^T + b_out   [8192, 1024], K=2048
    gemm_mma<2><<<dim3(D_MODEL / BN, M_TOTAL / BM), 256, GSMEM_BYTES>>>(
        yf, wo, b_out, out, nullptr, M_TOTAL, D_MODEL, D_INNER);
}

// round 13
// speedup vs baseline: 5.2129x; 1.0267x over previous
#include <cuda_runtime.h>
#include <cuda_fp16.h>
#include <cstdint>
#include <cstddef>

#define D_MODEL 1024
#define D_INNER 2048
#define BATCH   4
#define SEQ     2048
#define M_TOTAL (BATCH * SEQ)   // 8192
#define NCH     16              // scan chunks per sequence
#define LCH     (SEQ / NCH)     // 128

// ---------------- scratch (device globals; no allocation) ----------------
__device__ __half g_xz  [(size_t)M_TOTAL * (2 * D_INNER)];
__device__ __half g_vals[(size_t)M_TOTAL * D_INNER];

__device__ __half g_xf  [(size_t)M_TOTAL * D_MODEL];
__device__ __half g_xcf [(size_t)M_TOTAL * D_INNER];
__device__ __half g_yf  [(size_t)M_TOTAL * D_INNER];
__device__ __half g_wi  [(size_t)(2*D_INNER) * D_MODEL];
__device__ __half g_wd  [(size_t)D_INNER * D_INNER];
__device__ __half g_wo  [(size_t)D_MODEL * D_INNER];
__device__ float g_carry[BATCH * NCH * D_INNER];
__device__ float g_hin  [BATCH * NCH * D_INNER];

// ---------------- helpers ----------------
__device__ __forceinline__ uint32_t smem_u32(const void* p) {
    uint32_t a;
    asm("{ .reg .u64 t; cvta.to.shared.u64 t, %1; cvt.u32.u64 %0, t; }" : "=r"(a) : "l"(p));
    return a;
}
__device__ __forceinline__ void cp16(uint32_t saddr, const void* g) {
    asm volatile("cp.async.cg.shared.global [%0], [%1], 16;" :: "r"(saddr), "l"(g) : "memory");
}
__device__ __forceinline__ float silu_f(float x) { return x / (1.0f + expf(-x)); }
__device__ __forceinline__ float softplus_f(float x) { return (x > 20.0f) ? x : log1pf(expf(x)); }

// ---------------- mma.sync fp16 GEMM ----------------
// C[M,N] = A[M,K] @ B[N,K]^T
// CTA tile 128x256, 8 warps as 2x4 -> 64x64 warp tile. 3-stage cp.async pipeline.
// MODE 0: Chalf = acc + bias
// MODE 1: Chalf = softplus(acc+bias) * auxhalf; ALSO emits per-chunk scan carry
//         (CTA M-tile == one scan chunk of 128 steps)
// MODE 2: Cfloat = acc + bias
#define BM 128
#define BN 256
#define BK 64
#define AST 72         // smem row stride (halves): 144B, conflict-free ldmatrix
#define TILE_A_H (BM * AST)
#define TILE_B_H (BN * AST)
#define STAGE_H (TILE_A_H + TILE_B_H)  // 54KB
#define OFF_A  0
#define OFF_B  TILE_A_H
#define NSTAGE 3
#define GSMEM_BYTES (NSTAGE * STAGE_H * 2)  // 165888

template <int MODE>
__global__ __launch_bounds__(256)
void gemm_mma(const __half* __restrict__ A, const __half* __restrict__ B,
              const float* __restrict__ bias, void* __restrict__ Cv,
              const __half* __restrict__ aux,
              const float* __restrict__ decay, float* __restrict__ carry,
              int M, int N, int K)
{
    extern __shared__ __half smem[];

    const int tid  = threadIdx.x;
    const int wid  = tid >> 5;
    const int lane = tid & 31;
    const int bm = blockIdx.y * BM;
    const int bn = blockIdx.x * BN;
    const int wm = (wid >> 2) * 64;
    const int wn = (wid & 3) * 64;

    const __half* Aa = A + (size_t)bm * K;
    const __half* Bb = B + (size_t)bn * K;

    const int nst = K / BK;

    float acc[4][8][4];
    #pragma unroll
    for (int i = 0; i < 4; i++)
        #pragma unroll
        for (int j = 0; j < 8; j++)
            #pragma unroll
            for (int r = 0; r < 4; r++) acc[i][j][r] = 0.0f;

    auto load_stage = [&](int s, int buf) {
        const int kb = s * BK;
        __half* st = smem + buf * STAGE_H;
        #pragma unroll
        for (int it = 0; it < 4; it++) {
            int seg = tid + it * 256;
            int r = seg >> 3;
            int q = (seg & 7) * 8;
            cp16(smem_u32(st + OFF_A + r * AST + q), Aa + (size_t)r * K + kb + q);
        }
        #pragma unroll
        for (int it = 0; it < 8; it++) {
            int seg = tid + it * 256;
            int r = seg >> 3;
            int q = (seg & 7) * 8;
            cp16(smem_u32(st + OFF_B + r * AST + q), Bb + (size_t)r * K + kb + q);
        }
        asm volatile("cp.async.commit_group;" ::: "memory");
    };

    load_stage(0, 0);
    load_stage(1, 1);
    asm volatile("cp.async.wait_group 1;" ::: "memory");
    __syncthreads();

    int buf = 0;
    for (int s = 0; s < nst; s++) {
        if (s + 2 < nst) load_stage(s + 2, (s + 2) % NSTAGE);

        const __half* st = smem + buf * STAGE_H;
        #pragma unroll
        for (int kk = 0; kk < 4; kk++) {
            uint32_t a[4][4], b[8][2];
            #pragma unroll
            for (int mf = 0; mf < 4; mf++) {
                int so = (wm + mf * 16 + (lane & 15)) * AST + kk * 16 + (lane >> 4) * 8;
                uint32_t ad = smem_u32(st + OFF_A + so);
                asm volatile("ldmatrix.sync.aligned.m8n8.x4.shared.b16 {%0,%1,%2,%3}, [%4];"
                             : "=r"(a[mf][0]), "=r"(a[mf][1]), "=r"(a[mf][2]), "=r"(a[mf][3]) : "r"(ad));
            }
            #pragma unroll
            for (int nfp = 0; nfp < 4; nfp++) {
                int nfq   = nfp * 2 + ((lane >> 4) & 1);
                int khalf = (lane >> 3) & 1;
                int so = (wn + nfq * 8 + (lane & 7)) * AST + kk * 16 + khalf * 8;
                uint32_t bd = smem_u32(st + OFF_B + so);
                asm volatile("ldmatrix.sync.aligned.m8n8.x4.shared.b16 {%0,%1,%2,%3}, [%4];"
                             : "=r"(b[nfp*2][0]), "=r"(b[nfp*2][1]),
                               "=r"(b[nfp*2+1][0]), "=r"(b[nfp*2+1][1]) : "r"(bd));
            }
            #pragma unroll
            for (int mf = 0; mf < 4; mf++)
                #pragma unroll
                for (int nf = 0; nf < 8; nf++) {
                    asm volatile(
                        "mma.sync.aligned.m16n8k16.row.col.f32.f16.f16.f32 "
                        "{%0,%1,%2,%3}, {%4,%5,%6,%7}, {%8,%9}, {%0,%1,%2,%3};"
                        : "+f"(acc[mf][nf][0]), "+f"(acc[mf][nf][1]),
                          "+f"(acc[mf][nf][2]), "+f"(acc[mf][nf][3])
                        : "r"(a[mf][0]), "r"(a[mf][1]), "r"(a[mf][2]), "r"(a[mf][3]),
                          "r"(b[nf][0]), "r"(b[nf][1]));
                }
        }

        if (s + 2 < nst)      { asm volatile("cp.async.wait_group 1;" ::: "memory"); }
        else if (s + 1 < nst) { asm volatile("cp.async.wait_group 0;" ::: "memory"); }
        __syncthreads();
        buf = (buf + 1) % NSTAGE;
    }

    const int tr = lane >> 2;
    const int tc = (lane & 3) * 2;

    if (MODE == 1) {
        // softplus-gate epilogue + fused per-chunk scan carry.
        // carry_col = sum_{row=0..127} d^(127-row) * vals_row
        // d^(127-row) = d^(127-wm-tr) * (d^-16)^mf * (d^-8)^h
        float cw0[8], cw1[8];
        const float e0 = (float)(127 - wm - tr);
        #pragma unroll
        for (int nf = 0; nf < 8; nf++) {
            int gn = bn + wn + nf * 8 + tc;
            float d0 = decay[gn], d1 = decay[gn + 1];
            float b0 = bias[gn],  b1 = bias[gn + 1];
            float pb0 = __powf(d0, e0), pb1 = __powf(d1, e0);
            float iv0 = __frcp_rn(d0), iv1 = __frcp_rn(d1);
            float i80 = iv0 * iv0; i80 *= i80; i80 *= i80;   // d^-8
            float i81 = iv1 * iv1; i81 *= i81; i81 *= i81;
            float i160 = i80 * i80, i161 = i81 * i81;        // d^-16
            float wmf0 = pb0, wmf1 = pb1;
            float c0 = 0.0f, c1 = 0.0f;
            #pragma unroll
            for (int mf = 0; mf < 4; mf++) {
                #pragma unroll
                for (int h = 0; h < 2; h++) {
                    int gm = bm + wm + mf * 16 + tr + h * 8;
                    size_t rb = (size_t)gm * N;
                    float v0 = acc[mf][nf][h * 2 + 0] + b0;
                    float v1 = acc[mf][nf][h * 2 + 1] + b1;
                    __half2 ax = *reinterpret_cast<const __half2*>(aux + rb + gn);
                    v0 = softplus_f(v0) * __half2float(__low2half(ax));
                    v1 = softplus_f(v1) * __half2float(__high2half(ax));
                    *reinterpret_cast<__half2*>((__half*)Cv + rb + gn) =
                        __halves2half2(__float2half(v0), __float2half(v1));
                    float w0 = h ? wmf0 * i80 : wmf0;
                    float w1 = h ? wmf1 * i81 : wmf1;
                    c0 = fmaf(w0, v0, c0);
                    c1 = fmaf(w1, v1, c1);
                }
                wmf0 *= i160; wmf1 *= i161;
            }
            cw0[nf] = c0; cw1[nf] = c1;
        }
        // reduce over the 8 tr-lanes (stride-4 xor shuffles preserve tc group)
        #pragma unroll
        for (int nf = 0; nf < 8; nf++) {
            #pragma unroll
            for (int off = 4; off <= 16; off <<= 1) {
                cw0[nf] += __shfl_xor_sync(0xffffffff, cw0[nf], off);
                cw1[nf] += __shfl_xor_sync(0xffffffff, cw1[nf], off);
            }
        }
        float* csm = reinterpret_cast<float*>(smem);   // [2][BN]
        if (lane < 4) {
            #pragma unroll
            for (int nf = 0; nf < 8; nf++) {
                int col = wn + nf * 8 + lane * 2;
                csm[(wid >> 2) * BN + col]     = cw0[nf];
                csm[(wid >> 2) * BN + col + 1] = cw1[nf];
            }
        }
        __syncthreads();
        {
            int j = tid;  // 0..255 == BN
            float cval = csm[j] + csm[BN + j];
            carry[((size_t)(bm >> 7)) * N + bn + j] = cval;
        }
    } else {
        #pragma unroll
        for (int mf = 0; mf < 4; mf++) {
            #pragma unroll
            for (int h = 0; h < 2; h++) {
                int gm = bm + wm + mf * 16 + tr + h * 8;
                size_t rb = (size_t)gm * N;
                #pragma unroll
                for (int nf = 0; nf < 8; nf++) {
                    int gn = bn + wn + nf * 8 + tc;
                    float v0 = acc[mf][nf][h * 2 + 0] + bias[gn];
                    float v1 = acc[mf][nf][h * 2 + 1] + bias[gn + 1];
                    if (MODE == 2) {
                        float2 o; o.x = v0; o.y = v1;
                        *reinterpret_cast<float2*>((float*)Cv + rb + gn) = o;
                    } else {
                        *reinterpret_cast<__half2*>((__half*)Cv + rb + gn) =
                            __halves2half2(__float2half(v0), __float2half(v1));
                    }
                }
            }
        }
    }
}

// ---------------- one-shot conversion of x + 3 weights ----------------
__global__ void cvt_all_kernel(const float* __restrict__ s0, __half* __restrict__ h0, int n0,
                               const float* __restrict__ s1, __half* __restrict__ h1, int n1,
                               const float* __restrict__ s2, __half* __restrict__ h2, int n2,
                               const float* __restrict__ s3, __half* __restrict__ h3, int n3)
{
    int i = blockIdx.x * 256 + threadIdx.x;
    const float* s; __half* h; int j = i;
    if (j < n0) { s = s0; h = h0; }
    else {
        j -= n0;
        if (j < n1) { s = s1; h = h1; }
        else {
            j -= n1;
            if (j < n2) { s = s2; h = h2; }
            else {
                j -= n2;
                if (j >= n3) return;
                s = s3; h = h3;
            }
        }
    }
    float4 v = reinterpret_cast<const float4*>(s)[j];
    reinterpret_cast<__half2*>(h)[2*j]   = __halves2half2(__float2half(v.x), __float2half(v.y));
    reinterpret_cast<__half2*>(h)[2*j+1] = __halves2half2(__float2half(v.z), __float2half(v.w));
}

// ---------------- depthwise causal conv (width 4) + SiLU, half2 ----------------
__global__ void conv_silu_kernel(const __half* __restrict__ xz,
                                 const float* __restrict__ Wc,
                                 const float* __restrict__ bc,
                                 __half* __restrict__ xcf)
{
    int idx = blockIdx.x * blockDim.x + threadIdx.x;     // over M_TOTAL * D_INNER/2
    if (idx >= M_TOTAL * (D_INNER / 2)) return;
    int c2 = idx & (D_INNER / 2 - 1);
    int c = c2 * 2;
    int m = idx >> 10;               // D_INNER/2 == 1024
    int t = m & (SEQ - 1);

    float4 w0 = *reinterpret_cast<const float4*>(Wc + c * 4);
    float4 w1 = *reinterpret_cast<const float4*>(Wc + (c + 1) * 4);
    float2 bb = *reinterpret_cast<const float2*>(bc + c);
    float a0 = bb.x, a1 = bb.y;

    const size_t st = 2 * D_INNER;
    size_t base = (size_t)m * st + c;

    __half2 x0 = *reinterpret_cast<const __half2*>(xz + base);
    a0 += w0.w * __half2float(__low2half(x0));
    a1 += w1.w * __half2float(__high2half(x0));
    if (t >= 1) {
        __half2 x1 = *reinterpret_cast<const __half2*>(xz + base - st);
        a0 += w0.z * __half2float(__low2half(x1));
        a1 += w1.z * __half2float(__high2half(x1));
    }
    if (t >= 2) {
        __half2 x2 = *reinterpret_cast<const __half2*>(xz + base - 2 * st);
        a0 += w0.y * __half2float(__low2half(x2));
        a1 += w1.y * __half2float(__high2half(x2));
    }
    if (t >= 3) {
        __half2 x3 = *reinterpret_cast<const __half2*>(xz + base - 3 * st);
        a0 += w0.x * __half2float(__low2half(x3));
        a1 += w1.x * __half2float(__high2half(x3));
    }
    *reinterpret_cast<__half2*>(xcf + (size_t)m * D_INNER + c) =
        __halves2half2(__float2half(silu_f(a0)), __float2half(silu_f(a1)));
}

// ---------------- chunked scan (carry produced by GEMM2 epilogue) ----------------
__global__ void scanB_kernel(const float* __restrict__ carry, const float* __restrict__ decay,
                             float* __restrict__ hin)
{
    int idx = blockIdx.x * 256 + threadIdx.x;      // 8192
    if (idx >= BATCH * D_INNER) return;
    int c = idx & (D_INNER - 1);
    int b = idx >> 11;
    float d = decay[c];
    float dL = d;
    #pragma unroll
    for (int j = 0; j < 7; j++) dL = dL * dL;      // d^128
    float H = 0.0f;
    for (int ch = 0; ch < NCH; ch++) {
        int o = (b * NCH + ch) * D_INNER + c;
        hin[o] = H;
        H = fmaf(dL, H, carry[o]);
    }
}

__global__ void scanC_kernel(const __half* __restrict__ vals, const __half* __restrict__ xz,
                             const float* __restrict__ decay, const float* __restrict__ hin,
                             __half* __restrict__ yf)
{
    int idx = blockIdx.x * 256 + threadIdx.x;      // BATCH*NCH*D_INNER/2 = 65536
    if (idx >= BATCH * NCH * (D_INNER / 2)) return;
    int c2 = idx & (D_INNER / 2 - 1);
    int c = c2 * 2;
    int ch = (idx >> 10) & (NCH - 1);
    int b = idx >> 14;
    float2 d = *reinterpret_cast<const float2*>(decay + c);
    float2 h = *reinterpret_cast<const float2*>(hin + (size_t)(b * NCH + ch) * D_INNER + c);
    size_t m0 = (size_t)(b * SEQ + ch * LCH);
    size_t vbase = m0 * D_INNER + c;
    size_t zbase = m0 * (2 * D_INNER) + D_INNER + c;
    #pragma unroll 4
    for (int i = 0; i < LCH; i++) {
        __half2 v = *reinterpret_cast<const __half2*>(vals + vbase + (size_t)i * D_INNER);
        h.x = fmaf(d.x, h.x, __half2float(__low2half(v)));
        h.y = fmaf(d.y, h.y, __half2float(__high2half(v)));
        __half2 z = *reinterpret_cast<const __half2*>(xz + zbase + (size_t)i * (2 * D_INNER));
        float g0 = h.x * silu_f(__half2float(__low2half(z)));
        float g1 = h.y * silu_f(__half2float(__high2half(z)));
        *reinterpret_cast<__half2*>(yf + vbase + (size_t)i * D_INNER) =
            __halves2half2(__float2half(g0), __float2half(g1));
    }
}

// ---------------- launcher ----------------
extern "C" void kernel_launch(void* const* d_in, const int* in_sizes, int n_in,
                              void* d_out, int out_size)
{
    const float* x      = (const float*)d_in[0];
    const float* W_in   = (const float*)d_in[1];
    const float* b_in   = (const float*)d_in[2];
    const float* W_conv = (const float*)d_in[3];
    const float* b_conv = (const float*)d_in[4];
    const float* W_dt   = (const float*)d_in[5];
    const float* b_dt   = (const float*)d_in[6];
    const float* W_out  = (const float*)d_in[7];
    const float* b_out  = (const float*)d_in[8];
    const float* decay  = (const float*)d_in[9];
    float* out = (float*)d_out;

    float *carry, *hin;
    __half *xz, *vals, *xf, *xcf, *yf, *wi, *wd, *wo;
    cudaGetSymbolAddress((void**)&xz, g_xz);
    cudaGetSymbolAddress((void**)&vals, g_vals);
    cudaGetSymbolAddress((void**)&carry, g_carry);
    cudaGetSymbolAddress((void**)&hin, g_hin);
    cudaGetSymbolAddress((void**)&xf, g_xf);
    cudaGetSymbolAddress((void**)&xcf, g_xcf);
    cudaGetSymbolAddress((void**)&yf, g_yf);
    cudaGetSymbolAddress((void**)&wi, g_wi);
    cudaGetSymbolAddress((void**)&wd, g_wd);
    cudaGetSymbolAddress((void**)&wo, g_wo);

    cudaFuncSetAttribute(gemm_mma<0>, cudaFuncAttributeMaxDynamicSharedMemorySize, GSMEM_BYTES);
    cudaFuncSetAttribute(gemm_mma<1>, cudaFuncAttributeMaxDynamicSharedMemorySize, GSMEM_BYTES);
    cudaFuncSetAttribute(gemm_mma<2>, cudaFuncAttributeMaxDynamicSharedMemorySize, GSMEM_BYTES);

    // one fused conversion launch (all counts in float4 units)
    const int n0 = M_TOTAL * D_MODEL / 4;        // x
    const int n1 = 2 * D_INNER * D_MODEL / 4;    // W_in
    const int n2 = D_INNER * D_INNER / 4;        // W_dt
    const int n3 = D_MODEL * D_INNER / 4;        // W_out
    cvt_all_kernel<<<(n0 + n1 + n2 + n3 + 255) / 256, 256>>>(
        x, xf, n0, W_in, wi, n1, W_dt, wd, n2, W_out, wo, n3);

    // GEMM1: xz(fp16) = x @ W_in^T + b_in   [8192, 4096], K=1024
    gemm_mma<0><<<dim3((2 * D_INNER) / BN, M_TOTAL / BM), 256, GSMEM_BYTES>>>(
        xf, wi, b_in, xz, nullptr, nullptr, nullptr, M_TOTAL, 2 * D_INNER, D_MODEL);

    // conv + silu -> xcf (fp16), half2
    conv_silu_kernel<<<(M_TOTAL * D_INNER / 2) / 256, 256>>>(xz, W_conv, b_conv, xcf);

    // GEMM2: vals(fp16) = softplus(xcf @ W_dt^T + b_dt) * xcf ; + fused chunk carries
    gemm_mma<1><<<dim3(D_INNER / BN, M_TOTAL / BM), 256, GSMEM_BYTES>>>(
        xcf, wd, b_dt, vals, xcf, decay, carry, M_TOTAL, D_INNER, D_INNER);

    // cross-chunk prefix + per-chunk recompute/gate
    scanB_kernel<<<(BATCH * D_INNER) / 256, 256>>>(carry, decay, hin);
    scanC_kernel<<<(BATCH * NCH * D_INNER / 2) / 256, 256>>>(vals, xz, decay, hin, yf);

    // GEMM3: out(fp32) = y @ W_out^T + b_out   [8192, 1024], K=2048
    gemm_mma<2><<<dim3(D_MODEL / BN, M_TOTAL / BM), 256, GSMEM_BYTES>>>(
        yf, wo, b_out, out, nullptr, nullptr, nullptr, M_TOTAL, D_MODEL, D_INNER);
}

// round 15
// speedup vs baseline: 5.2169x; 1.0008x over previous
#include <cuda_runtime.h>
#include <cuda_fp16.h>
#include <cstdint>
#include <cstddef>

#define D_MODEL 1024
#define D_INNER 2048
#define BATCH   4
#define SEQ     2048
#define M_TOTAL (BATCH * SEQ)   // 8192
#define NCH     16              // scan chunks per sequence
#define LCH     (SEQ / NCH)     // 128

// ---------------- scratch (device globals; no allocation) ----------------
__device__ __half g_xz  [(size_t)M_TOTAL * (2 * D_INNER)];
__device__ __half g_vals[(size_t)M_TOTAL * D_INNER];

__device__ __half g_xf  [(size_t)M_TOTAL * D_MODEL];
__device__ __half g_xcf [(size_t)M_TOTAL * D_INNER];
__device__ __half g_yf  [(size_t)M_TOTAL * D_INNER];
__device__ __half g_wi  [(size_t)(2*D_INNER) * D_MODEL];
__device__ __half g_wd  [(size_t)D_INNER * D_INNER];
__device__ __half g_wo  [(size_t)D_MODEL * D_INNER];
__device__ float g_carry[BATCH * NCH * D_INNER];
__device__ float g_hin  [BATCH * NCH * D_INNER];

// ---------------- helpers ----------------
__device__ __forceinline__ uint32_t smem_u32(const void* p) {
    uint32_t a;
    asm("{ .reg .u64 t; cvta.to.shared.u64 t, %1; cvt.u32.u64 %0, t; }" : "=r"(a) : "l"(p));
    return a;
}
__device__ __forceinline__ void cp16(uint32_t saddr, const void* g) {
    asm volatile("cp.async.cg.shared.global [%0], [%1], 16;" :: "r"(saddr), "l"(g) : "memory");
}
__device__ __forceinline__ float silu_f(float x) { return x / (1.0f + expf(-x)); }
__device__ __forceinline__ float softplus_f(float x) { return (x > 20.0f) ? x : log1pf(expf(x)); }

// ---------------- mma.sync fp16 GEMM ----------------
// C[M,N] = A[M,K] @ B[N,K]^T
// CTA tile 128x256, 512 threads: 16 warps as 2x8 -> 64x32 warp tile.
// 3-stage cp.async pipeline.
// MODE 0: Chalf = acc + bias
// MODE 1: Chalf = softplus(acc+bias) * auxhalf; + fused per-chunk scan carry
// MODE 2: Cfloat = acc + bias
#define BM 128
#define BN 256
#define BK 64
#define AST 72
#define TILE_A_H (BM * AST)
#define TILE_B_H (BN * AST)
#define STAGE_H (TILE_A_H + TILE_B_H)  // 54KB
#define OFF_A  0
#define OFF_B  TILE_A_H
#define NSTAGE 3
#define GSMEM_BYTES (NSTAGE * STAGE_H * 2)  // 165888
#define NTHR 512

template <int MODE>
__global__ __launch_bounds__(NTHR)
void gemm_mma(const __half* __restrict__ A, const __half* __restrict__ B,
              const float* __restrict__ bias, void* __restrict__ Cv,
              const __half* __restrict__ aux,
              const float* __restrict__ decay, float* __restrict__ carry,
              int M, int N, int K)
{
    extern __shared__ __half smem[];

    const int tid  = threadIdx.x;
    const int wid  = tid >> 5;
    const int lane = tid & 31;
    const int bm = blockIdx.y * BM;
    const int bn = blockIdx.x * BN;
    const int wm = (wid >> 3) * 64;    // warp row: 0 or 64
    const int wn = (wid & 7) * 32;     // warp col: 0..224

    const __half* Aa = A + (size_t)bm * K;
    const __half* Bb = B + (size_t)bn * K;

    const int nst = K / BK;

    float acc[4][4][4];
    #pragma unroll
    for (int i = 0; i < 4; i++)
        #pragma unroll
        for (int j = 0; j < 4; j++)
            #pragma unroll
            for (int r = 0; r < 4; r++) acc[i][j][r] = 0.0f;

    auto load_stage = [&](int s, int buf) {
        const int kb = s * BK;
        __half* st = smem + buf * STAGE_H;
        #pragma unroll
        for (int it = 0; it < 2; it++) {        // A: 1024 segs / 512 thr
            int seg = tid + it * NTHR;
            int r = seg >> 3;
            int q = (seg & 7) * 8;
            cp16(smem_u32(st + OFF_A + r * AST + q), Aa + (size_t)r * K + kb + q);
        }
        #pragma unroll
        for (int it = 0; it < 4; it++) {        // B: 2048 segs / 512 thr
            int seg = tid + it * NTHR;
            int r = seg >> 3;
            int q = (seg & 7) * 8;
            cp16(smem_u32(st + OFF_B + r * AST + q), Bb + (size_t)r * K + kb + q);
        }
        asm volatile("cp.async.commit_group;" ::: "memory");
    };

    load_stage(0, 0);
    load_stage(1, 1);
    asm volatile("cp.async.wait_group 1;" ::: "memory");
    __syncthreads();

    int buf = 0;
    for (int s = 0; s < nst; s++) {
        if (s + 2 < nst) load_stage(s + 2, (s + 2) % NSTAGE);

        const __half* st = smem + buf * STAGE_H;
        #pragma unroll
        for (int kk = 0; kk < 4; kk++) {
            uint32_t a[4][4], b[4][2];
            #pragma unroll
            for (int mf = 0; mf < 4; mf++) {
                int so = (wm + mf * 16 + (lane & 15)) * AST + kk * 16 + (lane >> 4) * 8;
                uint32_t ad = smem_u32(st + OFF_A + so);
                asm volatile("ldmatrix.sync.aligned.m8n8.x4.shared.b16 {%0,%1,%2,%3}, [%4];"
                             : "=r"(a[mf][0]), "=r"(a[mf][1]), "=r"(a[mf][2]), "=r"(a[mf][3]) : "r"(ad));
            }
            #pragma unroll
            for (int nfp = 0; nfp < 2; nfp++) {
                int nfq   = nfp * 2 + ((lane >> 4) & 1);
                int khalf = (lane >> 3) & 1;
                int so = (wn + nfq * 8 + (lane & 7)) * AST + kk * 16 + khalf * 8;
                uint32_t bd = smem_u32(st + OFF_B + so);
                asm volatile("ldmatrix.sync.aligned.m8n8.x4.shared.b16 {%0,%1,%2,%3}, [%4];"
                             : "=r"(b[nfp*2][0]), "=r"(b[nfp*2][1]),
                               "=r"(b[nfp*2+1][0]), "=r"(b[nfp*2+1][1]) : "r"(bd));
            }
            #pragma unroll
            for (int mf = 0; mf < 4; mf++)
                #pragma unroll
                for (int nf = 0; nf < 4; nf++) {
                    asm volatile(
                        "mma.sync.aligned.m16n8k16.row.col.f32.f16.f16.f32 "
                        "{%0,%1,%2,%3}, {%4,%5,%6,%7}, {%8,%9}, {%0,%1,%2,%3};"
                        : "+f"(acc[mf][nf][0]), "+f"(acc[mf][nf][1]),
                          "+f"(acc[mf][nf][2]), "+f"(acc[mf][nf][3])
                        : "r"(a[mf][0]), "r"(a[mf][1]), "r"(a[mf][2]), "r"(a[mf][3]),
                          "r"(b[nf][0]), "r"(b[nf][1]));
                }
        }

        if (s + 2 < nst)      { asm volatile("cp.async.wait_group 1;" ::: "memory"); }
        else if (s + 1 < nst) { asm volatile("cp.async.wait_group 0;" ::: "memory"); }
        __syncthreads();
        buf = (buf + 1) % NSTAGE;
    }

    const int tr = lane >> 2;
    const int tc = (lane & 3) * 2;

    if (MODE == 1) {
        // softplus-gate epilogue + fused per-chunk scan carry.
        // carry_col = sum_{row} d^(127-row) * vals_row
        // d^(127-row) = d^(127-wm-tr) * (d^-16)^mf * (d^-8)^h
        float cw0[4], cw1[4];
        const float e0 = (float)(127 - wm - tr);
        #pragma unroll
        for (int nf = 0; nf < 4; nf++) {
            int gn = bn + wn + nf * 8 + tc;
            float d0 = decay[gn], d1 = decay[gn + 1];
            float b0 = bias[gn],  b1 = bias[gn + 1];
            float pb0 = __powf(d0, e0), pb1 = __powf(d1, e0);
            float iv0 = __frcp_rn(d0), iv1 = __frcp_rn(d1);
            float i80 = iv0 * iv0; i80 *= i80; i80 *= i80;   // d^-8
            float i81 = iv1 * iv1; i81 *= i81; i81 *= i81;
            float i160 = i80 * i80, i161 = i81 * i81;        // d^-16
            float wmf0 = pb0, wmf1 = pb1;
            float c0 = 0.0f, c1 = 0.0f;
            #pragma unroll
            for (int mf = 0; mf < 4; mf++) {
                #pragma unroll
                for (int h = 0; h < 2; h++) {
                    int gm = bm + wm + mf * 16 + tr + h * 8;
                    size_t rb = (size_t)gm * N;
                    float v0 = acc[mf][nf][h * 2 + 0] + b0;
                    float v1 = acc[mf][nf][h * 2 + 1] + b1;
                    __half2 ax = *reinterpret_cast<const __half2*>(aux + rb + gn);
                    v0 = softplus_f(v0) * __half2float(__low2half(ax));
                    v1 = softplus_f(v1) * __half2float(__high2half(ax));
                    *reinterpret_cast<__half2*>((__half*)Cv + rb + gn) =
                        __halves2half2(__float2half(v0), __float2half(v1));
                    float w0 = h ? wmf0 * i80 : wmf0;
                    float w1 = h ? wmf1 * i81 : wmf1;
                    c0 = fmaf(w0, v0, c0);
                    c1 = fmaf(w1, v1, c1);
                }
                wmf0 *= i160; wmf1 *= i161;
            }
            cw0[nf] = c0; cw1[nf] = c1;
        }
        #pragma unroll
        for (int nf = 0; nf < 4; nf++) {
            #pragma unroll
            for (int off = 4; off <= 16; off <<= 1) {
                cw0[nf] += __shfl_xor_sync(0xffffffff, cw0[nf], off);
                cw1[nf] += __shfl_xor_sync(0xffffffff, cw1[nf], off);
            }
        }
        float* csm = reinterpret_cast<float*>(smem);   // [2][BN]
        if (lane < 4) {
            #pragma unroll
            for (int nf = 0; nf < 4; nf++) {
                int col = wn + nf * 8 + lane * 2;
                csm[(wid >> 3) * BN + col]     = cw0[nf];
                csm[(wid >> 3) * BN + col + 1] = cw1[nf];
            }
        }
        __syncthreads();
        if (tid < BN) {
            int j = tid;
            float cval = csm[j] + csm[BN + j];
            carry[((size_t)(bm >> 7)) * N + bn + j] = cval;
        }
    } else {
        #pragma unroll
        for (int mf = 0; mf < 4; mf++) {
            #pragma unroll
            for (int h = 0; h < 2; h++) {
                int gm = bm + wm + mf * 16 + tr + h * 8;
                size_t rb = (size_t)gm * N;
                #pragma unroll
                for (int nf = 0; nf < 4; nf++) {
                    int gn = bn + wn + nf * 8 + tc;
                    float v0 = acc[mf][nf][h * 2 + 0] + bias[gn];
                    float v1 = acc[mf][nf][h * 2 + 1] + bias[gn + 1];
                    if (MODE == 2) {
                        float2 o; o.x = v0; o.y = v1;
                        *reinterpret_cast<float2*>((float*)Cv + rb + gn) = o;
                    } else {
                        *reinterpret_cast<__half2*>((__half*)Cv + rb + gn) =
                            __halves2half2(__float2half(v0), __float2half(v1));
                    }
                }
            }
        }
    }
}

// ---------------- one-shot conversion of x + 3 weights ----------------
__global__ void cvt_all_kernel(const float* __restrict__ s0, __half* __restrict__ h0, int n0,
                               const float* __restrict__ s1, __half* __restrict__ h1, int n1,
                               const float* __restrict__ s2, __half* __restrict__ h2, int n2,
                               const float* __restrict__ s3, __half* __restrict__ h3, int n3)
{
    int i = blockIdx.x * 256 + threadIdx.x;
    const float* s; __half* h; int j = i;
    if (j < n0) { s = s0; h = h0; }
    else {
        j -= n0;
        if (j < n1) { s = s1; h = h1; }
        else {
            j -= n1;
            if (j < n2) { s = s2; h = h2; }
            else {
                j -= n2;
                if (j >= n3) return;
                s = s3; h = h3;
            }
        }
    }
    float4 v = reinterpret_cast<const float4*>(s)[j];
    reinterpret_cast<__half2*>(h)[2*j]   = __halves2half2(__float2half(v.x), __float2half(v.y));
    reinterpret_cast<__half2*>(h)[2*j+1] = __halves2half2(__float2half(v.z), __float2half(v.w));
}

// ---------------- depthwise causal conv (width 4) + SiLU, half2 ----------------
__global__ void conv_silu_kernel(const __half* __restrict__ xz,
                                 const float* __restrict__ Wc,
                                 const float* __restrict__ bc,
                                 __half* __restrict__ xcf)
{
    int idx = blockIdx.x * blockDim.x + threadIdx.x;
    if (idx >= M_TOTAL * (D_INNER / 2)) return;
    int c2 = idx & (D_INNER / 2 - 1);
    int c = c2 * 2;
    int m = idx >> 10;
    int t = m & (SEQ - 1);

    float4 w0 = *reinterpret_cast<const float4*>(Wc + c * 4);
    float4 w1 = *reinterpret_cast<const float4*>(Wc + (c + 1) * 4);
    float2 bb = *reinterpret_cast<const float2*>(bc + c);
    float a0 = bb.x, a1 = bb.y;

    const size_t st = 2 * D_INNER;
    size_t base = (size_t)m * st + c;

    __half2 x0 = *reinterpret_cast<const __half2*>(xz + base);
    a0 += w0.w * __half2float(__low2half(x0));
    a1 += w1.w * __half2float(__high2half(x0));
    if (t >= 1) {
        __half2 x1 = *reinterpret_cast<const __half2*>(xz + base - st);
        a0 += w0.z * __half2float(__low2half(x1));
        a1 += w1.z * __half2float(__high2half(x1));
    }
    if (t >= 2) {
        __half2 x2 = *reinterpret_cast<const __half2*>(xz + base - 2 * st);
        a0 += w0.y * __half2float(__low2half(x2));
        a1 += w1.y * __half2float(__high2half(x2));
    }
    if (t >= 3) {
        __half2 x3 = *reinterpret_cast<const __half2*>(xz + base - 3 * st);
        a0 += w0.x * __half2float(__low2half(x3));
        a1 += w1.x * __half2float(__high2half(x3));
    }
    *reinterpret_cast<__half2*>(xcf + (size_t)m * D_INNER + c) =
        __halves2half2(__float2half(silu_f(a0)), __float2half(silu_f(a1)));
}

// ---------------- chunked scan (carry from GEMM2 epilogue) ----------------
__global__ void scanB_kernel(const float* __restrict__ carry, const float* __restrict__ decay,
                             float* __restrict__ hin)
{
    int idx = blockIdx.x * 256 + threadIdx.x;      // 8192
    if (idx >= BATCH * D_INNER) return;
    int c = idx & (D_INNER - 1);
    int b = idx >> 11;
    float d = decay[c];
    float dL = d;
    #pragma unroll
    for (int j = 0; j < 7; j++) dL = dL * dL;      // d^128
    float H = 0.0f;
    for (int ch = 0; ch < NCH; ch++) {
        int o = (b * NCH + ch) * D_INNER + c;
        hin[o] = H;
        H = fmaf(dL, H, carry[o]);
    }
}

__global__ void scanC_kernel(const __half* __restrict__ vals, const __half* __restrict__ xz,
                             const float* __restrict__ decay, const float* __restrict__ hin,
                             __half* __restrict__ yf)
{
    int idx = blockIdx.x * 256 + threadIdx.x;      // 65536
    if (idx >= BATCH * NCH * (D_INNER / 2)) return;
    int c2 = idx & (D_INNER / 2 - 1);
    int c = c2 * 2;
    int ch = (idx >> 10) & (NCH - 1);
    int b = idx >> 14;
    float2 d = *reinterpret_cast<const float2*>(decay + c);
    float2 h = *reinterpret_cast<const float2*>(hin + (size_t)(b * NCH + ch) * D_INNER + c);
    size_t m0 = (size_t)(b * SEQ + ch * LCH);
    size_t vbase = m0 * D_INNER + c;
    size_t zbase = m0 * (2 * D_INNER) + D_INNER + c;
    #pragma unroll 4
    for (int i = 0; i < LCH; i++) {
        __half2 v = *reinterpret_cast<const __half2*>(vals + vbase + (size_t)i * D_INNER);
        h.x = fmaf(d.x, h.x, __half2float(__low2half(v)));
        h.y = fmaf(d.y, h.y, __half2float(__high2half(v)));
        __half2 z = *reinterpret_cast<const __half2*>(xz + zbase + (size_t)i * (2 * D_INNER));
        float g0 = h.x * silu_f(__half2float(__low2half(z)));
        float g1 = h.y * silu_f(__half2float(__high2half(z)));
        *reinterpret_cast<__half2*>(yf + vbase + (size_t)i * D_INNER) =
            __halves2half2(__float2half(g0), __float2half(g1));
    }
}

// ---------------- launcher ----------------
extern "C" void kernel_launch(void* const* d_in, const int* in_sizes, int n_in,
                              void* d_out, int out_size)
{
    const float* x      = (const float*)d_in[0];
    const float* W_in   = (const float*)d_in[1];
    const float* b_in   = (const float*)d_in[2];
    const float* W_conv = (const float*)d_in[3];
    const float* b_conv = (const float*)d_in[4];
    const float* W_dt   = (const float*)d_in[5];
    const float* b_dt   = (const float*)d_in[6];
    const float* W_out  = (const float*)d_in[7];
    const float* b_out  = (const float*)d_in[8];
    const float* decay  = (const float*)d_in[9];
    float* out = (float*)d_out;

    float *carry, *hin;
    __half *xz, *vals, *xf, *xcf, *yf, *wi, *wd, *wo;
    cudaGetSymbolAddress((void**)&xz, g_xz);
    cudaGetSymbolAddress((void**)&vals, g_vals);
    cudaGetSymbolAddress((void**)&carry, g_carry);
    cudaGetSymbolAddress((void**)&hin, g_hin);
    cudaGetSymbolAddress((void**)&xf, g_xf);
    cudaGetSymbolAddress((void**)&xcf, g_xcf);
    cudaGetSymbolAddress((void**)&yf, g_yf);
    cudaGetSymbolAddress((void**)&wi, g_wi);
    cudaGetSymbolAddress((void**)&wd, g_wd);
    cudaGetSymbolAddress((void**)&wo, g_wo);

    cudaFuncSetAttribute(gemm_mma<0>, cudaFuncAttributeMaxDynamicSharedMemorySize, GSMEM_BYTES);
    cudaFuncSetAttribute(gemm_mma<1>, cudaFuncAttributeMaxDynamicSharedMemorySize, GSMEM_BYTES);
    cudaFuncSetAttribute(gemm_mma<2>, cudaFuncAttributeMaxDynamicSharedMemorySize, GSMEM_BYTES);

    const int n0 = M_TOTAL * D_MODEL / 4;
    const int n1 = 2 * D_INNER * D_MODEL / 4;
    const int n2 = D_INNER * D_INNER / 4;
    const int n3 = D_MODEL * D_INNER / 4;
    cvt_all_kernel<<<(n0 + n1 + n2 + n3 + 255) / 256, 256>>>(
        x, xf, n0, W_in, wi, n1, W_dt, wd, n2, W_out, wo, n3);

    // GEMM1: xz(fp16) = x @ W_in^T + b_in   [8192, 4096], K=1024
    gemm_mma<0><<<dim3((2 * D_INNER) / BN, M_TOTAL / BM), NTHR, GSMEM_BYTES>>>(
        xf, wi, b_in, xz, nullptr, nullptr, nullptr, M_TOTAL, 2 * D_INNER, D_MODEL);

    // conv + silu -> xcf (fp16)
    conv_silu_kernel<<<(M_TOTAL * D_INNER / 2) / 256, 256>>>(xz, W_conv, b_conv, xcf);

    // GEMM2: vals(fp16) = softplus(xcf @ W_dt^T + b_dt) * xcf ; + fused chunk carries
    gemm_mma<1><<<dim3(D_INNER / BN, M_TOTAL / BM), NTHR, GSMEM_BYTES>>>(
        xcf, wd, b_dt, vals, xcf, decay, carry, M_TOTAL, D_INNER, D_INNER);

    // cross-chunk prefix + per-chunk recompute/gate
    scanB_kernel<<<(BATCH * D_INNER) / 256, 256>>>(carry, decay, hin);
    scanC_kernel<<<(BATCH * NCH * D_INNER / 2) / 256, 256>>>(vals, xz, decay, hin, yf);

    // GEMM3: out(fp32) = y @ W_out^T + b_out   [8192, 1024], K=2048
    gemm_mma<2><<<dim3(D_MODEL / BN, M_TOTAL / BM), NTHR, GSMEM_BYTES>>>(
        yf, wo, b_out, out, nullptr, nullptr, nullptr, M_TOTAL, D_MODEL, D_INNER);
}

// round 16
// speedup vs baseline: 5.6991x; 1.0924x over previous
#include <cuda_runtime.h>
#include <cuda_fp16.h>
#include <cstdint>
#include <cstddef>

#define D_MODEL 1024
#define D_INNER 2048
#define BATCH   4
#define SEQ     2048
#define M_TOTAL (BATCH * SEQ)   // 8192
#define NCH     16              // scan chunks per sequence
#define LCH     (SEQ / NCH)     // 128

// ---------------- scratch (device globals; no allocation) ----------------
__device__ __half g_xz  [(size_t)M_TOTAL * (2 * D_INNER)];
__device__ __half g_vals[(size_t)M_TOTAL * D_INNER];

__device__ __half g_xf  [(size_t)M_TOTAL * D_MODEL];
__device__ __half g_xcf [(size_t)M_TOTAL * D_INNER];
__device__ __half g_yf  [(size_t)M_TOTAL * D_INNER];
__device__ __half g_wi  [(size_t)(2*D_INNER) * D_MODEL];
__device__ __half g_wd  [(size_t)D_INNER * D_INNER];
__device__ __half g_wo  [(size_t)D_MODEL * D_INNER];
__device__ float g_carry[BATCH * NCH * D_INNER];
__device__ float g_hin  [BATCH * NCH * D_INNER];

// ---------------- helpers ----------------
__device__ __forceinline__ uint32_t smem_u32(const void* p) {
    uint32_t a;
    asm("{ .reg .u64 t; cvta.to.shared.u64 t, %1; cvt.u32.u64 %0, t; }" : "=r"(a) : "l"(p));
    return a;
}
__device__ __forceinline__ void cp16(uint32_t saddr, const void* g) {
    asm volatile("cp.async.cg.shared.global [%0], [%1], 16;" :: "r"(saddr), "l"(g) : "memory");
}
__device__ __forceinline__ float silu_f(float x) { return x / (1.0f + expf(-x)); }
__device__ __forceinline__ float softplus_f(float x) { return (x > 20.0f) ? x : log1pf(expf(x)); }

// ---------------- mma.sync fp16 GEMM ----------------
// C[M,N] = A[M,K] @ B[N,K]^T
// CTA tile 128x128, 256 threads: 8 warps as 2x4 -> 64x32 warp tile.
// 3-stage cp.async pipeline; 2 CTAs co-resident per SM (barrier decoupling).
// MODE 0: Chalf = acc + bias
// MODE 1: Chalf = softplus(acc+bias) * auxhalf; + fused per-chunk scan carry
// MODE 2: Cfloat = acc + bias
#define BM 128
#define BN 128
#define BK 64
#define AST 72
#define TILE_A_H (BM * AST)            // 9216 halves (18KB)
#define TILE_B_H (BN * AST)            // 9216 halves (18KB)
#define STAGE_H (TILE_A_H + TILE_B_H)  // 36KB
#define OFF_A  0
#define OFF_B  TILE_A_H
#define NSTAGE 3
#define GSMEM_BYTES (NSTAGE * STAGE_H * 2)  // 110592 -> 2 CTAs/SM
#define NTHR 256

template <int MODE>
__global__ __launch_bounds__(NTHR, 2)
void gemm_mma(const __half* __restrict__ A, const __half* __restrict__ B,
              const float* __restrict__ bias, void* __restrict__ Cv,
              const __half* __restrict__ aux,
              const float* __restrict__ decay, float* __restrict__ carry,
              int M, int N, int K)
{
    extern __shared__ __half smem[];

    const int tid  = threadIdx.x;
    const int wid  = tid >> 5;
    const int lane = tid & 31;
    const int bm = blockIdx.y * BM;
    const int bn = blockIdx.x * BN;
    const int wm = (wid >> 2) * 64;    // warp row: 0 or 64
    const int wn = (wid & 3) * 32;     // warp col: 0,32,64,96

    const __half* Aa = A + (size_t)bm * K;
    const __half* Bb = B + (size_t)bn * K;

    const int nst = K / BK;

    float acc[4][4][4];
    #pragma unroll
    for (int i = 0; i < 4; i++)
        #pragma unroll
        for (int j = 0; j < 4; j++)
            #pragma unroll
            for (int r = 0; r < 4; r++) acc[i][j][r] = 0.0f;

    auto load_stage = [&](int s, int buf) {
        const int kb = s * BK;
        __half* st = smem + buf * STAGE_H;
        #pragma unroll
        for (int it = 0; it < 4; it++) {        // A: 1024 segs / 256 thr
            int seg = tid + it * NTHR;
            int r = seg >> 3;
            int q = (seg & 7) * 8;
            cp16(smem_u32(st + OFF_A + r * AST + q), Aa + (size_t)r * K + kb + q);
        }
        #pragma unroll
        for (int it = 0; it < 4; it++) {        // B: 1024 segs / 256 thr
            int seg = tid + it * NTHR;
            int r = seg >> 3;
            int q = (seg & 7) * 8;
            cp16(smem_u32(st + OFF_B + r * AST + q), Bb + (size_t)r * K + kb + q);
        }
        asm volatile("cp.async.commit_group;" ::: "memory");
    };

    load_stage(0, 0);
    load_stage(1, 1);
    asm volatile("cp.async.wait_group 1;" ::: "memory");
    __syncthreads();

    int buf = 0;
    for (int s = 0; s < nst; s++) {
        if (s + 2 < nst) load_stage(s + 2, (s + 2) % NSTAGE);

        const __half* st = smem + buf * STAGE_H;
        #pragma unroll
        for (int kk = 0; kk < 4; kk++) {
            uint32_t a[4][4], b[4][2];
            #pragma unroll
            for (int mf = 0; mf < 4; mf++) {
                int so = (wm + mf * 16 + (lane & 15)) * AST + kk * 16 + (lane >> 4) * 8;
                uint32_t ad = smem_u32(st + OFF_A + so);
                asm volatile("ldmatrix.sync.aligned.m8n8.x4.shared.b16 {%0,%1,%2,%3}, [%4];"
                             : "=r"(a[mf][0]), "=r"(a[mf][1]), "=r"(a[mf][2]), "=r"(a[mf][3]) : "r"(ad));
            }
            #pragma unroll
            for (int nfp = 0; nfp < 2; nfp++) {
                int nfq   = nfp * 2 + ((lane >> 4) & 1);
                int khalf = (lane >> 3) & 1;
                int so = (wn + nfq * 8 + (lane & 7)) * AST + kk * 16 + khalf * 8;
                uint32_t bd = smem_u32(st + OFF_B + so);
                asm volatile("ldmatrix.sync.aligned.m8n8.x4.shared.b16 {%0,%1,%2,%3}, [%4];"
                             : "=r"(b[nfp*2][0]), "=r"(b[nfp*2][1]),
                               "=r"(b[nfp*2+1][0]), "=r"(b[nfp*2+1][1]) : "r"(bd));
            }
            #pragma unroll
            for (int mf = 0; mf < 4; mf++)
                #pragma unroll
                for (int nf = 0; nf < 4; nf++) {
                    asm volatile(
                        "mma.sync.aligned.m16n8k16.row.col.f32.f16.f16.f32 "
                        "{%0,%1,%2,%3}, {%4,%5,%6,%7}, {%8,%9}, {%0,%1,%2,%3};"
                        : "+f"(acc[mf][nf][0]), "+f"(acc[mf][nf][1]),
                          "+f"(acc[mf][nf][2]), "+f"(acc[mf][nf][3])
                        : "r"(a[mf][0]), "r"(a[mf][1]), "r"(a[mf][2]), "r"(a[mf][3]),
                          "r"(b[nf][0]), "r"(b[nf][1]));
                }
        }

        if (s + 2 < nst)      { asm volatile("cp.async.wait_group 1;" ::: "memory"); }
        else if (s + 1 < nst) { asm volatile("cp.async.wait_group 0;" ::: "memory"); }
        __syncthreads();
        buf = (buf + 1) % NSTAGE;
    }

    const int tr = lane >> 2;
    const int tc = (lane & 3) * 2;

    if (MODE == 1) {
        // softplus-gate epilogue + fused per-chunk scan carry.
        // carry_col = sum_{row} d^(127-row) * vals_row
        // d^(127-row) = d^(127-wm-tr) * (d^-16)^mf * (d^-8)^h
        float cw0[4], cw1[4];
        const float e0 = (float)(127 - wm - tr);
        #pragma unroll
        for (int nf = 0; nf < 4; nf++) {
            int gn = bn + wn + nf * 8 + tc;
            float d0 = decay[gn], d1 = decay[gn + 1];
            float b0 = bias[gn],  b1 = bias[gn + 1];
            float pb0 = __powf(d0, e0), pb1 = __powf(d1, e0);
            float iv0 = __frcp_rn(d0), iv1 = __frcp_rn(d1);
            float i80 = iv0 * iv0; i80 *= i80; i80 *= i80;   // d^-8
            float i81 = iv1 * iv1; i81 *= i81; i81 *= i81;
            float i160 = i80 * i80, i161 = i81 * i81;        // d^-16
            float wmf0 = pb0, wmf1 = pb1;
            float c0 = 0.0f, c1 = 0.0f;
            #pragma unroll
            for (int mf = 0; mf < 4; mf++) {
                #pragma unroll
                for (int h = 0; h < 2; h++) {
                    int gm = bm + wm + mf * 16 + tr + h * 8;
                    size_t rb = (size_t)gm * N;
                    float v0 = acc[mf][nf][h * 2 + 0] + b0;
                    float v1 = acc[mf][nf][h * 2 + 1] + b1;
                    __half2 ax = *reinterpret_cast<const __half2*>(aux + rb + gn);
                    v0 = softplus_f(v0) * __half2float(__low2half(ax));
                    v1 = softplus_f(v1) * __half2float(__high2half(ax));
                    *reinterpret_cast<__half2*>((__half*)Cv + rb + gn) =
                        __halves2half2(__float2half(v0), __float2half(v1));
                    float w0 = h ? wmf0 * i80 : wmf0;
                    float w1 = h ? wmf1 * i81 : wmf1;
                    c0 = fmaf(w0, v0, c0);
                    c1 = fmaf(w1, v1, c1);
                }
                wmf0 *= i160; wmf1 *= i161;
            }
            cw0[nf] = c0; cw1[nf] = c1;
        }
        #pragma unroll
        for (int nf = 0; nf < 4; nf++) {
            #pragma unroll
            for (int off = 4; off <= 16; off <<= 1) {
                cw0[nf] += __shfl_xor_sync(0xffffffff, cw0[nf], off);
                cw1[nf] += __shfl_xor_sync(0xffffffff, cw1[nf], off);
            }
        }
        float* csm = reinterpret_cast<float*>(smem);   // [2][BN]
        if (lane < 4) {
            #pragma unroll
            for (int nf = 0; nf < 4; nf++) {
                int col = wn + nf * 8 + lane * 2;
                csm[(wid >> 2) * BN + col]     = cw0[nf];
                csm[(wid >> 2) * BN + col + 1] = cw1[nf];
            }
        }
        __syncthreads();
        if (tid < BN) {
            int j = tid;
            float cval = csm[j] + csm[BN + j];
            carry[((size_t)(bm >> 7)) * N + bn + j] = cval;
        }
    } else {
        #pragma unroll
        for (int mf = 0; mf < 4; mf++) {
            #pragma unroll
            for (int h = 0; h < 2; h++) {
                int gm = bm + wm + mf * 16 + tr + h * 8;
                size_t rb = (size_t)gm * N;
                #pragma unroll
                for (int nf = 0; nf < 4; nf++) {
                    int gn = bn + wn + nf * 8 + tc;
                    float v0 = acc[mf][nf][h * 2 + 0] + bias[gn];
                    float v1 = acc[mf][nf][h * 2 + 1] + bias[gn + 1];
                    if (MODE == 2) {
                        float2 o; o.x = v0; o.y = v1;
                        *reinterpret_cast<float2*>((float*)Cv + rb + gn) = o;
                    } else {
                        *reinterpret_cast<__half2*>((__half*)Cv + rb + gn) =
                            __halves2half2(__float2half(v0), __float2half(v1));
                    }
                }
            }
        }
    }
}

// ---------------- one-shot conversion of x + 3 weights ----------------
__global__ void cvt_all_kernel(const float* __restrict__ s0, __half* __restrict__ h0, int n0,
                               const float* __restrict__ s1, __half* __restrict__ h1, int n1,
                               const float* __restrict__ s2, __half* __restrict__ h2, int n2,
                               const float* __restrict__ s3, __half* __restrict__ h3, int n3)
{
    int i = blockIdx.x * 256 + threadIdx.x;
    const float* s; __half* h; int j = i;
    if (j < n0) { s = s0; h = h0; }
    else {
        j -= n0;
        if (j < n1) { s = s1; h = h1; }
        else {
            j -= n1;
            if (j < n2) { s = s2; h = h2; }
            else {
                j -= n2;
                if (j >= n3) return;
                s = s3; h = h3;
            }
        }
    }
    float4 v = reinterpret_cast<const float4*>(s)[j];
    reinterpret_cast<__half2*>(h)[2*j]   = __halves2half2(__float2half(v.x), __float2half(v.y));
    reinterpret_cast<__half2*>(h)[2*j+1] = __halves2half2(__float2half(v.z), __float2half(v.w));
}

// ---------------- depthwise causal conv (width 4) + SiLU, half2 ----------------
__global__ void conv_silu_kernel(const __half* __restrict__ xz,
                                 const float* __restrict__ Wc,
                                 const float* __restrict__ bc,
                                 __half* __restrict__ xcf)
{
    int idx = blockIdx.x * blockDim.x + threadIdx.x;
    if (idx >= M_TOTAL * (D_INNER / 2)) return;
    int c2 = idx & (D_INNER / 2 - 1);
    int c = c2 * 2;
    int m = idx >> 10;
    int t = m & (SEQ - 1);

    float4 w0 = *reinterpret_cast<const float4*>(Wc + c * 4);
    float4 w1 = *reinterpret_cast<const float4*>(Wc + (c + 1) * 4);
    float2 bb = *reinterpret_cast<const float2*>(bc + c);
    float a0 = bb.x, a1 = bb.y;

    const size_t st = 2 * D_INNER;
    size_t base = (size_t)m * st + c;

    __half2 x0 = *reinterpret_cast<const __half2*>(xz + base);
    a0 += w0.w * __half2float(__low2half(x0));
    a1 += w1.w * __half2float(__high2half(x0));
    if (t >= 1) {
        __half2 x1 = *reinterpret_cast<const __half2*>(xz + base - st);
        a0 += w0.z * __half2float(__low2half(x1));
        a1 += w1.z * __half2float(__high2half(x1));
    }
    if (t >= 2) {
        __half2 x2 = *reinterpret_cast<const __half2*>(xz + base - 2 * st);
        a0 += w0.y * __half2float(__low2half(x2));
        a1 += w1.y * __half2float(__high2half(x2));
    }
    if (t >= 3) {
        __half2 x3 = *reinterpret_cast<const __half2*>(xz + base - 3 * st);
        a0 += w0.x * __half2float(__low2half(x3));
        a1 += w1.x * __half2float(__high2half(x3));
    }
    *reinterpret_cast<__half2*>(xcf + (size_t)m * D_INNER + c) =
        __halves2half2(__float2half(silu_f(a0)), __float2half(silu_f(a1)));
}

// ---------------- chunked scan (carry from GEMM2 epilogue) ----------------
__global__ void scanB_kernel(const float* __restrict__ carry, const float* __restrict__ decay,
                             float* __restrict__ hin)
{
    int idx = blockIdx.x * 256 + threadIdx.x;      // 8192
    if (idx >= BATCH * D_INNER) return;
    int c = idx & (D_INNER - 1);
    int b = idx >> 11;
    float d = decay[c];
    float dL = d;
    #pragma unroll
    for (int j = 0; j < 7; j++) dL = dL * dL;      // d^128
    float H = 0.0f;
    for (int ch = 0; ch < NCH; ch++) {
        int o = (b * NCH + ch) * D_INNER + c;
        hin[o] = H;
        H = fmaf(dL, H, carry[o]);
    }
}

__global__ void scanC_kernel(const __half* __restrict__ vals, const __half* __restrict__ xz,
                             const float* __restrict__ decay, const float* __restrict__ hin,
                             __half* __restrict__ yf)
{
    int idx = blockIdx.x * 256 + threadIdx.x;      // 65536
    if (idx >= BATCH * NCH * (D_INNER / 2)) return;
    int c2 = idx & (D_INNER / 2 - 1);
    int c = c2 * 2;
    int ch = (idx >> 10) & (NCH - 1);
    int b = idx >> 14;
    float2 d = *reinterpret_cast<const float2*>(decay + c);
    float2 h = *reinterpret_cast<const float2*>(hin + (size_t)(b * NCH + ch) * D_INNER + c);
    size_t m0 = (size_t)(b * SEQ + ch * LCH);
    size_t vbase = m0 * D_INNER + c;
    size_t zbase = m0 * (2 * D_INNER) + D_INNER + c;
    #pragma unroll 4
    for (int i = 0; i < LCH; i++) {
        __half2 v = *reinterpret_cast<const __half2*>(vals + vbase + (size_t)i * D_INNER);
        h.x = fmaf(d.x, h.x, __half2float(__low2half(v)));
        h.y = fmaf(d.y, h.y, __half2float(__high2half(v)));
        __half2 z = *reinterpret_cast<const __half2*>(xz + zbase + (size_t)i * (2 * D_INNER));
        float g0 = h.x * silu_f(__half2float(__low2half(z)));
        float g1 = h.y * silu_f(__half2float(__high2half(z)));
        *reinterpret_cast<__half2*>(yf + vbase + (size_t)i * D_INNER) =
            __halves2half2(__float2half(g0), __float2half(g1));
    }
}

// ---------------- launcher ----------------
extern "C" void kernel_launch(void* const* d_in, const int* in_sizes, int n_in,
                              void* d_out, int out_size)
{
    const float* x      = (const float*)d_in[0];
    const float* W_in   = (const float*)d_in[1];
    const float* b_in   = (const float*)d_in[2];
    const float* W_conv = (const float*)d_in[3];
    const float* b_conv = (const float*)d_in[4];
    const float* W_dt   = (const float*)d_in[5];
    const float* b_dt   = (const float*)d_in[6];
    const float* W_out  = (const float*)d_in[7];
    const float* b_out  = (const float*)d_in[8];
    const float* decay  = (const float*)d_in[9];
    float* out = (float*)d_out;

    float *carry, *hin;
    __half *xz, *vals, *xf, *xcf, *yf, *wi, *wd, *wo;
    cudaGetSymbolAddress((void**)&xz, g_xz);
    cudaGetSymbolAddress((void**)&vals, g_vals);
    cudaGetSymbolAddress((void**)&carry, g_carry);
    cudaGetSymbolAddress((void**)&hin, g_hin);
    cudaGetSymbolAddress((void**)&xf, g_xf);
    cudaGetSymbolAddress((void**)&xcf, g_xcf);
    cudaGetSymbolAddress((void**)&yf, g_yf);
    cudaGetSymbolAddress((void**)&wi, g_wi);
    cudaGetSymbolAddress((void**)&wd, g_wd);
    cudaGetSymbolAddress((void**)&wo, g_wo);

    cudaFuncSetAttribute(gemm_mma<0>, cudaFuncAttributeMaxDynamicSharedMemorySize, GSMEM_BYTES);
    cudaFuncSetAttribute(gemm_mma<1>, cudaFuncAttributeMaxDynamicSharedMemorySize, GSMEM_BYTES);
    cudaFuncSetAttribute(gemm_mma<2>, cudaFuncAttributeMaxDynamicSharedMemorySize, GSMEM_BYTES);

    const int n0 = M_TOTAL * D_MODEL / 4;
    const int n1 = 2 * D_INNER * D_MODEL / 4;
    const int n2 = D_INNER * D_INNER / 4;
    const int n3 = D_MODEL * D_INNER / 4;
    cvt_all_kernel<<<(n0 + n1 + n2 + n3 + 255) / 256, 256>>>(
        x, xf, n0, W_in, wi, n1, W_dt, wd, n2, W_out, wo, n3);

    // GEMM1: xz(fp16) = x @ W_in^T + b_in   [8192, 4096], K=1024
    gemm_mma<0><<<dim3((2 * D_INNER) / BN, M_TOTAL / BM), NTHR, GSMEM_BYTES>>>(
        xf, wi, b_in, xz, nullptr, nullptr, nullptr, M_TOTAL, 2 * D_INNER, D_MODEL);

    // conv + silu -> xcf (fp16)
    conv_silu_kernel<<<(M_TOTAL * D_INNER / 2) / 256, 256>>>(xz, W_conv, b_conv, xcf);

    // GEMM2: vals(fp16) = softplus(xcf @ W_dt^T + b_dt) * xcf ; + fused chunk carries
    gemm_mma<1><<<dim3(D_INNER / BN, M_TOTAL / BM), NTHR, GSMEM_BYTES>>>(
        xcf, wd, b_dt, vals, xcf, decay, carry, M_TOTAL, D_INNER, D_INNER);

    // cross-chunk prefix + per-chunk recompute/gate
    scanB_kernel<<<(BATCH * D_INNER) / 256, 256>>>(carry, decay, hin);
    scanC_kernel<<<(BATCH * NCH * D_INNER / 2) / 256, 256>>>(vals, xz, decay, hin, yf);

    // GEMM3: out(fp32) = y @ W_out^T + b_out   [8192, 1024], K=2048
    gemm_mma<2><<<dim3(D_MODEL / BN, M_TOTAL / BM), NTHR, GSMEM_BYTES>>>(
        yf, wo, b_out, out, nullptr, nullptr, nullptr, M_TOTAL, D_MODEL, D_INNER);
}

// round 17
// speedup vs baseline: 6.0249x; 1.0572x over previous
#include <cuda_runtime.h>
#include <cuda_fp16.h>
#include <cstdint>
#include <cstddef>

#define D_MODEL 1024
#define D_INNER 2048
#define BATCH   4
#define SEQ     2048
#define M_TOTAL (BATCH * SEQ)   // 8192
#define NCH     16              // scan chunks per sequence
#define LCH     (SEQ / NCH)     // 128

// ---------------- scratch (device globals; no allocation) ----------------
__device__ __half g_xz  [(size_t)M_TOTAL * (2 * D_INNER)];
__device__ __half g_vals[(size_t)M_TOTAL * D_INNER];

__device__ __half g_xf  [(size_t)M_TOTAL * D_MODEL];
__device__ __half g_xcf [(size_t)M_TOTAL * D_INNER];
__device__ __half g_yf  [(size_t)M_TOTAL * D_INNER];
__device__ __half g_wi  [(size_t)(2*D_INNER) * D_MODEL];
__device__ __half g_wd  [(size_t)D_INNER * D_INNER];
__device__ __half g_wo  [(size_t)D_MODEL * D_INNER];
__device__ float g_carry[BATCH * NCH * D_INNER];
__device__ float g_hin  [BATCH * NCH * D_INNER];

// ---------------- helpers ----------------
__device__ __forceinline__ uint32_t smem_u32(const void* p) {
    uint32_t a;
    asm("{ .reg .u64 t; cvta.to.shared.u64 t, %1; cvt.u32.u64 %0, t; }" : "=r"(a) : "l"(p));
    return a;
}
__device__ __forceinline__ void cp16(uint32_t saddr, const void* g) {
    asm volatile("cp.async.cg.shared.global [%0], [%1], 16;" :: "r"(saddr), "l"(g) : "memory");
}
__device__ __forceinline__ float silu_f(float x) { return x / (1.0f + expf(-x)); }
__device__ __forceinline__ float softplus_f(float x) { return (x > 20.0f) ? x : log1pf(expf(x)); }

// ---------------- mma.sync fp16 GEMM ----------------
// C[M,N] = A[M,K] @ B[N,K]^T
// CTA tile 128x128, 256 threads: 8 warps as 2x4 -> 64x32 warp tile.
// 3-stage cp.async pipeline; 2 CTAs co-resident per SM.
// MODE 0: Chalf = acc + bias
// MODE 1: Chalf = softplus(acc+bias) * auxhalf; + fused per-chunk scan carry
// MODE 2: Cfloat = acc + bias
#define BM 128
#define BN 128
#define BK 64
#define AST 72
#define TILE_A_H (BM * AST)
#define TILE_B_H (BN * AST)
#define STAGE_H (TILE_A_H + TILE_B_H)  // 36KB
#define OFF_A  0
#define OFF_B  TILE_A_H
#define NSTAGE 3
#define GSMEM_BYTES (NSTAGE * STAGE_H * 2)  // 110592 -> 2 CTAs/SM
#define NTHR 256
#define STAGE_BYTES (STAGE_H * 2)

template <int MODE>
__global__ __launch_bounds__(NTHR, 2)
void gemm_mma(const __half* __restrict__ A, const __half* __restrict__ B,
              const float* __restrict__ bias, void* __restrict__ Cv,
              const __half* __restrict__ aux,
              const float* __restrict__ decay, float* __restrict__ carry,
              int M, int N, int K)
{
    extern __shared__ __half smem[];

    const int tid  = threadIdx.x;
    const int wid  = tid >> 5;
    const int lane = tid & 31;
    const int bm = blockIdx.y * BM;
    const int bn = blockIdx.x * BN;
    const int wm = (wid >> 2) * 64;    // warp row: 0 or 64
    const int wn = (wid & 3) * 32;     // warp col: 0,32,64,96

    const __half* Aa = A + (size_t)bm * K;
    const __half* Bb = B + (size_t)bn * K;

    const int nst = K / BK;

    float acc[4][4][4];
    #pragma unroll
    for (int i = 0; i < 4; i++)
        #pragma unroll
        for (int j = 0; j < 4; j++)
            #pragma unroll
            for (int r = 0; r < 4; r++) acc[i][j][r] = 0.0f;

    // hoisted ldmatrix addresses (buf 0, kk 0); per use add bufoff + kk*32B
    uint32_t a_ad[4], b_ad[2];
    #pragma unroll
    for (int mf = 0; mf < 4; mf++)
        a_ad[mf] = smem_u32(smem + OFF_A + (wm + mf * 16 + (lane & 15)) * AST + (lane >> 4) * 8);
    #pragma unroll
    for (int nfp = 0; nfp < 2; nfp++) {
        int nfq   = nfp * 2 + ((lane >> 4) & 1);
        int khalf = (lane >> 3) & 1;
        b_ad[nfp] = smem_u32(smem + OFF_B + (wn + nfq * 8 + (lane & 7)) * AST + khalf * 8);
    }

    auto load_stage = [&](int s, int buf) {
        const int kb = s * BK;
        __half* st = smem + buf * STAGE_H;
        #pragma unroll
        for (int it = 0; it < 4; it++) {        // A: 1024 segs / 256 thr
            int seg = tid + it * NTHR;
            int r = seg >> 3;
            int q = (seg & 7) * 8;
            cp16(smem_u32(st + OFF_A + r * AST + q), Aa + (size_t)r * K + kb + q);
        }
        #pragma unroll
        for (int it = 0; it < 4; it++) {        // B: 1024 segs / 256 thr
            int seg = tid + it * NTHR;
            int r = seg >> 3;
            int q = (seg & 7) * 8;
            cp16(smem_u32(st + OFF_B + r * AST + q), Bb + (size_t)r * K + kb + q);
        }
        asm volatile("cp.async.commit_group;" ::: "memory");
    };

    load_stage(0, 0);
    load_stage(1, 1);
    asm volatile("cp.async.wait_group 1;" ::: "memory");
    __syncthreads();

    int buf = 0;
    for (int s = 0; s < nst; s++) {
        if (s + 2 < nst) load_stage(s + 2, (s + 2) % NSTAGE);

        const uint32_t bufoff = buf * STAGE_BYTES;
        #pragma unroll
        for (int kk = 0; kk < 4; kk++) {
            const uint32_t kkoff = bufoff + kk * 32;
            uint32_t a[4][4], b[4][2];
            #pragma unroll
            for (int mf = 0; mf < 4; mf++) {
                asm volatile("ldmatrix.sync.aligned.m8n8.x4.shared.b16 {%0,%1,%2,%3}, [%4];"
                             : "=r"(a[mf][0]), "=r"(a[mf][1]), "=r"(a[mf][2]), "=r"(a[mf][3])
                             : "r"(a_ad[mf] + kkoff));
            }
            #pragma unroll
            for (int nfp = 0; nfp < 2; nfp++) {
                asm volatile("ldmatrix.sync.aligned.m8n8.x4.shared.b16 {%0,%1,%2,%3}, [%4];"
                             : "=r"(b[nfp*2][0]), "=r"(b[nfp*2][1]),
                               "=r"(b[nfp*2+1][0]), "=r"(b[nfp*2+1][1])
                             : "r"(b_ad[nfp] + kkoff));
            }
            #pragma unroll
            for (int mf = 0; mf < 4; mf++)
                #pragma unroll
                for (int nf = 0; nf < 4; nf++) {
                    asm volatile(
                        "mma.sync.aligned.m16n8k16.row.col.f32.f16.f16.f32 "
                        "{%0,%1,%2,%3}, {%4,%5,%6,%7}, {%8,%9}, {%0,%1,%2,%3};"
                        : "+f"(acc[mf][nf][0]), "+f"(acc[mf][nf][1]),
                          "+f"(acc[mf][nf][2]), "+f"(acc[mf][nf][3])
                        : "r"(a[mf][0]), "r"(a[mf][1]), "r"(a[mf][2]), "r"(a[mf][3]),
                          "r"(b[nf][0]), "r"(b[nf][1]));
                }
        }

        if (s + 2 < nst)      { asm volatile("cp.async.wait_group 1;" ::: "memory"); }
        else if (s + 1 < nst) { asm volatile("cp.async.wait_group 0;" ::: "memory"); }
        __syncthreads();
        buf = (buf + 1) % NSTAGE;
    }

    const int tr = lane >> 2;
    const int tc = (lane & 3) * 2;

    if (MODE == 1) {
        // softplus-gate epilogue + fused per-chunk scan carry.
        float cw0[4], cw1[4];
        const float e0 = (float)(127 - wm - tr);
        #pragma unroll
        for (int nf = 0; nf < 4; nf++) {
            int gn = bn + wn + nf * 8 + tc;
            float d0 = decay[gn], d1 = decay[gn + 1];
            float b0 = bias[gn],  b1 = bias[gn + 1];
            float pb0 = __powf(d0, e0), pb1 = __powf(d1, e0);
            float iv0 = __frcp_rn(d0), iv1 = __frcp_rn(d1);
            float i80 = iv0 * iv0; i80 *= i80; i80 *= i80;   // d^-8
            float i81 = iv1 * iv1; i81 *= i81; i81 *= i81;
            float i160 = i80 * i80, i161 = i81 * i81;        // d^-16
            float wmf0 = pb0, wmf1 = pb1;
            float c0 = 0.0f, c1 = 0.0f;
            #pragma unroll
            for (int mf = 0; mf < 4; mf++) {
                #pragma unroll
                for (int h = 0; h < 2; h++) {
                    int gm = bm + wm + mf * 16 + tr + h * 8;
                    size_t rb = (size_t)gm * N;
                    float v0 = acc[mf][nf][h * 2 + 0] + b0;
                    float v1 = acc[mf][nf][h * 2 + 1] + b1;
                    __half2 ax = *reinterpret_cast<const __half2*>(aux + rb + gn);
                    v0 = softplus_f(v0) * __half2float(__low2half(ax));
                    v1 = softplus_f(v1) * __half2float(__high2half(ax));
                    *reinterpret_cast<__half2*>((__half*)Cv + rb + gn) =
                        __halves2half2(__float2half(v0), __float2half(v1));
                    float w0 = h ? wmf0 * i80 : wmf0;
                    float w1 = h ? wmf1 * i81 : wmf1;
                    c0 = fmaf(w0, v0, c0);
                    c1 = fmaf(w1, v1, c1);
                }
                wmf0 *= i160; wmf1 *= i161;
            }
            cw0[nf] = c0; cw1[nf] = c1;
        }
        #pragma unroll
        for (int nf = 0; nf < 4; nf++) {
            #pragma unroll
            for (int off = 4; off <= 16; off <<= 1) {
                cw0[nf] += __shfl_xor_sync(0xffffffff, cw0[nf], off);
                cw1[nf] += __shfl_xor_sync(0xffffffff, cw1[nf], off);
            }
        }
        float* csm = reinterpret_cast<float*>(smem);   // [2][BN]
        if (lane < 4) {
            #pragma unroll
            for (int nf = 0; nf < 4; nf++) {
                int col = wn + nf * 8 + lane * 2;
                csm[(wid >> 2) * BN + col]     = cw0[nf];
                csm[(wid >> 2) * BN + col + 1] = cw1[nf];
            }
        }
        __syncthreads();
        if (tid < BN) {
            int j = tid;
            float cval = csm[j] + csm[BN + j];
            carry[((size_t)(bm >> 7)) * N + bn + j] = cval;
        }
    } else {
        #pragma unroll
        for (int mf = 0; mf < 4; mf++) {
            #pragma unroll
            for (int h = 0; h < 2; h++) {
                int gm = bm + wm + mf * 16 + tr + h * 8;
                size_t rb = (size_t)gm * N;
                #pragma unroll
                for (int nf = 0; nf < 4; nf++) {
                    int gn = bn + wn + nf * 8 + tc;
                    float v0 = acc[mf][nf][h * 2 + 0] + bias[gn];
                    float v1 = acc[mf][nf][h * 2 + 1] + bias[gn + 1];
                    if (MODE == 2) {
                        float2 o; o.x = v0; o.y = v1;
                        *reinterpret_cast<float2*>((float*)Cv + rb + gn) = o;
                    } else {
                        *reinterpret_cast<__half2*>((__half*)Cv + rb + gn) =
                            __halves2half2(__float2half(v0), __float2half(v1));
                    }
                }
            }
        }
    }
}

// ---------------- one-shot conversion of x + 3 weights (8 floats/thread) ----------------
__global__ void cvt_all_kernel(const float* __restrict__ s0, __half* __restrict__ h0, int n0,
                               const float* __restrict__ s1, __half* __restrict__ h1, int n1,
                               const float* __restrict__ s2, __half* __restrict__ h2, int n2,
                               const float* __restrict__ s3, __half* __restrict__ h3, int n3)
{
    int i = blockIdx.x * 256 + threadIdx.x;   // float8 index
    const float* s; __half* h; int j = i;
    if (j < n0) { s = s0; h = h0; }
    else {
        j -= n0;
        if (j < n1) { s = s1; h = h1; }
        else {
            j -= n1;
            if (j < n2) { s = s2; h = h2; }
            else {
                j -= n2;
                if (j >= n3) return;
                s = s3; h = h3;
            }
        }
    }
    float4 v0 = reinterpret_cast<const float4*>(s)[2*j];
    float4 v1 = reinterpret_cast<const float4*>(s)[2*j+1];
    __half2* ho = reinterpret_cast<__half2*>(h);
    ho[4*j]   = __halves2half2(__float2half(v0.x), __float2half(v0.y));
    ho[4*j+1] = __halves2half2(__float2half(v0.z), __float2half(v0.w));
    ho[4*j+2] = __halves2half2(__float2half(v1.x), __float2half(v1.y));
    ho[4*j+3] = __halves2half2(__float2half(v1.z), __float2half(v1.w));
}

// ---------------- depthwise causal conv (width 4) + SiLU, 4 channels/thread ----------------
__global__ void conv_silu_kernel(const __half* __restrict__ xz,
                                 const float* __restrict__ Wc,
                                 const float* __restrict__ bc,
                                 __half* __restrict__ xcf)
{
    int idx = blockIdx.x * blockDim.x + threadIdx.x;     // over M_TOTAL * D_INNER/4
    if (idx >= M_TOTAL * (D_INNER / 4)) return;
    int c4 = idx & (D_INNER / 4 - 1);
    int c = c4 * 4;
    int m = idx >> 9;               // D_INNER/4 == 512
    int t = m & (SEQ - 1);

    float4 w[4];
    #pragma unroll
    for (int u = 0; u < 4; u++) w[u] = *reinterpret_cast<const float4*>(Wc + (c + u) * 4);
    float4 bb = *reinterpret_cast<const float4*>(bc + c);
    float a[4] = {bb.x, bb.y, bb.z, bb.w};

    const size_t st = 2 * D_INNER;
    size_t base = (size_t)m * st + c;

    #pragma unroll
    for (int tap = 0; tap < 4; tap++) {           // tap 0 = current, 1..3 = history
        if (tap > t) break;
        uint2 raw = *reinterpret_cast<const uint2*>(xz + base - (size_t)tap * st);
        __half2 lo = *reinterpret_cast<__half2*>(&raw.x);
        __half2 hi = *reinterpret_cast<__half2*>(&raw.y);
        float xv[4] = { __half2float(__low2half(lo)), __half2float(__high2half(lo)),
                        __half2float(__low2half(hi)), __half2float(__high2half(hi)) };
        #pragma unroll
        for (int u = 0; u < 4; u++) {
            float wt = (tap == 0) ? w[u].w : (tap == 1) ? w[u].z : (tap == 2) ? w[u].y : w[u].x;
            a[u] = fmaf(wt, xv[u], a[u]);
        }
    }
    uint2 out;
    __half2 o0 = __halves2half2(__float2half(silu_f(a[0])), __float2half(silu_f(a[1])));
    __half2 o1 = __halves2half2(__float2half(silu_f(a[2])), __float2half(silu_f(a[3])));
    out.x = *reinterpret_cast<uint32_t*>(&o0);
    out.y = *reinterpret_cast<uint32_t*>(&o1);
    *reinterpret_cast<uint2*>(xcf + (size_t)m * D_INNER + c) = out;
}

// ---------------- chunked scan (carry from GEMM2 epilogue) ----------------
__global__ void scanB_kernel(const float* __restrict__ carry, const float* __restrict__ decay,
                             float* __restrict__ hin)
{
    int idx = blockIdx.x * 256 + threadIdx.x;      // 8192
    if (idx >= BATCH * D_INNER) return;
    int c = idx & (D_INNER - 1);
    int b = idx >> 11;
    float d = decay[c];
    float dL = d;
    #pragma unroll
    for (int j = 0; j < 7; j++) dL = dL * dL;      // d^128
    float H = 0.0f;
    for (int ch = 0; ch < NCH; ch++) {
        int o = (b * NCH + ch) * D_INNER + c;
        hin[o] = H;
        H = fmaf(dL, H, carry[o]);
    }
}

// 4 channels per thread
__global__ void scanC_kernel(const __half* __restrict__ vals, const __half* __restrict__ xz,
                             const float* __restrict__ decay, const float* __restrict__ hin,
                             __half* __restrict__ yf)
{
    int idx = blockIdx.x * 256 + threadIdx.x;      // BATCH*NCH*D_INNER/4 = 32768
    if (idx >= BATCH * NCH * (D_INNER / 4)) return;
    int c4 = idx & (D_INNER / 4 - 1);
    int c = c4 * 4;
    int ch = (idx >> 9) & (NCH - 1);
    int b = idx >> 13;
    float4 d = *reinterpret_cast<const float4*>(decay + c);
    float4 h = *reinterpret_cast<const float4*>(hin + (size_t)(b * NCH + ch) * D_INNER + c);
    size_t m0 = (size_t)(b * SEQ + ch * LCH);
    size_t vbase = m0 * D_INNER + c;
    size_t zbase = m0 * (2 * D_INNER) + D_INNER + c;
    #pragma unroll 4
    for (int i = 0; i < LCH; i++) {
        uint2 vr = *reinterpret_cast<const uint2*>(vals + vbase + (size_t)i * D_INNER);
        __half2 v0 = *reinterpret_cast<__half2*>(&vr.x);
        __half2 v1 = *reinterpret_cast<__half2*>(&vr.y);
        h.x = fmaf(d.x, h.x, __half2float(__low2half(v0)));
        h.y = fmaf(d.y, h.y, __half2float(__high2half(v0)));
        h.z = fmaf(d.z, h.z, __half2float(__low2half(v1)));
        h.w = fmaf(d.w, h.w, __half2float(__high2half(v1)));
        uint2 zr = *reinterpret_cast<const uint2*>(xz + zbase + (size_t)i * (2 * D_INNER));
        __half2 z0 = *reinterpret_cast<__half2*>(&zr.x);
        __half2 z1 = *reinterpret_cast<__half2*>(&zr.y);
        float g0 = h.x * silu_f(__half2float(__low2half(z0)));
        float g1 = h.y * silu_f(__half2float(__high2half(z0)));
        float g2 = h.z * silu_f(__half2float(__low2half(z1)));
        float g3 = h.w * silu_f(__half2float(__high2half(z1)));
        uint2 outw;
        __half2 o0 = __halves2half2(__float2half(g0), __float2half(g1));
        __half2 o1 = __halves2half2(__float2half(g2), __float2half(g3));
        outw.x = *reinterpret_cast<uint32_t*>(&o0);
        outw.y = *reinterpret_cast<uint32_t*>(&o1);
        *reinterpret_cast<uint2*>(yf + vbase + (size_t)i * D_INNER) = outw;
    }
}

// ---------------- launcher ----------------
extern "C" void kernel_launch(void* const* d_in, const int* in_sizes, int n_in,
                              void* d_out, int out_size)
{
    const float* x      = (const float*)d_in[0];
    const float* W_in   = (const float*)d_in[1];
    const float* b_in   = (const float*)d_in[2];
    const float* W_conv = (const float*)d_in[3];
    const float* b_conv = (const float*)d_in[4];
    const float* W_dt   = (const float*)d_in[5];
    const float* b_dt   = (const float*)d_in[6];
    const float* W_out  = (const float*)d_in[7];
    const float* b_out  = (const float*)d_in[8];
    const float* decay  = (const float*)d_in[9];
    float* out = (float*)d_out;

    float *carry, *hin;
    __half *xz, *vals, *xf, *xcf, *yf, *wi, *wd, *wo;
    cudaGetSymbolAddress((void**)&xz, g_xz);
    cudaGetSymbolAddress((void**)&vals, g_vals);
    cudaGetSymbolAddress((void**)&carry, g_carry);
    cudaGetSymbolAddress((void**)&hin, g_hin);
    cudaGetSymbolAddress((void**)&xf, g_xf);
    cudaGetSymbolAddress((void**)&xcf, g_xcf);
    cudaGetSymbolAddress((void**)&yf, g_yf);
    cudaGetSymbolAddress((void**)&wi, g_wi);
    cudaGetSymbolAddress((void**)&wd, g_wd);
    cudaGetSymbolAddress((void**)&wo, g_wo);

    cudaFuncSetAttribute(gemm_mma<0>, cudaFuncAttributeMaxDynamicSharedMemorySize, GSMEM_BYTES);
    cudaFuncSetAttribute(gemm_mma<1>, cudaFuncAttributeMaxDynamicSharedMemorySize, GSMEM_BYTES);
    cudaFuncSetAttribute(gemm_mma<2>, cudaFuncAttributeMaxDynamicSharedMemorySize, GSMEM_BYTES);

    // fused conversion launch (counts in float8 units; all sizes divisible by 8)
    const int n0 = M_TOTAL * D_MODEL / 8;
    const int n1 = 2 * D_INNER * D_MODEL / 8;
    const int n2 = D_INNER * D_INNER / 8;
    const int n3 = D_MODEL * D_INNER / 8;
    cvt_all_kernel<<<(n0 + n1 + n2 + n3 + 255) / 256, 256>>>(
        x, xf, n0, W_in, wi, n1, W_dt, wd, n2, W_out, wo, n3);

    // GEMM1: xz(fp16) = x @ W_in^T + b_in   [8192, 4096], K=1024
    gemm_mma<0><<<dim3((2 * D_INNER) / BN, M_TOTAL / BM), NTHR, GSMEM_BYTES>>>(
        xf, wi, b_in, xz, nullptr, nullptr, nullptr, M_TOTAL, 2 * D_INNER, D_MODEL);

    // conv + silu -> xcf (fp16)
    conv_silu_kernel<<<(M_TOTAL * D_INNER / 4) / 256, 256>>>(xz, W_conv, b_conv, xcf);

    // GEMM2: vals(fp16) = softplus(xcf @ W_dt^T + b_dt) * xcf ; + fused chunk carries
    gemm_mma<1><<<dim3(D_INNER / BN, M_TOTAL / BM), NTHR, GSMEM_BYTES>>>(
        xcf, wd, b_dt, vals, xcf, decay, carry, M_TOTAL, D_INNER, D_INNER);

    // cross-chunk prefix + per-chunk recompute/gate
    scanB_kernel<<<(BATCH * D_INNER) / 256, 256>>>(carry, decay, hin);
    scanC_kernel<<<(BATCH * NCH * D_INNER / 4) / 256, 256>>>(vals, xz, decay, hin, yf);

    // GEMM3: out(fp32) = y @ W_out^T + b_out   [8192, 1024], K=2048
    gemm_mma<2><<<dim3(D_MODEL / BN, M_TOTAL / BM), NTHR, GSMEM_BYTES>>>(
        yf, wo, b_out, out, nullptr, nullptr, nullptr, M_TOTAL, D_MODEL, D_INNER);
}